// round 2
// baseline (speedup 1.0000x reference)
#include <cuda_runtime.h>
#include <cuda_bf16.h>
#include <math.h>
#include <stdint.h>

typedef unsigned long long U64;

// ---------------- device scratch (allocations are forbidden) ----------------
__device__ int  g_xmin[64], g_xmax[64], g_ymin[64], g_ymax[64];
__device__ float g_bbox[64 * 4];
__device__ float g_pos2[64 * 256];      // pos MLP output per (b*16+t)
__device__ U64  g_h0[2][512];           // layer0 h, [parity][bp*256+j], packed (b=2bp, 2bp+1)
__device__ U64  g_h1[2][512];           // layer1 h
__device__ U64  g_c0[512];              // layer0 c
__device__ U64  g_c1[512];              // layer1 c
__device__ U64  g_hs0[2 * 16 * 256];    // layer0 outputs: [bp*16 + t][256]

// ---------------- packed f32x2 helpers ----------------
__device__ __forceinline__ U64 pk2(float a, float b) {
    U64 r; asm("mov.b64 %0, {%1, %2};" : "=l"(r) : "f"(a), "f"(b)); return r;
}
__device__ __forceinline__ float2 upk(U64 v) {
    float2 f; asm("mov.b64 {%0, %1}, %2;" : "=f"(f.x), "=f"(f.y) : "l"(v)); return f;
}
__device__ __forceinline__ U64 dup2(float a) {
    U64 r; asm("mov.b64 %0, {%1, %1};" : "=l"(r) : "f"(a)); return r;
}
__device__ __forceinline__ U64 fma2(U64 x, U64 w, U64 a) {
    U64 d; asm("fma.rn.f32x2 %0, %1, %2, %3;" : "=l"(d) : "l"(x), "l"(w), "l"(a)); return d;
}
__device__ __forceinline__ U64 add2(U64 a, U64 b) {
    U64 d; asm("add.rn.f32x2 %0, %1, %2;" : "=l"(d) : "l"(a), "l"(b)); return d;
}
__device__ __forceinline__ float sigf(float x) { return 1.0f / (1.0f + __expf(-x)); }

// ---------------- init: reset state every graph replay ----------------
__global__ void mp_init_kernel() {
    int t = threadIdx.x;
    if (t < 64) {
        g_xmin[t] = 0x7fffffff; g_xmax[t] = -1;
        g_ymin[t] = 0x7fffffff; g_ymax[t] = -1;
    }
    g_c0[t] = 0ull;       g_c0[t + 256] = 0ull;
    g_c1[t] = 0ull;       g_c1[t + 256] = 0ull;
    g_h0[0][t] = 0ull;    g_h0[0][t + 256] = 0ull;
    g_h1[0][t] = 0ull;    g_h1[0][t + 256] = 0ull;
}

// ---------------- 256 MB mask scan (DRAM-bound) ----------------
__global__ void __launch_bounds__(256) mp_scan_kernel(const float* __restrict__ pred) {
    int img   = blockIdx.x >> 5;   // 64 images (b*16+t)
    int slice = blockIdx.x & 31;   // 32 slices of 32 rows
    const float4* p4 = (const float4*)(pred + (size_t)img * (1024u * 1024u)
                                            + (size_t)slice * (32u * 1024u));
    int tid = threadIdx.x;

    int lxmin = 0x7fffffff, lxmax = -1, lymin = 0x7fffffff, lymax = -1;
    #pragma unroll 4
    for (int r = 0; r < 32; r++) {
        float4 v = p4[r * 256 + tid];
        bool m0 = v.x > 0.5f, m1 = v.y > 0.5f, m2 = v.z > 0.5f, m3 = v.w > 0.5f;
        if (m0 | m1 | m2 | m3) {
            int x0 = tid * 4;
            int f = m0 ? 0 : (m1 ? 1 : (m2 ? 2 : 3));
            int l = m3 ? 3 : (m2 ? 2 : (m1 ? 1 : 0));
            lxmin = min(lxmin, x0 + f);
            lxmax = max(lxmax, x0 + l);
            int y = slice * 32 + r;
            lymin = min(lymin, y);
            lymax = max(lymax, y);
        }
    }
    #pragma unroll
    for (int off = 16; off; off >>= 1) {
        lxmin = min(lxmin, __shfl_xor_sync(0xffffffffu, lxmin, off));
        lxmax = max(lxmax, __shfl_xor_sync(0xffffffffu, lxmax, off));
        lymin = min(lymin, __shfl_xor_sync(0xffffffffu, lymin, off));
        lymax = max(lymax, __shfl_xor_sync(0xffffffffu, lymax, off));
    }
    __shared__ int sx0, sx1, sy0, sy1;
    if (tid == 0) { sx0 = 0x7fffffff; sx1 = -1; sy0 = 0x7fffffff; sy1 = -1; }
    __syncthreads();
    if ((tid & 31) == 0) {
        atomicMin(&sx0, lxmin); atomicMax(&sx1, lxmax);
        atomicMin(&sy0, lymin); atomicMax(&sy1, lymax);
    }
    __syncthreads();
    if (tid == 0) {
        atomicMin(&g_xmin[img], sx0); atomicMax(&g_xmax[img], sx1);
        atomicMin(&g_ymin[img], sy0); atomicMax(&g_ymax[img], sy1);
    }
}

// ---------------- bbox finalize + pos MLP (64 CTAs, one per (b,t)) ----------------
__global__ void __launch_bounds__(256) mp_pos_kernel(
    const float* __restrict__ pe_w1, const float* __restrict__ pe_b1,
    const float* __restrict__ pe_w2, const float* __restrict__ pe_b2,
    float* __restrict__ out)
{
    __shared__ float sbb[4];
    __shared__ float sp1[256];
    int img = blockIdx.x;
    int tid = threadIdx.x;
    if (tid == 0) {
        int xm = g_xmin[img], xM = g_xmax[img], ym = g_ymin[img], yM = g_ymax[img];
        float b0, b1, b2, b3;
        if (xM < 0) { b0 = 0.5f; b1 = 0.5f; b2 = 0.1f; b3 = 0.1f; }
        else {
            b0 = (float)(xm + xM) / 2.0f / 1024.0f;
            b1 = (float)(ym + yM) / 2.0f / 1024.0f;
            b2 = (float)(xM - xm) / 1024.0f;
            b3 = (float)(yM - ym) / 1024.0f;
        }
        sbb[0] = b0; sbb[1] = b1; sbb[2] = b2; sbb[3] = b3;
        g_bbox[img * 4 + 0] = b0; g_bbox[img * 4 + 1] = b1;
        g_bbox[img * 4 + 2] = b2; g_bbox[img * 4 + 3] = b3;
        out[16644 + img * 4 + 0] = b0; out[16644 + img * 4 + 1] = b1;
        out[16644 + img * 4 + 2] = b2; out[16644 + img * 4 + 3] = b3;
    }
    __syncthreads();
    int j = tid;
    float a = pe_b1[j];
    #pragma unroll
    for (int k = 0; k < 4; k++) a += sbb[k] * pe_w1[k * 256 + j];
    sp1[j] = fmaxf(a, 0.0f);
    __syncthreads();
    float a2 = pe_b2[j];
    #pragma unroll 8
    for (int k = 0; k < 256; k++) a2 += sp1[k] * pe_w2[k * 256 + j];
    g_pos2[img * 256 + j] = fmaxf(a2, 0.0f);
}

// ---------------- pipelined LSTM step ----------------
// launch s (0..16): blocks 0..7  = layer0 step t=s   (if s<16)
//                   blocks 8..15 = layer1 step t=s-1 (if s>=1)
// Each CTA owns hidden units j in [blk*32, blk*32+32), i.e. gate cols
// {g*256 + blk*32 + jj}. Gates: g = x@Wx + h@Wh + (bx+bh). Batch pairs packed f32x2.
__global__ void __launch_bounds__(256) mp_step_kernel(
    int s,
    const float* __restrict__ wih0, const float* __restrict__ whh0,
    const float* __restrict__ bih0, const float* __restrict__ bhh0,
    const float* __restrict__ wih1, const float* __restrict__ whh1,
    const float* __restrict__ bih1, const float* __restrict__ bhh1,
    float* __restrict__ out)
{
    __shared__ U64 sh_x[512];            // [bp*256 + k]
    __shared__ U64 sh_h[512];
    __shared__ U64 sh_part[256][8];      // [tid][c4*2+bp]
    __shared__ U64 sh_gate[256];         // [bp*128 + g*32 + jj]

    int tid = threadIdx.x;
    int layer = blockIdx.x >> 3;
    int blk = blockIdx.x & 7;
    int t;
    if (layer == 0) { if (s >= 16) return; t = s; }
    else            { if (s == 0)  return; t = s - 1; }

    const float* Wx = layer == 0 ? wih0 : wih1;
    const float* Wh = layer == 0 ? whh0 : whh1;
    const float* bx = layer == 0 ? bih0 : bih1;
    const float* bh = layer == 0 ? bhh0 : bhh1;
    U64* cbuf = layer == 0 ? g_c0 : g_c1;
    const U64* hR = layer == 0 ? g_h0[t & 1] : g_h1[t & 1];
    U64* hW = layer == 0 ? g_h0[(t + 1) & 1] : g_h1[(t + 1) & 1];

    // stage inputs into smem
    for (int idx = tid; idx < 512; idx += 256) {
        int bp = idx >> 8, k = idx & 255;
        if (layer == 0)
            sh_x[idx] = pk2(g_pos2[((2 * bp) * 16 + t) * 256 + k],
                            g_pos2[((2 * bp + 1) * 16 + t) * 256 + k]);
        else
            sh_x[idx] = g_hs0[(bp * 16 + t) * 256 + k];
        sh_h[idx] = hR[idx];
    }
    __syncthreads();

    // dual matmul: thread = (kc warp, col-quad q)
    int kc = tid >> 5;              // 8 k-chunks of 32
    int q  = tid & 31;              // 32 col-quads
    int g  = q >> 3, jq = q & 7;
    int colbase = g * 256 + blk * 32 + jq * 4;
    int k0 = kc * 32;

    U64 acc[8];
    #pragma unroll
    for (int i = 0; i < 8; i++) acc[i] = 0ull;

    const float* wxp = Wx + (size_t)k0 * 1024 + colbase;
    const float* whp = Wh + (size_t)k0 * 1024 + colbase;
    #pragma unroll 4
    for (int i = 0; i < 32; i++) {
        float4 w = *(const float4*)(wxp + i * 1024);
        U64 x0 = sh_x[k0 + i], x1 = sh_x[256 + k0 + i];
        acc[0] = fma2(x0, dup2(w.x), acc[0]); acc[1] = fma2(x1, dup2(w.x), acc[1]);
        acc[2] = fma2(x0, dup2(w.y), acc[2]); acc[3] = fma2(x1, dup2(w.y), acc[3]);
        acc[4] = fma2(x0, dup2(w.z), acc[4]); acc[5] = fma2(x1, dup2(w.z), acc[5]);
        acc[6] = fma2(x0, dup2(w.w), acc[6]); acc[7] = fma2(x1, dup2(w.w), acc[7]);
    }
    #pragma unroll 4
    for (int i = 0; i < 32; i++) {
        float4 w = *(const float4*)(whp + i * 1024);
        U64 h0v = sh_h[k0 + i], h1v = sh_h[256 + k0 + i];
        acc[0] = fma2(h0v, dup2(w.x), acc[0]); acc[1] = fma2(h1v, dup2(w.x), acc[1]);
        acc[2] = fma2(h0v, dup2(w.y), acc[2]); acc[3] = fma2(h1v, dup2(w.y), acc[3]);
        acc[4] = fma2(h0v, dup2(w.z), acc[4]); acc[5] = fma2(h1v, dup2(w.z), acc[5]);
        acc[6] = fma2(h0v, dup2(w.w), acc[6]); acc[7] = fma2(h1v, dup2(w.w), acc[7]);
    }
    #pragma unroll
    for (int i = 0; i < 8; i++) sh_part[tid][i] = acc[i];
    __syncthreads();

    // k-chunk reduction + bias -> gate preactivations
    {
        int c = tid & 127, bp = tid >> 7;
        int g2 = c >> 5, jj = c & 31;
        int q2 = g2 * 8 + (jj >> 2), c4 = jj & 3;
        int gcol = g2 * 256 + blk * 32 + jj;
        U64 sum = dup2(bx[gcol] + bh[gcol]);
        #pragma unroll
        for (int kk = 0; kk < 8; kk++)
            sum = add2(sum, sh_part[kk * 32 + q2][c4 * 2 + bp]);
        sh_gate[bp * 128 + c] = sum;
    }
    __syncthreads();

    // cell/hidden update for this CTA's 32 hidden units
    if (tid < 64) {
        int bp = tid >> 5, jj = tid & 31;
        int j = blk * 32 + jj;
        float2 gi = upk(sh_gate[bp * 128 + jj]);
        float2 gf = upk(sh_gate[bp * 128 + 32 + jj]);
        float2 gg = upk(sh_gate[bp * 128 + 64 + jj]);
        float2 go = upk(sh_gate[bp * 128 + 96 + jj]);
        float2 co = upk(cbuf[bp * 256 + j]);

        float i0 = sigf(gi.x), f0 = sigf(gf.x), m0 = tanhf(gg.x), o0 = sigf(go.x);
        float cn0 = f0 * co.x + i0 * m0;
        float hn0 = o0 * tanhf(cn0);
        float i1 = sigf(gi.y), f1 = sigf(gf.y), m1 = tanhf(gg.y), o1 = sigf(go.y);
        float cn1 = f1 * co.y + i1 * m1;
        float hn1 = o1 * tanhf(cn1);

        cbuf[bp * 256 + j] = pk2(cn0, cn1);
        U64 hp = pk2(hn0, hn1);
        hW[bp * 256 + j] = hp;
        if (layer == 0) {
            g_hs0[(bp * 16 + t) * 256 + j] = hp;
        } else {
            out[240 + ((2 * bp) * 16 + t) * 256 + j]     = hn0;
            out[240 + ((2 * bp + 1) * 16 + t) * 256 + j] = hn1;
        }
    }
}

// ---------------- heads: MLPs + cumsum + confidence ----------------
__global__ void __launch_bounds__(256) mp_heads_kernel(
    const float* __restrict__ mp_w1, const float* __restrict__ mp_b1,
    const float* __restrict__ mp_w2, const float* __restrict__ mp_b2,
    const float* __restrict__ mp_w3, const float* __restrict__ mp_b3,
    const float* __restrict__ cf_w1, const float* __restrict__ cf_b1,
    const float* __restrict__ cf_w2, const float* __restrict__ cf_b2,
    float* __restrict__ out)
{
    __shared__ float slh[1024];   // last_hidden [b][256]
    __shared__ float sx1[1024];   // relu(lh@mp_w1+b1)
    __shared__ float sx2[512];    // relu(x1@mp_w2+b2) [b][128]
    __shared__ float sch[512];    // relu(lh@cf_w1+b1) [b][128]
    __shared__ float sdel[80];    // deltas [b][20]
    int tid = threadIdx.x;

    for (int idx = tid; idx < 512; idx += 256) {
        int bp = idx >> 8, k = idx & 255;
        float2 v = upk(g_h1[0][idx]);   // layer1 t=15 writes parity 0
        slh[(2 * bp) * 256 + k]     = v.x;
        slh[(2 * bp + 1) * 256 + k] = v.y;
    }
    __syncthreads();

    for (int idx = tid; idx < 1024; idx += 256) {
        int b = idx >> 8, j = idx & 255;
        float a = mp_b1[j];
        #pragma unroll 8
        for (int k = 0; k < 256; k++) a += slh[b * 256 + k] * mp_w1[k * 256 + j];
        sx1[idx] = fmaxf(a, 0.0f);
    }
    __syncthreads();

    for (int idx = tid; idx < 512; idx += 256) {
        int b = idx >> 7, j = idx & 127;
        float a = mp_b2[j];
        float a2 = cf_b1[j];
        #pragma unroll 8
        for (int k = 0; k < 256; k++) {
            a  += sx1[b * 256 + k] * mp_w2[k * 128 + j];
            a2 += slh[b * 256 + k] * cf_w1[k * 128 + j];
        }
        sx2[idx] = fmaxf(a, 0.0f);
        sch[idx] = fmaxf(a2, 0.0f);
    }
    __syncthreads();

    if (tid < 80) {
        int b = tid / 20, r = tid % 20;
        float a = mp_b3[r];
        #pragma unroll 8
        for (int k = 0; k < 128; k++) a += sx2[b * 128 + k] * mp_w3[k * 20 + r];
        sdel[tid] = a;
        out[tid] = a;                   // predicted_deltas
    }
    if (tid >= 128 && tid < 148) {
        int z = tid - 128;
        int b = z / 5, hh = z % 5;
        float a = cf_b2[hh];
        #pragma unroll 8
        for (int k = 0; k < 128; k++) a += sch[b * 128 + k] * cf_w2[k * 5 + hh];
        out[16624 + z] = sigf(a);       // confidence
    }
    __syncthreads();

    if (tid < 16) {
        int b = tid >> 2, d = tid & 3;
        float run = g_bbox[(b * 16 + 15) * 4 + d];
        #pragma unroll
        for (int hh = 0; hh < 5; hh++) {
            run += sdel[b * 20 + hh * 4 + d];
            out[80 + (b * 5 + hh) * 4 + d] = run;                 // predicted_bboxes
            if (d < 2) out[160 + (b * 5 + hh) * 2 + d] = run;     // locations
            else       out[200 + (b * 5 + hh) * 2 + (d - 2)] = run; // scales
        }
    }
}

extern "C" void kernel_launch(void* const* d_in, const int* in_sizes, int n_in,
                              void* d_out, int out_size) {
    (void)in_sizes; (void)n_in; (void)out_size;
    const float* pred  = (const float*)d_in[1];
    const float* pe_w1 = (const float*)d_in[2];
    const float* pe_b1 = (const float*)d_in[3];
    const float* pe_w2 = (const float*)d_in[4];
    const float* pe_b2 = (const float*)d_in[5];
    const float* wih0  = (const float*)d_in[6];
    const float* whh0  = (const float*)d_in[7];
    const float* bih0  = (const float*)d_in[8];
    const float* bhh0  = (const float*)d_in[9];
    const float* wih1  = (const float*)d_in[10];
    const float* whh1  = (const float*)d_in[11];
    const float* bih1  = (const float*)d_in[12];
    const float* bhh1  = (const float*)d_in[13];
    const float* mp_w1 = (const float*)d_in[14];
    const float* mp_b1 = (const float*)d_in[15];
    const float* mp_w2 = (const float*)d_in[16];
    const float* mp_b2 = (const float*)d_in[17];
    const float* mp_w3 = (const float*)d_in[18];
    const float* mp_b3 = (const float*)d_in[19];
    const float* cf_w1 = (const float*)d_in[20];
    const float* cf_b1 = (const float*)d_in[21];
    const float* cf_w2 = (const float*)d_in[22];
    const float* cf_b2 = (const float*)d_in[23];
    float* out = (float*)d_out;

    mp_init_kernel<<<1, 256>>>();
    mp_scan_kernel<<<2048, 256>>>(pred);
    mp_pos_kernel<<<64, 256>>>(pe_w1, pe_b1, pe_w2, pe_b2, out);
    for (int s = 0; s < 17; s++) {
        mp_step_kernel<<<16, 256>>>(s, wih0, whh0, bih0, bhh0,
                                    wih1, whh1, bih1, bhh1, out);
    }
    mp_heads_kernel<<<1, 256>>>(mp_w1, mp_b1, mp_w2, mp_b2, mp_w3, mp_b3,
                                cf_w1, cf_b1, cf_w2, cf_b2, out);
}

// round 4
// speedup vs baseline: 1.3559x; 1.3559x over previous
#include <cuda_runtime.h>
#include <cuda_bf16.h>
#include <math.h>
#include <stdint.h>

typedef unsigned long long U64;

// ---------------- device scratch (allocations are forbidden) ----------------
__device__ int   g_xmin[64], g_xmax[64], g_ymin[64], g_ymax[64];
__device__ float g_bbox[64 * 4];
__device__ float g_pos2[64 * 256];      // pos MLP output per (b*16+t)
__device__ U64   g_h0[2][512];          // layer0 h, [parity][bp*256+j], packed (b=2bp,2bp+1)
__device__ U64   g_h1[2][512];          // layer1 h
__device__ U64   g_hs0[16 * 512];       // layer0 outputs per t: [t][bp*256+j]
__device__ unsigned g_done0[16];
__device__ unsigned g_done1[16];

// ---------------- packed f32x2 helpers ----------------
__device__ __forceinline__ U64 pk2(float a, float b) {
    U64 r; asm("mov.b64 %0, {%1, %2};" : "=l"(r) : "f"(a), "f"(b)); return r;
}
__device__ __forceinline__ float2 upk(U64 v) {
    float2 f; asm("mov.b64 {%0, %1}, %2;" : "=f"(f.x), "=f"(f.y) : "l"(v)); return f;
}
__device__ __forceinline__ U64 dup2(float a) {
    U64 r; asm("mov.b64 %0, {%1, %1};" : "=l"(r) : "f"(a)); return r;
}
__device__ __forceinline__ U64 fma2(U64 x, U64 w, U64 a) {
    U64 d; asm("fma.rn.f32x2 %0, %1, %2, %3;" : "=l"(d) : "l"(x), "l"(w), "l"(a)); return d;
}
__device__ __forceinline__ U64 add2(U64 a, U64 b) {
    U64 d; asm("add.rn.f32x2 %0, %1, %2;" : "=l"(d) : "l"(a), "l"(b)); return d;
}
__device__ __forceinline__ float sigf(float x) { return 1.0f / (1.0f + __expf(-x)); }

// ---- hardened sync primitives (PTX memory model, gpu scope) ----
__device__ __forceinline__ unsigned ld_acq_u32(const unsigned* p) {
    unsigned v;
    asm volatile("ld.acquire.gpu.global.u32 %0, [%1];" : "=r"(v) : "l"(p) : "memory");
    return v;
}
__device__ __forceinline__ void st_rel_u64(U64* p, U64 v) {
    asm volatile("st.release.gpu.global.u64 [%0], %1;" :: "l"(p), "l"(v) : "memory");
}
__device__ __forceinline__ void red_rel_add(unsigned* p) {
    asm volatile("red.release.gpu.global.add.u32 [%0], 1;" :: "l"(p) : "memory");
}
__device__ __forceinline__ U64 ldcv_u64(const U64* p) {
    U64 v; asm volatile("ld.global.cv.u64 %0, [%1];" : "=l"(v) : "l"(p)); return v;
}

// ---------------- init: reset state every graph replay ----------------
__global__ void mp_init_kernel() {
    int t = threadIdx.x;
    if (t < 64) {
        g_xmin[t] = 0x7fffffff; g_xmax[t] = -1;
        g_ymin[t] = 0x7fffffff; g_ymax[t] = -1;
    }
    if (t < 16) { g_done0[t] = 0u; g_done1[t] = 0u; }
    g_h0[0][t] = 0ull;  g_h0[0][t + 256] = 0ull;
    g_h1[0][t] = 0ull;  g_h1[0][t + 256] = 0ull;
}

// ---------------- 256 MB mask scan (DRAM-bound) ----------------
__global__ void __launch_bounds__(256) mp_scan_kernel(const float* __restrict__ pred) {
    int img   = blockIdx.x >> 5;   // 64 images (b*16+t)
    int slice = blockIdx.x & 31;   // 32 slices of 32 rows
    const float4* p4 = (const float4*)(pred + (size_t)img * (1024u * 1024u)
                                            + (size_t)slice * (32u * 1024u));
    int tid = threadIdx.x;

    int lxmin = 0x7fffffff, lxmax = -1, lymin = 0x7fffffff, lymax = -1;
    #pragma unroll 4
    for (int r = 0; r < 32; r++) {
        float4 v = p4[r * 256 + tid];
        bool m0 = v.x > 0.5f, m1 = v.y > 0.5f, m2 = v.z > 0.5f, m3 = v.w > 0.5f;
        if (m0 | m1 | m2 | m3) {
            int x0 = tid * 4;
            int f = m0 ? 0 : (m1 ? 1 : (m2 ? 2 : 3));
            int l = m3 ? 3 : (m2 ? 2 : (m1 ? 1 : 0));
            lxmin = min(lxmin, x0 + f);
            lxmax = max(lxmax, x0 + l);
            int y = slice * 32 + r;
            lymin = min(lymin, y);
            lymax = max(lymax, y);
        }
    }
    #pragma unroll
    for (int off = 16; off; off >>= 1) {
        lxmin = min(lxmin, __shfl_xor_sync(0xffffffffu, lxmin, off));
        lxmax = max(lxmax, __shfl_xor_sync(0xffffffffu, lxmax, off));
        lymin = min(lymin, __shfl_xor_sync(0xffffffffu, lymin, off));
        lymax = max(lymax, __shfl_xor_sync(0xffffffffu, lymax, off));
    }
    __shared__ int sx0, sx1, sy0, sy1;
    if (tid == 0) { sx0 = 0x7fffffff; sx1 = -1; sy0 = 0x7fffffff; sy1 = -1; }
    __syncthreads();
    if ((tid & 31) == 0) {
        atomicMin(&sx0, lxmin); atomicMax(&sx1, lxmax);
        atomicMin(&sy0, lymin); atomicMax(&sy1, lymax);
    }
    __syncthreads();
    if (tid == 0) {
        atomicMin(&g_xmin[img], sx0); atomicMax(&g_xmax[img], sx1);
        atomicMin(&g_ymin[img], sy0); atomicMax(&g_ymax[img], sy1);
    }
}

// ---------------- bbox finalize + pos MLP (64 CTAs, one per (b,t)) ----------------
__global__ void __launch_bounds__(256) mp_pos_kernel(
    const float* __restrict__ pe_w1, const float* __restrict__ pe_b1,
    const float* __restrict__ pe_w2, const float* __restrict__ pe_b2,
    float* __restrict__ out)
{
    __shared__ float sbb[4];
    __shared__ float sp1[256];
    int img = blockIdx.x;
    int tid = threadIdx.x;
    if (tid == 0) {
        int xm = g_xmin[img], xM = g_xmax[img], ym = g_ymin[img], yM = g_ymax[img];
        float b0, b1, b2, b3;
        if (xM < 0) { b0 = 0.5f; b1 = 0.5f; b2 = 0.1f; b3 = 0.1f; }
        else {
            b0 = (float)(xm + xM) / 2.0f / 1024.0f;
            b1 = (float)(ym + yM) / 2.0f / 1024.0f;
            b2 = (float)(xM - xm) / 1024.0f;
            b3 = (float)(yM - ym) / 1024.0f;
        }
        sbb[0] = b0; sbb[1] = b1; sbb[2] = b2; sbb[3] = b3;
        g_bbox[img * 4 + 0] = b0; g_bbox[img * 4 + 1] = b1;
        g_bbox[img * 4 + 2] = b2; g_bbox[img * 4 + 3] = b3;
        out[16644 + img * 4 + 0] = b0; out[16644 + img * 4 + 1] = b1;
        out[16644 + img * 4 + 2] = b2; out[16644 + img * 4 + 3] = b3;
    }
    __syncthreads();
    int j = tid;
    float a = pe_b1[j];
    #pragma unroll
    for (int k = 0; k < 4; k++) a += sbb[k] * pe_w1[k * 256 + j];
    sp1[j] = fmaxf(a, 0.0f);
    __syncthreads();
    float a2 = pe_b2[j];
    #pragma unroll 8
    for (int k = 0; k < 256; k++) a2 += sp1[k] * pe_w2[k * 256 + j];
    g_pos2[img * 256 + j] = fmaxf(a2, 0.0f);
}

// ---------------- fused persistent LSTM ----------------
// 64 CTAs: layer = blockIdx.x>>5, blk = blockIdx.x&31.
// CTA owns hidden units j in [blk*8, blk*8+8), i.e. gate cols {g*256+blk*8+u}.
// Weight slices live in SMEM (loaded once). Cell state in registers of tid<16.
// Sync: st.release data stores -> __syncthreads -> red.release counter;
// consumers: tid0 ld.acquire spin -> __syncthreads -> all-thread fence -> ld.cv.
#define FUSED_SMEM (16384*4 + 1024*8 + 512*8 + 64*8 + 32*4)

__global__ void __launch_bounds__(256, 1) mp_fused_kernel(
    const float* __restrict__ wih0, const float* __restrict__ whh0,
    const float* __restrict__ bih0, const float* __restrict__ bhh0,
    const float* __restrict__ wih1, const float* __restrict__ whh1,
    const float* __restrict__ bih1, const float* __restrict__ bhh1,
    float* __restrict__ out)
{
    extern __shared__ char smem_raw[];
    float* sW    = (float*)smem_raw;          // [2][256][32]: x weights then h weights
    U64*   sXH   = (U64*)(sW + 16384);        // [1024]: x packed [bp*256+k], then h
    U64*   sPart = sXH + 1024;                // [8][32][2]
    U64*   sGate = sPart + 512;               // [32][2]
    float* sBias = (float*)(sGate + 64);      // [32]

    int tid   = threadIdx.x;
    int layer = blockIdx.x >> 5;
    int blk   = blockIdx.x & 31;

    const float* Wx = layer ? wih1 : wih0;
    const float* Wh = layer ? whh1 : whh0;
    const float* bx = layer ? bih1 : bih0;
    const float* bh = layer ? bhh1 : bhh0;
    U64 (*hbuf)[512] = layer ? g_h1 : g_h0;

    // one-time weight preload into SMEM (layout [k][ci], ci = g*8+u)
    for (int idx = tid; idx < 8192; idx += 256) {
        int k = idx >> 5, ci = idx & 31;
        int col = (ci >> 3) * 256 + blk * 8 + (ci & 7);
        sW[idx]        = Wx[k * 1024 + col];
        sW[8192 + idx] = Wh[k * 1024 + col];
    }
    if (tid < 32) {
        int col = (tid >> 3) * 256 + blk * 8 + (tid & 7);
        sBias[tid] = bx[col] + bh[col];
    }

    float2 creg = make_float2(0.0f, 0.0f);  // cell state for tid<16: (u=tid>>1, bp=tid&1)

    for (int t = 0; t < 16; t++) {
        // ---- wait for producers (acquire) ----
        if (tid == 0) {
            if (layer == 0) {
                if (t > 0) while (ld_acq_u32(&g_done0[t - 1]) < 32u) {}
            } else {
                while (ld_acq_u32(&g_done0[t]) < 32u) {}
                if (t > 0) while (ld_acq_u32(&g_done1[t - 1]) < 32u) {}
            }
        }
        __syncthreads();
        __threadfence();   // all threads: order subsequent loads after the sync point

        // ---- stage x_t and h_{t-1} into SMEM ----
        const U64* hR = hbuf[t & 1];
        for (int idx = tid; idx < 512; idx += 256) {
            int bp = idx >> 8, k = idx & 255;
            if (layer == 0)
                sXH[idx] = pk2(g_pos2[((2 * bp) * 16 + t) * 256 + k],
                               g_pos2[((2 * bp + 1) * 16 + t) * 256 + k]);
            else
                sXH[idx] = ldcv_u64(&g_hs0[t * 512 + idx]);
            sXH[512 + idx] = ldcv_u64(&hR[idx]);
        }
        __syncthreads();

        // ---- matmul: thread = (kc in 0..7, ci in 0..31) ----
        {
            int kc = tid >> 5, ci = tid & 31;
            const float* W = sW  + (kc < 4 ? 0 : 8192);
            const U64*   V = sXH + (kc < 4 ? 0 : 512);
            int k0 = (kc & 3) * 64;
            U64 a0 = 0ull, a1 = 0ull;
            #pragma unroll 8
            for (int i = 0; i < 64; i++) {
                U64 wv = dup2(W[(k0 + i) * 32 + ci]);
                a0 = fma2(V[k0 + i],       wv, a0);
                a1 = fma2(V[256 + k0 + i], wv, a1);
            }
            sPart[kc * 64 + ci * 2 + 0] = a0;
            sPart[kc * 64 + ci * 2 + 1] = a1;
        }
        __syncthreads();

        // ---- reduce 8 k-chunks + bias ----
        if (tid < 64) {
            int ci = tid >> 1, bp = tid & 1;
            U64 s = dup2(sBias[ci]);
            #pragma unroll
            for (int kk = 0; kk < 8; kk++) s = add2(s, sPart[kk * 64 + ci * 2 + bp]);
            sGate[ci * 2 + bp] = s;
        }
        __syncthreads();

        // ---- gates + cell/hidden update (8 units x 2 batch-pairs) ----
        if (tid < 16) {
            int u = tid >> 1, bp = tid & 1;
            float2 gi = upk(sGate[(0 * 8 + u) * 2 + bp]);
            float2 gf = upk(sGate[(1 * 8 + u) * 2 + bp]);
            float2 gg = upk(sGate[(2 * 8 + u) * 2 + bp]);
            float2 go = upk(sGate[(3 * 8 + u) * 2 + bp]);

            float i0 = sigf(gi.x), f0 = sigf(gf.x), m0 = tanhf(gg.x), o0 = sigf(go.x);
            float cn0 = f0 * creg.x + i0 * m0;
            float hn0 = o0 * tanhf(cn0);
            float i1 = sigf(gi.y), f1 = sigf(gf.y), m1 = tanhf(gg.y), o1 = sigf(go.y);
            float cn1 = f1 * creg.y + i1 * m1;
            float hn1 = o1 * tanhf(cn1);
            creg = make_float2(cn0, cn1);

            int j = blk * 8 + u;
            U64 hp = pk2(hn0, hn1);
            st_rel_u64(&hbuf[(t + 1) & 1][bp * 256 + j], hp);
            if (layer == 0) {
                st_rel_u64(&g_hs0[t * 512 + bp * 256 + j], hp);
            } else {
                out[240 + ((2 * bp) * 16 + t) * 256 + j]     = hn0;
                out[240 + ((2 * bp + 1) * 16 + t) * 256 + j] = hn1;
            }
            __threadfence();
        }
        __syncthreads();

        // ---- signal (release RMW) ----
        if (tid == 0) {
            red_rel_add(layer ? &g_done1[t] : &g_done0[t]);
        }
    }
}

// ---------------- heads: MLPs + cumsum + confidence ----------------
__global__ void __launch_bounds__(256) mp_heads_kernel(
    const float* __restrict__ mp_w1, const float* __restrict__ mp_b1,
    const float* __restrict__ mp_w2, const float* __restrict__ mp_b2,
    const float* __restrict__ mp_w3, const float* __restrict__ mp_b3,
    const float* __restrict__ cf_w1, const float* __restrict__ cf_b1,
    const float* __restrict__ cf_w2, const float* __restrict__ cf_b2,
    float* __restrict__ out)
{
    __shared__ float slh[1024];   // last_hidden [b][256]
    __shared__ float sx1[1024];   // relu(lh@mp_w1+b1)
    __shared__ float sx2[512];    // relu(x1@mp_w2+b2) [b][128]
    __shared__ float sch[512];    // relu(lh@cf_w1+b1) [b][128]
    __shared__ float sdel[80];    // deltas [b][20]
    int tid = threadIdx.x;

    for (int idx = tid; idx < 512; idx += 256) {
        int bp = idx >> 8, k = idx & 255;
        float2 v = upk(g_h1[0][idx]);   // layer1 t=15 writes parity 0
        slh[(2 * bp) * 256 + k]     = v.x;
        slh[(2 * bp + 1) * 256 + k] = v.y;
    }
    __syncthreads();

    for (int idx = tid; idx < 1024; idx += 256) {
        int b = idx >> 8, j = idx & 255;
        float a = mp_b1[j];
        #pragma unroll 8
        for (int k = 0; k < 256; k++) a += slh[b * 256 + k] * mp_w1[k * 256 + j];
        sx1[idx] = fmaxf(a, 0.0f);
    }
    __syncthreads();

    for (int idx = tid; idx < 512; idx += 256) {
        int b = idx >> 7, j = idx & 127;
        float a = mp_b2[j];
        float a2 = cf_b1[j];
        #pragma unroll 8
        for (int k = 0; k < 256; k++) {
            a  += sx1[b * 256 + k] * mp_w2[k * 128 + j];
            a2 += slh[b * 256 + k] * cf_w1[k * 128 + j];
        }
        sx2[idx] = fmaxf(a, 0.0f);
        sch[idx] = fmaxf(a2, 0.0f);
    }
    __syncthreads();

    if (tid < 80) {
        int b = tid / 20, r = tid % 20;
        float a = mp_b3[r];
        #pragma unroll 8
        for (int k = 0; k < 128; k++) a += sx2[b * 128 + k] * mp_w3[k * 20 + r];
        sdel[tid] = a;
        out[tid] = a;                   // predicted_deltas
    }
    if (tid >= 128 && tid < 148) {
        int z = tid - 128;
        int b = z / 5, hh = z % 5;
        float a = cf_b2[hh];
        #pragma unroll 8
        for (int k = 0; k < 128; k++) a += sch[b * 128 + k] * cf_w2[k * 5 + hh];
        out[16624 + z] = sigf(a);       // confidence
    }
    __syncthreads();

    if (tid < 16) {
        int b = tid >> 2, d = tid & 3;
        float run = g_bbox[(b * 16 + 15) * 4 + d];
        #pragma unroll
        for (int hh = 0; hh < 5; hh++) {
            run += sdel[b * 20 + hh * 4 + d];
            out[80 + (b * 5 + hh) * 4 + d] = run;                   // predicted_bboxes
            if (d < 2) out[160 + (b * 5 + hh) * 2 + d] = run;       // locations
            else       out[200 + (b * 5 + hh) * 2 + (d - 2)] = run; // scales
        }
    }
}

extern "C" void kernel_launch(void* const* d_in, const int* in_sizes, int n_in,
                              void* d_out, int out_size) {
    (void)in_sizes; (void)n_in; (void)out_size;
    const float* pred  = (const float*)d_in[1];
    const float* pe_w1 = (const float*)d_in[2];
    const float* pe_b1 = (const float*)d_in[3];
    const float* pe_w2 = (const float*)d_in[4];
    const float* pe_b2 = (const float*)d_in[5];
    const float* wih0  = (const float*)d_in[6];
    const float* whh0  = (const float*)d_in[7];
    const float* bih0  = (const float*)d_in[8];
    const float* bhh0  = (const float*)d_in[9];
    const float* wih1  = (const float*)d_in[10];
    const float* whh1  = (const float*)d_in[11];
    const float* bih1  = (const float*)d_in[12];
    const float* bhh1  = (const float*)d_in[13];
    const float* mp_w1 = (const float*)d_in[14];
    const float* mp_b1 = (const float*)d_in[15];
    const float* mp_w2 = (const float*)d_in[16];
    const float* mp_b2 = (const float*)d_in[17];
    const float* mp_w3 = (const float*)d_in[18];
    const float* mp_b3 = (const float*)d_in[19];
    const float* cf_w1 = (const float*)d_in[20];
    const float* cf_b1 = (const float*)d_in[21];
    const float* cf_w2 = (const float*)d_in[22];
    const float* cf_b2 = (const float*)d_in[23];
    float* out = (float*)d_out;

    cudaFuncSetAttribute(mp_fused_kernel,
                         cudaFuncAttributeMaxDynamicSharedMemorySize, FUSED_SMEM);

    mp_init_kernel<<<1, 256>>>();
    mp_scan_kernel<<<2048, 256>>>(pred);
    mp_pos_kernel<<<64, 256>>>(pe_w1, pe_b1, pe_w2, pe_b2, out);
    mp_fused_kernel<<<64, 256, FUSED_SMEM>>>(wih0, whh0, bih0, bhh0,
                                             wih1, whh1, bih1, bhh1, out);
    mp_heads_kernel<<<1, 256>>>(mp_w1, mp_b1, mp_w2, mp_b2, mp_w3, mp_b3,
                                cf_w1, cf_b1, cf_w2, cf_b2, out);
}

// round 5
// speedup vs baseline: 1.8083x; 1.3336x over previous
#include <cuda_runtime.h>
#include <cuda_bf16.h>
#include <math.h>
#include <stdint.h>

typedef unsigned long long U64;

// ---------------- device scratch (allocations are forbidden) ----------------
__device__ int   g_xmin[64], g_xmax[64], g_ymin[64], g_ymax[64];
__device__ float g_bbox[64 * 4];
__device__ float g_pos2[64 * 256];      // pos MLP output per (b*16+t)
__device__ U64   g_h0[2][512];          // layer0 h, [parity][bp*256+j], packed (b=2bp,2bp+1)
__device__ U64   g_h1[2][512];          // layer1 h
__device__ U64   g_hs0[16 * 512];       // layer0 outputs per t: [t][bp*256+j]
__device__ unsigned g_done0[16];
__device__ unsigned g_done1[16];

// ---------------- packed f32x2 helpers ----------------
__device__ __forceinline__ U64 pk2(float a, float b) {
    U64 r; asm("mov.b64 %0, {%1, %2};" : "=l"(r) : "f"(a), "f"(b)); return r;
}
__device__ __forceinline__ float2 upk(U64 v) {
    float2 f; asm("mov.b64 {%0, %1}, %2;" : "=f"(f.x), "=f"(f.y) : "l"(v)); return f;
}
__device__ __forceinline__ U64 dup2(float a) {
    U64 r; asm("mov.b64 %0, {%1, %1};" : "=l"(r) : "f"(a)); return r;
}
__device__ __forceinline__ U64 fma2(U64 x, U64 w, U64 a) {
    U64 d; asm("fma.rn.f32x2 %0, %1, %2, %3;" : "=l"(d) : "l"(x), "l"(w), "l"(a)); return d;
}
__device__ __forceinline__ U64 add2(U64 a, U64 b) {
    U64 d; asm("add.rn.f32x2 %0, %1, %2;" : "=l"(d) : "l"(a), "l"(b)); return d;
}
__device__ __forceinline__ float sigf(float x) { return 1.0f / (1.0f + __expf(-x)); }

// ---- sync primitives (PTX memory model, gpu scope) ----
__device__ __forceinline__ unsigned ld_acq_u32(const unsigned* p) {
    unsigned v;
    asm volatile("ld.acquire.gpu.global.u32 %0, [%1];" : "=r"(v) : "l"(p) : "memory");
    return v;
}
__device__ __forceinline__ void st_rel_u64(U64* p, U64 v) {
    asm volatile("st.release.gpu.global.u64 [%0], %1;" :: "l"(p), "l"(v) : "memory");
}
__device__ __forceinline__ void red_rel_add(unsigned* p) {
    unsigned one = 1u;
    asm volatile("red.release.gpu.global.add.u32 [%0], %1;" :: "l"(p), "r"(one) : "memory");
}
__device__ __forceinline__ U64 ldcv_u64(const U64* p) {
    U64 v; asm volatile("ld.global.cv.u64 %0, [%1];" : "=l"(v) : "l"(p)); return v;
}

// ---------------- init: reset state every graph replay ----------------
__global__ void mp_init_kernel() {
    int t = threadIdx.x;
    if (t < 64) {
        g_xmin[t] = 0x7fffffff; g_xmax[t] = -1;
        g_ymin[t] = 0x7fffffff; g_ymax[t] = -1;
    }
    if (t < 16) { g_done0[t] = 0u; g_done1[t] = 0u; }
    g_h0[0][t] = 0ull;  g_h0[0][t + 256] = 0ull;
    g_h1[0][t] = 0ull;  g_h1[0][t + 256] = 0ull;
}

// ---------------- 256 MB mask scan (DRAM-bound) ----------------
__global__ void __launch_bounds__(256) mp_scan_kernel(const float* __restrict__ pred) {
    int img   = blockIdx.x >> 5;   // 64 images (b*16+t)
    int slice = blockIdx.x & 31;   // 32 slices of 32 rows
    const float4* p4 = (const float4*)(pred + (size_t)img * (1024u * 1024u)
                                            + (size_t)slice * (32u * 1024u));
    int tid = threadIdx.x;

    int lxmin = 0x7fffffff, lxmax = -1, lymin = 0x7fffffff, lymax = -1;
    #pragma unroll 8
    for (int r = 0; r < 32; r++) {
        float4 v = p4[r * 256 + tid];
        bool m0 = v.x > 0.5f, m1 = v.y > 0.5f, m2 = v.z > 0.5f, m3 = v.w > 0.5f;
        if (m0 | m1 | m2 | m3) {
            int x0 = tid * 4;
            int f = m0 ? 0 : (m1 ? 1 : (m2 ? 2 : 3));
            int l = m3 ? 3 : (m2 ? 2 : (m1 ? 1 : 0));
            lxmin = min(lxmin, x0 + f);
            lxmax = max(lxmax, x0 + l);
            int y = slice * 32 + r;
            lymin = min(lymin, y);
            lymax = max(lymax, y);
        }
    }
    #pragma unroll
    for (int off = 16; off; off >>= 1) {
        lxmin = min(lxmin, __shfl_xor_sync(0xffffffffu, lxmin, off));
        lxmax = max(lxmax, __shfl_xor_sync(0xffffffffu, lxmax, off));
        lymin = min(lymin, __shfl_xor_sync(0xffffffffu, lymin, off));
        lymax = max(lymax, __shfl_xor_sync(0xffffffffu, lymax, off));
    }
    __shared__ int sx0, sx1, sy0, sy1;
    if (tid == 0) { sx0 = 0x7fffffff; sx1 = -1; sy0 = 0x7fffffff; sy1 = -1; }
    __syncthreads();
    if ((tid & 31) == 0) {
        atomicMin(&sx0, lxmin); atomicMax(&sx1, lxmax);
        atomicMin(&sy0, lymin); atomicMax(&sy1, lymax);
    }
    __syncthreads();
    if (tid == 0) {
        atomicMin(&g_xmin[img], sx0); atomicMax(&g_xmax[img], sx1);
        atomicMin(&g_ymin[img], sy0); atomicMax(&g_ymax[img], sy1);
    }
}

// ---------------- bbox finalize + pos MLP (64 CTAs, one per (b,t)) ----------------
__global__ void __launch_bounds__(256) mp_pos_kernel(
    const float* __restrict__ pe_w1, const float* __restrict__ pe_b1,
    const float* __restrict__ pe_w2, const float* __restrict__ pe_b2,
    float* __restrict__ out)
{
    __shared__ float sbb[4];
    __shared__ float sp1[256];
    int img = blockIdx.x;
    int tid = threadIdx.x;
    if (tid == 0) {
        int xm = g_xmin[img], xM = g_xmax[img], ym = g_ymin[img], yM = g_ymax[img];
        float b0, b1, b2, b3;
        if (xM < 0) { b0 = 0.5f; b1 = 0.5f; b2 = 0.1f; b3 = 0.1f; }
        else {
            b0 = (float)(xm + xM) / 2.0f / 1024.0f;
            b1 = (float)(ym + yM) / 2.0f / 1024.0f;
            b2 = (float)(xM - xm) / 1024.0f;
            b3 = (float)(yM - ym) / 1024.0f;
        }
        sbb[0] = b0; sbb[1] = b1; sbb[2] = b2; sbb[3] = b3;
        g_bbox[img * 4 + 0] = b0; g_bbox[img * 4 + 1] = b1;
        g_bbox[img * 4 + 2] = b2; g_bbox[img * 4 + 3] = b3;
        out[16644 + img * 4 + 0] = b0; out[16644 + img * 4 + 1] = b1;
        out[16644 + img * 4 + 2] = b2; out[16644 + img * 4 + 3] = b3;
    }
    __syncthreads();
    int j = tid;
    float a = pe_b1[j];
    #pragma unroll
    for (int k = 0; k < 4; k++) a += sbb[k] * pe_w1[k * 256 + j];
    sp1[j] = fmaxf(a, 0.0f);
    __syncthreads();
    float a2 = pe_b2[j];
    #pragma unroll 8
    for (int k = 0; k < 256; k++) a2 += sp1[k] * pe_w2[k * 256 + j];
    g_pos2[img * 256 + j] = fmaxf(a2, 0.0f);
}

// ---------------- fused persistent LSTM ----------------
// 64 CTAs: layer = blockIdx.x>>5, blk = blockIdx.x&31.
// CTA owns hidden units j in [blk*8, blk*8+8), gate cols {g*256+blk*8+u}.
// Weights in SMEM (loaded once). Cell state in registers of tid<16.
// Per step: [stage-x(l0)] wait-bar, stage, bar, matmul, bar, update+signal.
// Signal: each of the 16 updater threads does st.release data + red.release +1;
// flag full count = 32 CTAs * 16 = 512.
#define FUSED_SMEM (16384*4 + 1024*8 + 512*8 + 32*4)

__global__ void __launch_bounds__(256, 1) mp_fused_kernel(
    const float* __restrict__ wih0, const float* __restrict__ whh0,
    const float* __restrict__ bih0, const float* __restrict__ bhh0,
    const float* __restrict__ wih1, const float* __restrict__ whh1,
    const float* __restrict__ bih1, const float* __restrict__ bhh1,
    float* __restrict__ out)
{
    extern __shared__ char smem_raw[];
    float* sW    = (float*)smem_raw;          // [2][256][32]: x weights then h weights
    U64*   sXH   = (U64*)(sW + 16384);        // [1024]: x packed [bp*256+k], then h
    U64*   sPart = sXH + 1024;                // [8][32][2]
    float* sBias = (float*)(sPart + 512);     // [32]

    int tid   = threadIdx.x;
    int layer = blockIdx.x >> 5;
    int blk   = blockIdx.x & 31;

    const float* Wx = layer ? wih1 : wih0;
    const float* Wh = layer ? whh1 : whh0;
    const float* bx = layer ? bih1 : bih0;
    const float* bh = layer ? bhh1 : bhh0;
    U64 (*hbuf)[512] = layer ? g_h1 : g_h0;

    // one-time weight preload into SMEM (layout [k][ci], ci = g*8+u)
    for (int idx = tid; idx < 8192; idx += 256) {
        int k = idx >> 5, ci = idx & 31;
        int col = (ci >> 3) * 256 + blk * 8 + (ci & 7);
        sW[idx]        = Wx[k * 1024 + col];
        sW[8192 + idx] = Wh[k * 1024 + col];
    }
    if (tid < 32) {
        int col = (tid >> 3) * 256 + blk * 8 + (tid & 7);
        sBias[tid] = bx[col] + bh[col];
    }

    float2 creg = make_float2(0.0f, 0.0f);  // cell state for tid<16: (u=tid>>1, bp=tid&1)

    for (int t = 0; t < 16; t++) {
        // ---- stage x early for layer 0 (no producer dependency) ----
        if (layer == 0) {
            for (int idx = tid; idx < 512; idx += 256) {
                int bp = idx >> 8, k = idx & 255;
                sXH[idx] = pk2(g_pos2[((2 * bp) * 16 + t) * 256 + k],
                               g_pos2[((2 * bp + 1) * 16 + t) * 256 + k]);
            }
        }

        // ---- wait for producers (acquire, tid0) ----
        if (tid == 0) {
            if (layer == 0) {
                if (t > 0) while (ld_acq_u32(&g_done0[t - 1]) < 512u) {}
            } else {
                while (ld_acq_u32(&g_done0[t]) < 512u) {}
                if (t > 0) while (ld_acq_u32(&g_done1[t - 1]) < 512u) {}
            }
        }
        __syncthreads();

        // ---- stage h (and x for layer1) into SMEM ----
        const U64* hR = hbuf[t & 1];
        for (int idx = tid; idx < 512; idx += 256) {
            if (layer == 1) sXH[idx] = ldcv_u64(&g_hs0[t * 512 + idx]);
            sXH[512 + idx] = ldcv_u64(&hR[idx]);
        }
        __syncthreads();

        // ---- matmul: thread = (kc in 0..7, ci in 0..31) ----
        {
            int kc = tid >> 5, ci = tid & 31;
            const float* W = sW  + (kc < 4 ? 0 : 8192);
            const U64*   V = sXH + (kc < 4 ? 0 : 512);
            int k0 = (kc & 3) * 64;
            U64 a0 = 0ull, a1 = 0ull;
            #pragma unroll 8
            for (int i = 0; i < 64; i++) {
                U64 wv = dup2(W[(k0 + i) * 32 + ci]);
                a0 = fma2(V[k0 + i],       wv, a0);
                a1 = fma2(V[256 + k0 + i], wv, a1);
            }
            sPart[kc * 64 + ci * 2 + 0] = a0;
            sPart[kc * 64 + ci * 2 + 1] = a1;
        }
        __syncthreads();

        // ---- gates + cell/hidden update + signal (8 units x 2 batch-pairs) ----
        if (tid < 16) {
            int u = tid >> 1, bp = tid & 1;
            float2 gt[4];
            #pragma unroll
            for (int g = 0; g < 4; g++) {
                int ci = g * 8 + u;
                U64 s = dup2(sBias[ci]);
                #pragma unroll
                for (int kk = 0; kk < 8; kk++)
                    s = add2(s, sPart[kk * 64 + ci * 2 + bp]);
                gt[g] = upk(s);
            }

            float i0 = sigf(gt[0].x), f0 = sigf(gt[1].x), m0 = tanhf(gt[2].x), o0 = sigf(gt[3].x);
            float cn0 = f0 * creg.x + i0 * m0;
            float hn0 = o0 * tanhf(cn0);
            float i1 = sigf(gt[0].y), f1 = sigf(gt[1].y), m1 = tanhf(gt[2].y), o1 = sigf(gt[3].y);
            float cn1 = f1 * creg.y + i1 * m1;
            float hn1 = o1 * tanhf(cn1);
            creg = make_float2(cn0, cn1);

            int j = blk * 8 + u;
            U64 hp = pk2(hn0, hn1);
            st_rel_u64(&hbuf[(t + 1) & 1][bp * 256 + j], hp);
            if (layer == 0) {
                st_rel_u64(&g_hs0[t * 512 + bp * 256 + j], hp);
            } else {
                out[240 + ((2 * bp) * 16 + t) * 256 + j]     = hn0;
                out[240 + ((2 * bp + 1) * 16 + t) * 256 + j] = hn1;
            }
            red_rel_add(layer ? &g_done1[t] : &g_done0[t]);
        }
        // next iteration's wait-barrier orders everything
    }
}

// ---------------- heads: 4 CTAs, one per batch ----------------
__global__ void __launch_bounds__(256) mp_heads_kernel(
    const float* __restrict__ mp_w1, const float* __restrict__ mp_b1,
    const float* __restrict__ mp_w2, const float* __restrict__ mp_b2,
    const float* __restrict__ mp_w3, const float* __restrict__ mp_b3,
    const float* __restrict__ cf_w1, const float* __restrict__ cf_b1,
    const float* __restrict__ cf_w2, const float* __restrict__ cf_b2,
    float* __restrict__ out)
{
    __shared__ float slh[256];   // last_hidden for this batch
    __shared__ float sx1[256];   // relu(lh@mp_w1+b1)
    __shared__ float sx2[128];   // relu(x1@mp_w2+b2)
    __shared__ float sch[128];   // relu(lh@cf_w1+b1)
    __shared__ float sdel[20];   // deltas
    int b   = blockIdx.x;
    int tid = threadIdx.x;
    int bp = b >> 1, comp = b & 1;

    {
        float2 v = upk(g_h1[0][bp * 256 + tid]);   // layer1 t=15 writes parity 0
        slh[tid] = comp ? v.y : v.x;
    }
    __syncthreads();

    {
        float a = mp_b1[tid];
        #pragma unroll 8
        for (int k = 0; k < 256; k++) a += slh[k] * mp_w1[k * 256 + tid];
        sx1[tid] = fmaxf(a, 0.0f);
    }
    __syncthreads();

    if (tid < 128) {
        float a  = mp_b2[tid];
        float a2 = cf_b1[tid];
        #pragma unroll 8
        for (int k = 0; k < 256; k++) {
            a  += sx1[k] * mp_w2[k * 128 + tid];
            a2 += slh[k] * cf_w1[k * 128 + tid];
        }
        sx2[tid] = fmaxf(a, 0.0f);
        sch[tid] = fmaxf(a2, 0.0f);
    }
    __syncthreads();

    if (tid < 20) {
        float a = mp_b3[tid];
        #pragma unroll 8
        for (int k = 0; k < 128; k++) a += sx2[k] * mp_w3[k * 20 + tid];
        sdel[tid] = a;
        out[b * 20 + tid] = a;              // predicted_deltas
    }
    if (tid >= 32 && tid < 37) {
        int hh = tid - 32;
        float a = cf_b2[hh];
        #pragma unroll 8
        for (int k = 0; k < 128; k++) a += sch[k] * cf_w2[k * 5 + hh];
        out[16624 + b * 5 + hh] = sigf(a);  // confidence
    }
    __syncthreads();

    if (tid < 4) {
        int d = tid;
        float run = g_bbox[(b * 16 + 15) * 4 + d];
        #pragma unroll
        for (int hh = 0; hh < 5; hh++) {
            run += sdel[hh * 4 + d];
            out[80 + (b * 5 + hh) * 4 + d] = run;                   // predicted_bboxes
            if (d < 2) out[160 + (b * 5 + hh) * 2 + d] = run;       // locations
            else       out[200 + (b * 5 + hh) * 2 + (d - 2)] = run; // scales
        }
    }
}

extern "C" void kernel_launch(void* const* d_in, const int* in_sizes, int n_in,
                              void* d_out, int out_size) {
    (void)in_sizes; (void)n_in; (void)out_size;
    const float* pred  = (const float*)d_in[1];
    const float* pe_w1 = (const float*)d_in[2];
    const float* pe_b1 = (const float*)d_in[3];
    const float* pe_w2 = (const float*)d_in[4];
    const float* pe_b2 = (const float*)d_in[5];
    const float* wih0  = (const float*)d_in[6];
    const float* whh0  = (const float*)d_in[7];
    const float* bih0  = (const float*)d_in[8];
    const float* bhh0  = (const float*)d_in[9];
    const float* wih1  = (const float*)d_in[10];
    const float* whh1  = (const float*)d_in[11];
    const float* bih1  = (const float*)d_in[12];
    const float* bhh1  = (const float*)d_in[13];
    const float* mp_w1 = (const float*)d_in[14];
    const float* mp_b1 = (const float*)d_in[15];
    const float* mp_w2 = (const float*)d_in[16];
    const float* mp_b2 = (const float*)d_in[17];
    const float* mp_w3 = (const float*)d_in[18];
    const float* mp_b3 = (const float*)d_in[19];
    const float* cf_w1 = (const float*)d_in[20];
    const float* cf_b1 = (const float*)d_in[21];
    const float* cf_w2 = (const float*)d_in[22];
    const float* cf_b2 = (const float*)d_in[23];
    float* out = (float*)d_out;

    cudaFuncSetAttribute(mp_fused_kernel,
                         cudaFuncAttributeMaxDynamicSharedMemorySize, FUSED_SMEM);

    mp_init_kernel<<<1, 256>>>();
    mp_scan_kernel<<<2048, 256>>>(pred);
    mp_pos_kernel<<<64, 256>>>(pe_w1, pe_b1, pe_w2, pe_b2, out);
    mp_fused_kernel<<<64, 256, FUSED_SMEM>>>(wih0, whh0, bih0, bhh0,
                                             wih1, whh1, bih1, bhh1, out);
    mp_heads_kernel<<<4, 256>>>(mp_w1, mp_b1, mp_w2, mp_b2, mp_w3, mp_b3,
                                cf_w1, cf_b1, cf_w2, cf_b2, out);
}

// round 6
// speedup vs baseline: 1.8779x; 1.0385x over previous
#include <cuda_runtime.h>
#include <cuda_bf16.h>
#include <math.h>
#include <stdint.h>

typedef unsigned long long U64;

// ---------------- device scratch (allocations are forbidden) ----------------
__device__ int   g_xmin[64], g_xmax[64], g_ymin[64], g_ymax[64];
__device__ float g_bbox[64 * 4];
__device__ float g_pos2[64 * 256];      // pos MLP output per (b*16+t)
__device__ U64   g_hs0[16 * 512];       // layer0 outputs per t: [t][bp*256+j]
__device__ U64   g_h1f[512];            // layer1 final hidden (t=15), packed
__device__ unsigned g_done0[16];

// ---------------- packed f32x2 helpers ----------------
__device__ __forceinline__ U64 pk2(float a, float b) {
    U64 r; asm("mov.b64 %0, {%1, %2};" : "=l"(r) : "f"(a), "f"(b)); return r;
}
__device__ __forceinline__ float2 upk(U64 v) {
    float2 f; asm("mov.b64 {%0, %1}, %2;" : "=f"(f.x), "=f"(f.y) : "l"(v)); return f;
}
__device__ __forceinline__ U64 dup2(float a) {
    U64 r; asm("mov.b64 %0, {%1, %1};" : "=l"(r) : "f"(a)); return r;
}
__device__ __forceinline__ U64 fma2(U64 x, U64 w, U64 a) {
    U64 d; asm("fma.rn.f32x2 %0, %1, %2, %3;" : "=l"(d) : "l"(x), "l"(w), "l"(a)); return d;
}
__device__ __forceinline__ U64 add2(U64 a, U64 b) {
    U64 d; asm("add.rn.f32x2 %0, %1, %2;" : "=l"(d) : "l"(a), "l"(b)); return d;
}
__device__ __forceinline__ float sigf(float x) { return 1.0f / (1.0f + __expf(-x)); }

// ---- sync primitives ----
__device__ __forceinline__ unsigned ld_acq_u32(const unsigned* p) {
    unsigned v;
    asm volatile("ld.acquire.gpu.global.u32 %0, [%1];" : "=r"(v) : "l"(p) : "memory");
    return v;
}
__device__ __forceinline__ void st_rel_u64(U64* p, U64 v) {
    asm volatile("st.release.gpu.global.u64 [%0], %1;" :: "l"(p), "l"(v) : "memory");
}
__device__ __forceinline__ void red_rel_add(unsigned* p) {
    unsigned one = 1u;
    asm volatile("red.release.gpu.global.add.u32 [%0], %1;" :: "l"(p), "r"(one) : "memory");
}
__device__ __forceinline__ U64 ldcv_u64(const U64* p) {
    U64 v; asm volatile("ld.global.cv.u64 %0, [%1];" : "=l"(v) : "l"(p)); return v;
}
__device__ __forceinline__ unsigned smem_u32(const void* p) {
    unsigned r;
    asm("{ .reg .u64 t; cvta.to.shared.u64 t, %1; cvt.u32.u64 %0, t; }" : "=r"(r) : "l"(p));
    return r;
}
__device__ __forceinline__ void st_cluster_u64(unsigned laddr, unsigned rank, U64 v) {
    asm volatile("{ .reg .b32 ra; mapa.shared::cluster.u32 ra, %0, %1; st.shared::cluster.u64 [ra], %2; }"
                 :: "r"(laddr), "r"(rank), "l"(v) : "memory");
}
__device__ __forceinline__ unsigned ctarank() {
    unsigned r; asm("mov.u32 %0, %%cluster_ctarank;" : "=r"(r)); return r;
}
#define CLUSTER_SYNC() do { \
    asm volatile("barrier.cluster.arrive.aligned;" ::: "memory"); \
    asm volatile("barrier.cluster.wait.aligned;"   ::: "memory"); } while (0)

// ---------------- init: reset state every graph replay ----------------
__global__ void mp_init_kernel() {
    int t = threadIdx.x;
    if (t < 64) {
        g_xmin[t] = 0x7fffffff; g_xmax[t] = -1;
        g_ymin[t] = 0x7fffffff; g_ymax[t] = -1;
    }
    if (t < 16) g_done0[t] = 0u;
}

// ---------------- 256 MB mask scan (DRAM-bound) ----------------
__global__ void __launch_bounds__(256) mp_scan_kernel(const float* __restrict__ pred) {
    int img   = blockIdx.x >> 5;   // 64 images (b*16+t)
    int slice = blockIdx.x & 31;   // 32 slices of 32 rows
    const float4* p4 = (const float4*)(pred + (size_t)img * (1024u * 1024u)
                                            + (size_t)slice * (32u * 1024u));
    int tid = threadIdx.x;

    int lxmin = 0x7fffffff, lxmax = -1, lymin = 0x7fffffff, lymax = -1;
    #pragma unroll 8
    for (int r = 0; r < 32; r++) {
        float4 v = p4[r * 256 + tid];
        bool m0 = v.x > 0.5f, m1 = v.y > 0.5f, m2 = v.z > 0.5f, m3 = v.w > 0.5f;
        if (m0 | m1 | m2 | m3) {
            int x0 = tid * 4;
            int f = m0 ? 0 : (m1 ? 1 : (m2 ? 2 : 3));
            int l = m3 ? 3 : (m2 ? 2 : (m1 ? 1 : 0));
            lxmin = min(lxmin, x0 + f);
            lxmax = max(lxmax, x0 + l);
            int y = slice * 32 + r;
            lymin = min(lymin, y);
            lymax = max(lymax, y);
        }
    }
    #pragma unroll
    for (int off = 16; off; off >>= 1) {
        lxmin = min(lxmin, __shfl_xor_sync(0xffffffffu, lxmin, off));
        lxmax = max(lxmax, __shfl_xor_sync(0xffffffffu, lxmax, off));
        lymin = min(lymin, __shfl_xor_sync(0xffffffffu, lymin, off));
        lymax = max(lymax, __shfl_xor_sync(0xffffffffu, lymax, off));
    }
    __shared__ int sx0, sx1, sy0, sy1;
    if (tid == 0) { sx0 = 0x7fffffff; sx1 = -1; sy0 = 0x7fffffff; sy1 = -1; }
    __syncthreads();
    if ((tid & 31) == 0) {
        atomicMin(&sx0, lxmin); atomicMax(&sx1, lxmax);
        atomicMin(&sy0, lymin); atomicMax(&sy1, lymax);
    }
    __syncthreads();
    if (tid == 0) {
        atomicMin(&g_xmin[img], sx0); atomicMax(&g_xmax[img], sx1);
        atomicMin(&g_ymin[img], sy0); atomicMax(&g_ymax[img], sy1);
    }
}

// ---------------- bbox finalize + pos MLP (64 CTAs, one per (b,t)) ----------------
__global__ void __launch_bounds__(256) mp_pos_kernel(
    const float* __restrict__ pe_w1, const float* __restrict__ pe_b1,
    const float* __restrict__ pe_w2, const float* __restrict__ pe_b2,
    float* __restrict__ out)
{
    __shared__ float sbb[4];
    __shared__ float sp1[256];
    int img = blockIdx.x;
    int tid = threadIdx.x;
    if (tid == 0) {
        int xm = g_xmin[img], xM = g_xmax[img], ym = g_ymin[img], yM = g_ymax[img];
        float b0, b1, b2, b3;
        if (xM < 0) { b0 = 0.5f; b1 = 0.5f; b2 = 0.1f; b3 = 0.1f; }
        else {
            b0 = (float)(xm + xM) / 2.0f / 1024.0f;
            b1 = (float)(ym + yM) / 2.0f / 1024.0f;
            b2 = (float)(xM - xm) / 1024.0f;
            b3 = (float)(yM - ym) / 1024.0f;
        }
        sbb[0] = b0; sbb[1] = b1; sbb[2] = b2; sbb[3] = b3;
        g_bbox[img * 4 + 0] = b0; g_bbox[img * 4 + 1] = b1;
        g_bbox[img * 4 + 2] = b2; g_bbox[img * 4 + 3] = b3;
        out[16644 + img * 4 + 0] = b0; out[16644 + img * 4 + 1] = b1;
        out[16644 + img * 4 + 2] = b2; out[16644 + img * 4 + 3] = b3;
    }
    __syncthreads();
    int j = tid;
    float a = pe_b1[j];
    #pragma unroll
    for (int k = 0; k < 4; k++) a += sbb[k] * pe_w1[k * 256 + j];
    sp1[j] = fmaxf(a, 0.0f);
    __syncthreads();
    float a2 = pe_b2[j];
    #pragma unroll 8
    for (int k = 0; k < 256; k++) a2 += sp1[k] * pe_w2[k * 256 + j];
    g_pos2[img * 256 + j] = fmaxf(a2, 0.0f);
}

// ---------------- fused cluster LSTM ----------------
// grid 32 = 2 clusters x 16 CTAs. cluster 0 = layer0, cluster 1 = layer1.
// CTA rank r owns hidden units j in [r*16, r*16+16) (gate cols g*256 + r*16 + u).
// Weights (Wx,Wh slices) live in SMEM, transposed [ci][k] with +4 pad for LDS.128.
// h is exchanged via DSMEM mailboxes (double-buffered by parity) + one
// cluster barrier per step. Layer0->layer1 via release stores + flag in L2.
#define WPAD 260
#define FUSED_SMEM (2*64*WPAD*4 + 8192*8 + 1024*8 + 512*8 + 64*4)   // 211200 B

__global__ void __launch_bounds__(256, 1) mp_fused_kernel(
    const float* __restrict__ wih0, const float* __restrict__ whh0,
    const float* __restrict__ bih0, const float* __restrict__ bhh0,
    const float* __restrict__ wih1, const float* __restrict__ whh1,
    const float* __restrict__ bih1, const float* __restrict__ bhh1,
    float* __restrict__ out)
{
    extern __shared__ char smem_raw[];
    float* sWx   = (float*)smem_raw;              // [64][WPAD]
    float* sWh   = sWx + 64 * WPAD;               // [64][WPAD]
    U64*   sXall = (U64*)(sWh + 64 * WPAD);       // layer0: [16][512]; layer1: [512] staging
    U64*   sH    = sXall + 8192;                  // [2][512] mailboxes
    U64*   sPart = sH + 1024;                     // [4][64][2]
    float* sBias = (float*)(sPart + 512);         // [64]

    int tid   = threadIdx.x;
    int layer = blockIdx.x >> 4;
    unsigned rank = ctarank();

    const float* Wx = layer ? wih1 : wih0;
    const float* Wh = layer ? whh1 : whh0;
    const float* bx = layer ? bih1 : bih0;
    const float* bh = layer ? bhh1 : bhh0;

    // ---- prologue: weights -> SMEM (transposed, padded) ----
    for (int idx = tid; idx < 4096; idx += 256) {
        int k = idx >> 4, cq = idx & 15;
        int ci = cq * 4;
        int col = ((ci >> 4) << 8) + (int)rank * 16 + (ci & 15);
        float4 wx4 = *(const float4*)(Wx + k * 1024 + col);
        float4 wh4 = *(const float4*)(Wh + k * 1024 + col);
        sWx[(ci + 0) * WPAD + k] = wx4.x; sWx[(ci + 1) * WPAD + k] = wx4.y;
        sWx[(ci + 2) * WPAD + k] = wx4.z; sWx[(ci + 3) * WPAD + k] = wx4.w;
        sWh[(ci + 0) * WPAD + k] = wh4.x; sWh[(ci + 1) * WPAD + k] = wh4.y;
        sWh[(ci + 2) * WPAD + k] = wh4.z; sWh[(ci + 3) * WPAD + k] = wh4.w;
    }
    if (tid < 64) {
        int col = ((tid >> 4) << 8) + (int)rank * 16 + (tid & 15);
        sBias[tid] = bx[col] + bh[col];
    }
    // zero mailbox parity 0 (h_{-1} = 0)
    for (int idx = tid; idx < 512; idx += 256) sH[idx] = 0ull;
    // layer0: stage the whole x sequence once
    if (layer == 0) {
        for (int idx = tid; idx < 8192; idx += 256) {
            int t = idx >> 9, r2 = idx & 511, bp = r2 >> 8, k = r2 & 255;
            sXall[idx] = pk2(g_pos2[((2 * bp) * 16 + t) * 256 + k],
                             g_pos2[((2 * bp + 1) * 16 + t) * 256 + k]);
        }
    }
    __syncthreads();
    CLUSTER_SYNC();

    float2 creg = make_float2(0.0f, 0.0f);  // cell state for tid<32: (u=tid>>1, bp=tid&1)

    for (int t = 0; t < 16; t++) {
        // ---- layer1: wait for layer0's hs0[t], stage x ----
        if (layer == 1) {
            if (tid == 0) { while (ld_acq_u32(&g_done0[t]) < 512u) {} }
            __syncthreads();
            sXall[tid]       = ldcv_u64(&g_hs0[t * 512 + tid]);
            sXall[tid + 256] = ldcv_u64(&g_hs0[t * 512 + tid + 256]);
            __syncthreads();
        }
        const U64* xp = layer ? sXall : (sXall + t * 512);
        const U64* hp = sH + (t & 1) * 512;

        // ---- matmul: thread = (kc 0..3, ci 0..63), 64 k each, x+h fused ----
        {
            int kc = tid >> 6, ci = tid & 63;
            int k0 = kc * 64;
            const float* wxp = sWx + ci * WPAD + k0;
            const float* whp = sWh + ci * WPAD + k0;
            U64 a0 = 0ull, a1 = 0ull;
            #pragma unroll
            for (int i = 0; i < 64; i += 4) {
                float4 wx4 = *(const float4*)(wxp + i);
                float4 wh4 = *(const float4*)(whp + i);
                ulonglong2 x0a = *(const ulonglong2*)(xp + k0 + i);
                ulonglong2 x0b = *(const ulonglong2*)(xp + k0 + i + 2);
                ulonglong2 x1a = *(const ulonglong2*)(xp + 256 + k0 + i);
                ulonglong2 x1b = *(const ulonglong2*)(xp + 256 + k0 + i + 2);
                ulonglong2 h0a = *(const ulonglong2*)(hp + k0 + i);
                ulonglong2 h0b = *(const ulonglong2*)(hp + k0 + i + 2);
                ulonglong2 h1a = *(const ulonglong2*)(hp + 256 + k0 + i);
                ulonglong2 h1b = *(const ulonglong2*)(hp + 256 + k0 + i + 2);
                a0 = fma2(x0a.x, dup2(wx4.x), a0); a1 = fma2(x1a.x, dup2(wx4.x), a1);
                a0 = fma2(x0a.y, dup2(wx4.y), a0); a1 = fma2(x1a.y, dup2(wx4.y), a1);
                a0 = fma2(x0b.x, dup2(wx4.z), a0); a1 = fma2(x1b.x, dup2(wx4.z), a1);
                a0 = fma2(x0b.y, dup2(wx4.w), a0); a1 = fma2(x1b.y, dup2(wx4.w), a1);
                a0 = fma2(h0a.x, dup2(wh4.x), a0); a1 = fma2(h1a.x, dup2(wh4.x), a1);
                a0 = fma2(h0a.y, dup2(wh4.y), a0); a1 = fma2(h1a.y, dup2(wh4.y), a1);
                a0 = fma2(h0b.x, dup2(wh4.z), a0); a1 = fma2(h1b.x, dup2(wh4.z), a1);
                a0 = fma2(h0b.y, dup2(wh4.w), a0); a1 = fma2(h1b.y, dup2(wh4.w), a1);
            }
            sPart[(kc * 64 + ci) * 2 + 0] = a0;
            sPart[(kc * 64 + ci) * 2 + 1] = a1;
        }
        __syncthreads();

        // ---- update (16 units x 2 batch-pairs = 32 threads) + DSMEM push ----
        if (tid < 32) {
            int u = tid >> 1, bp = tid & 1;
            float2 gt[4];
            #pragma unroll
            for (int g = 0; g < 4; g++) {
                int ci2 = g * 16 + u;
                U64 s = dup2(sBias[ci2]);
                #pragma unroll
                for (int kc2 = 0; kc2 < 4; kc2++)
                    s = add2(s, sPart[(kc2 * 64 + ci2) * 2 + bp]);
                gt[g] = upk(s);
            }
            float i0 = sigf(gt[0].x), f0 = sigf(gt[1].x), m0 = tanhf(gt[2].x), o0 = sigf(gt[3].x);
            float cn0 = f0 * creg.x + i0 * m0;
            float hn0 = o0 * tanhf(cn0);
            float i1 = sigf(gt[0].y), f1 = sigf(gt[1].y), m1 = tanhf(gt[2].y), o1 = sigf(gt[3].y);
            float cn1 = f1 * creg.y + i1 * m1;
            float hn1 = o1 * tanhf(cn1);
            creg = make_float2(cn0, cn1);

            int j = (int)rank * 16 + u;
            U64 hpv = pk2(hn0, hn1);
            unsigned loc = smem_u32(&sH[((t + 1) & 1) * 512 + bp * 256 + j]);
            #pragma unroll
            for (int r = 0; r < 16; r++) st_cluster_u64(loc, r, hpv);

            if (layer == 0) {
                st_rel_u64(&g_hs0[t * 512 + bp * 256 + j], hpv);
                red_rel_add(&g_done0[t]);
            } else {
                out[240 + ((2 * bp) * 16 + t) * 256 + j]     = hn0;
                out[240 + ((2 * bp + 1) * 16 + t) * 256 + j] = hn1;
                if (t == 15) g_h1f[bp * 256 + j] = hpv;
            }
        }
        CLUSTER_SYNC();
    }
}

// ---------------- heads: 4 CTAs, one per batch ----------------
__global__ void __launch_bounds__(256) mp_heads_kernel(
    const float* __restrict__ mp_w1, const float* __restrict__ mp_b1,
    const float* __restrict__ mp_w2, const float* __restrict__ mp_b2,
    const float* __restrict__ mp_w3, const float* __restrict__ mp_b3,
    const float* __restrict__ cf_w1, const float* __restrict__ cf_b1,
    const float* __restrict__ cf_w2, const float* __restrict__ cf_b2,
    float* __restrict__ out)
{
    __shared__ float slh[256];   // last_hidden for this batch
    __shared__ float sx1[256];   // relu(lh@mp_w1+b1)
    __shared__ float sx2[128];   // relu(x1@mp_w2+b2)
    __shared__ float sch[128];   // relu(lh@cf_w1+b1)
    __shared__ float sdel[20];   // deltas
    int b   = blockIdx.x;
    int tid = threadIdx.x;
    int bp = b >> 1, comp = b & 1;

    {
        float2 v = upk(g_h1f[bp * 256 + tid]);
        slh[tid] = comp ? v.y : v.x;
    }
    __syncthreads();

    {
        float a = mp_b1[tid];
        #pragma unroll 8
        for (int k = 0; k < 256; k++) a += slh[k] * mp_w1[k * 256 + tid];
        sx1[tid] = fmaxf(a, 0.0f);
    }
    __syncthreads();

    if (tid < 128) {
        float a  = mp_b2[tid];
        float a2 = cf_b1[tid];
        #pragma unroll 8
        for (int k = 0; k < 256; k++) {
            a  += sx1[k] * mp_w2[k * 128 + tid];
            a2 += slh[k] * cf_w1[k * 128 + tid];
        }
        sx2[tid] = fmaxf(a, 0.0f);
        sch[tid] = fmaxf(a2, 0.0f);
    }
    __syncthreads();

    if (tid < 20) {
        float a = mp_b3[tid];
        #pragma unroll 8
        for (int k = 0; k < 128; k++) a += sx2[k] * mp_w3[k * 20 + tid];
        sdel[tid] = a;
        out[b * 20 + tid] = a;              // predicted_deltas
    }
    if (tid >= 32 && tid < 37) {
        int hh = tid - 32;
        float a = cf_b2[hh];
        #pragma unroll 8
        for (int k = 0; k < 128; k++) a += sch[k] * cf_w2[k * 5 + hh];
        out[16624 + b * 5 + hh] = sigf(a);  // confidence
    }
    __syncthreads();

    if (tid < 4) {
        int d = tid;
        float run = g_bbox[(b * 16 + 15) * 4 + d];
        #pragma unroll
        for (int hh = 0; hh < 5; hh++) {
            run += sdel[hh * 4 + d];
            out[80 + (b * 5 + hh) * 4 + d] = run;                   // predicted_bboxes
            if (d < 2) out[160 + (b * 5 + hh) * 2 + d] = run;       // locations
            else       out[200 + (b * 5 + hh) * 2 + (d - 2)] = run; // scales
        }
    }
}

extern "C" void kernel_launch(void* const* d_in, const int* in_sizes, int n_in,
                              void* d_out, int out_size) {
    (void)in_sizes; (void)n_in; (void)out_size;
    const float* pred  = (const float*)d_in[1];
    const float* pe_w1 = (const float*)d_in[2];
    const float* pe_b1 = (const float*)d_in[3];
    const float* pe_w2 = (const float*)d_in[4];
    const float* pe_b2 = (const float*)d_in[5];
    const float* wih0  = (const float*)d_in[6];
    const float* whh0  = (const float*)d_in[7];
    const float* bih0  = (const float*)d_in[8];
    const float* bhh0  = (const float*)d_in[9];
    const float* wih1  = (const float*)d_in[10];
    const float* whh1  = (const float*)d_in[11];
    const float* bih1  = (const float*)d_in[12];
    const float* bhh1  = (const float*)d_in[13];
    const float* mp_w1 = (const float*)d_in[14];
    const float* mp_b1 = (const float*)d_in[15];
    const float* mp_w2 = (const float*)d_in[16];
    const float* mp_b2 = (const float*)d_in[17];
    const float* mp_w3 = (const float*)d_in[18];
    const float* mp_b3 = (const float*)d_in[19];
    const float* cf_w1 = (const float*)d_in[20];
    const float* cf_b1 = (const float*)d_in[21];
    const float* cf_w2 = (const float*)d_in[22];
    const float* cf_b2 = (const float*)d_in[23];
    float* out = (float*)d_out;

    cudaFuncSetAttribute(mp_fused_kernel,
                         cudaFuncAttributeMaxDynamicSharedMemorySize, FUSED_SMEM);
    cudaFuncSetAttribute(mp_fused_kernel,
                         cudaFuncAttributeNonPortableClusterSizeAllowed, 1);

    mp_init_kernel<<<1, 256>>>();
    mp_scan_kernel<<<2048, 256>>>(pred);
    mp_pos_kernel<<<64, 256>>>(pe_w1, pe_b1, pe_w2, pe_b2, out);

    {
        cudaLaunchConfig_t cfg = {};
        cfg.gridDim = dim3(32, 1, 1);
        cfg.blockDim = dim3(256, 1, 1);
        cfg.dynamicSmemBytes = FUSED_SMEM;
        cfg.stream = 0;
        cudaLaunchAttribute attrs[1];
        attrs[0].id = cudaLaunchAttributeClusterDimension;
        attrs[0].val.clusterDim = {16, 1, 1};
        cfg.attrs = attrs;
        cfg.numAttrs = 1;
        cudaLaunchKernelEx(&cfg, mp_fused_kernel,
                           wih0, whh0, bih0, bhh0,
                           wih1, whh1, bih1, bhh1, out);
    }

    mp_heads_kernel<<<4, 256>>>(mp_w1, mp_b1, mp_w2, mp_b2, mp_w3, mp_b3,
                                cf_w1, cf_b1, cf_w2, cf_b2, out);
}

// round 7
// speedup vs baseline: 2.5129x; 1.3382x over previous
#include <cuda_runtime.h>
#include <cuda_bf16.h>
#include <math.h>
#include <stdint.h>

typedef unsigned long long U64;

// ---------------- device scratch (allocations are forbidden) ----------------
__device__ int   g_xmin[64], g_xmax[64], g_ymin[64], g_ymax[64];
__device__ float g_bbox[64 * 4];
__device__ float g_pos2[64 * 256];      // pos MLP output per (b*16+t)
__device__ float g_hs0f[16 * 1024];     // layer0 outputs: [t][b*256+j] scalar
__device__ float g_h1f[1024];           // layer1 final hidden [b*256+j] scalar
__device__ unsigned g_done0[16];

// ---------------- packed f32x2 helpers ----------------
__device__ __forceinline__ U64 pk2(float a, float b) {
    U64 r; asm("mov.b64 %0, {%1, %2};" : "=l"(r) : "f"(a), "f"(b)); return r;
}
__device__ __forceinline__ U64 dup2(float a) {
    U64 r; asm("mov.b64 %0, {%1, %1};" : "=l"(r) : "f"(a)); return r;
}
__device__ __forceinline__ U64 fma2(U64 x, U64 w, U64 a) {
    U64 d; asm("fma.rn.f32x2 %0, %1, %2, %3;" : "=l"(d) : "l"(x), "l"(w), "l"(a)); return d;
}
__device__ __forceinline__ float sigf(float x) { return 1.0f / (1.0f + __expf(-x)); }
__device__ __forceinline__ float tanh_fast(float x) {
    float e = __expf(2.0f * x);
    return 1.0f - 2.0f / (e + 1.0f);
}

// ---- sync primitives ----
__device__ __forceinline__ unsigned ld_acq_u32(const unsigned* p) {
    unsigned v;
    asm volatile("ld.acquire.gpu.global.u32 %0, [%1];" : "=r"(v) : "l"(p) : "memory");
    return v;
}
__device__ __forceinline__ void st_rel_f32(float* p, float v) {
    asm volatile("st.release.gpu.global.f32 [%0], %1;" :: "l"(p), "f"(v) : "memory");
}
__device__ __forceinline__ void red_rel_add(unsigned* p) {
    unsigned one = 1u;
    asm volatile("red.release.gpu.global.add.u32 [%0], %1;" :: "l"(p), "r"(one) : "memory");
}
__device__ __forceinline__ float ldcv_f32(const float* p) {
    float v; asm volatile("ld.global.cv.f32 %0, [%1];" : "=f"(v) : "l"(p)); return v;
}
__device__ __forceinline__ unsigned smem_u32(const void* p) {
    unsigned r;
    asm("{ .reg .u64 t; cvta.to.shared.u64 t, %1; cvt.u32.u64 %0, t; }" : "=r"(r) : "l"(p));
    return r;
}
__device__ __forceinline__ void st_cluster_u64(unsigned laddr, unsigned rank, U64 v) {
    asm volatile("{ .reg .b32 ra; mapa.shared::cluster.u32 ra, %0, %1; st.shared::cluster.u64 [ra], %2; }"
                 :: "r"(laddr), "r"(rank), "l"(v) : "memory");
}
__device__ __forceinline__ unsigned ctarank() {
    unsigned r; asm("mov.u32 %0, %%cluster_ctarank;" : "=r"(r)); return r;
}
#define CLUSTER_SYNC() do { \
    asm volatile("barrier.cluster.arrive.aligned;" ::: "memory"); \
    asm volatile("barrier.cluster.wait.aligned;"   ::: "memory"); } while (0)

// ---------------- init: reset state every graph replay ----------------
__global__ void mp_init_kernel() {
    int t = threadIdx.x;
    if (t < 64) {
        g_xmin[t] = 0x7fffffff; g_xmax[t] = -1;
        g_ymin[t] = 0x7fffffff; g_ymax[t] = -1;
    }
    if (t < 16) g_done0[t] = 0u;
}

// ---------------- 256 MB mask scan (DRAM-bound, MLP=8) ----------------
__global__ void __launch_bounds__(256) mp_scan_kernel(const float* __restrict__ pred) {
    int img   = blockIdx.x >> 5;   // 64 images (b*16+t)
    int slice = blockIdx.x & 31;   // 32 slices of 32 rows
    const float4* p4 = (const float4*)(pred + (size_t)img * (1024u * 1024u)
                                            + (size_t)slice * (32u * 1024u));
    int tid = threadIdx.x;

    int lxmin = 0x7fffffff, lxmax = -1, lymin = 0x7fffffff, lymax = -1;
    for (int rr = 0; rr < 4; rr++) {
        float4 v[8];
        #pragma unroll
        for (int u = 0; u < 8; u++)
            v[u] = __ldcs(p4 + (rr * 8 + u) * 256 + tid);
        #pragma unroll
        for (int u = 0; u < 8; u++) {
            bool m0 = v[u].x > 0.5f, m1 = v[u].y > 0.5f, m2 = v[u].z > 0.5f, m3 = v[u].w > 0.5f;
            if (m0 | m1 | m2 | m3) {
                int x0 = tid * 4;
                int f = m0 ? 0 : (m1 ? 1 : (m2 ? 2 : 3));
                int l = m3 ? 3 : (m2 ? 2 : (m1 ? 1 : 0));
                lxmin = min(lxmin, x0 + f);
                lxmax = max(lxmax, x0 + l);
                int y = slice * 32 + rr * 8 + u;
                lymin = min(lymin, y);
                lymax = max(lymax, y);
            }
        }
    }
    #pragma unroll
    for (int off = 16; off; off >>= 1) {
        lxmin = min(lxmin, __shfl_xor_sync(0xffffffffu, lxmin, off));
        lxmax = max(lxmax, __shfl_xor_sync(0xffffffffu, lxmax, off));
        lymin = min(lymin, __shfl_xor_sync(0xffffffffu, lymin, off));
        lymax = max(lymax, __shfl_xor_sync(0xffffffffu, lymax, off));
    }
    __shared__ int sx0, sx1, sy0, sy1;
    if (tid == 0) { sx0 = 0x7fffffff; sx1 = -1; sy0 = 0x7fffffff; sy1 = -1; }
    __syncthreads();
    if ((tid & 31) == 0) {
        atomicMin(&sx0, lxmin); atomicMax(&sx1, lxmax);
        atomicMin(&sy0, lymin); atomicMax(&sy1, lymax);
    }
    __syncthreads();
    if (tid == 0) {
        atomicMin(&g_xmin[img], sx0); atomicMax(&g_xmax[img], sx1);
        atomicMin(&g_ymin[img], sy0); atomicMax(&g_ymax[img], sy1);
    }
}

// ---------------- bbox finalize + pos MLP (64 CTAs, one per (b,t)) ----------------
__global__ void __launch_bounds__(256) mp_pos_kernel(
    const float* __restrict__ pe_w1, const float* __restrict__ pe_b1,
    const float* __restrict__ pe_w2, const float* __restrict__ pe_b2,
    float* __restrict__ out)
{
    __shared__ float sbb[4];
    __shared__ float sp1[256];
    int img = blockIdx.x;
    int tid = threadIdx.x;
    if (tid == 0) {
        int xm = g_xmin[img], xM = g_xmax[img], ym = g_ymin[img], yM = g_ymax[img];
        float b0, b1, b2, b3;
        if (xM < 0) { b0 = 0.5f; b1 = 0.5f; b2 = 0.1f; b3 = 0.1f; }
        else {
            b0 = (float)(xm + xM) / 2.0f / 1024.0f;
            b1 = (float)(ym + yM) / 2.0f / 1024.0f;
            b2 = (float)(xM - xm) / 1024.0f;
            b3 = (float)(yM - ym) / 1024.0f;
        }
        sbb[0] = b0; sbb[1] = b1; sbb[2] = b2; sbb[3] = b3;
        g_bbox[img * 4 + 0] = b0; g_bbox[img * 4 + 1] = b1;
        g_bbox[img * 4 + 2] = b2; g_bbox[img * 4 + 3] = b3;
        out[16644 + img * 4 + 0] = b0; out[16644 + img * 4 + 1] = b1;
        out[16644 + img * 4 + 2] = b2; out[16644 + img * 4 + 3] = b3;
    }
    __syncthreads();
    int j = tid;
    float a = pe_b1[j];
    #pragma unroll
    for (int k = 0; k < 4; k++) a += sbb[k] * pe_w1[k * 256 + j];
    sp1[j] = fmaxf(a, 0.0f);
    __syncthreads();
    float a2 = pe_b2[j];
    #pragma unroll 8
    for (int k = 0; k < 256; k++) a2 += sp1[k] * pe_w2[k * 256 + j];
    g_pos2[img * 256 + j] = fmaxf(a2, 0.0f);
}

// ---------------- fused cluster LSTM (weights in registers) ----------------
// grid 32 = 2 clusters x 16 CTAs. cluster 0 = layer0, cluster 1 = layer1.
// CTA rank r owns 16 hidden units (64 gate cols). Thread (kc 0..7, cg 0..31):
//   unified k-chunk kc*64.. (kc<4 -> Wx rows, kc>=4 -> Wh rows), column pair
//   ci = {2cg, 2cg+1}. Weights live in 64 packed f32x2 REGISTERS per thread.
// Activations are staged PRE-DUPLICATED (dup2 per batch) in SMEM; h is pushed
// dup'd straight into all peers' double-buffered SMEM via DSMEM.
#define FUSED_SMEM (131072 + 16384 + 8192 + 256)

__global__ void __launch_bounds__(256, 1) mp_fused_kernel(
    const float* __restrict__ wih0, const float* __restrict__ whh0,
    const float* __restrict__ bih0, const float* __restrict__ bhh0,
    const float* __restrict__ wih1, const float* __restrict__ whh1,
    const float* __restrict__ bih1, const float* __restrict__ bhh1,
    float* __restrict__ out)
{
    extern __shared__ char smem_raw[];
    U64*   sX    = (U64*)smem_raw;        // layer0: [t][b][256] dup (16384); layer1: [b][256] (first 1024)
    U64*   sHd   = sX + 16384;            // [2][b][256] dup mailboxes (2048)
    U64*   sPart = sHd + 2048;            // [tid][b] partials (1024)
    float* sBias = (float*)(sPart + 1024);// [64]

    int tid   = threadIdx.x;
    int layer = blockIdx.x >> 4;
    unsigned rank = ctarank();
    int kc = tid >> 5, cg = tid & 31;

    const float* Wx = layer ? wih1 : wih0;
    const float* Wh = layer ? whh1 : whh0;
    const float* bx = layer ? bih1 : bih0;
    const float* bh = layer ? bhh1 : bhh0;

    // ---- prologue: weight slice -> registers (2 cols x 64 k, packed) ----
    int ci0 = 2 * cg;
    int col0 = ((ci0 >> 4) << 8) + (int)rank * 16 + (ci0 & 15);
    const float* Wm = (kc < 4) ? Wx : Wh;
    int krbase = (kc & 3) * 64;
    U64 wAB[64];
    #pragma unroll
    for (int i = 0; i < 64; i++) {
        float2 w2 = *(const float2*)(Wm + (size_t)(krbase + i) * 1024 + col0);
        wAB[i] = pk2(w2.x, w2.y);
    }
    if (tid < 64) {
        int col = ((tid >> 4) << 8) + (int)rank * 16 + (tid & 15);
        sBias[tid] = bx[col] + bh[col];
    }
    // zero mailbox parity 0 (h_{-1} = 0)
    for (int idx = tid; idx < 1024; idx += 256) sHd[idx] = 0ull;
    // layer0: prestage the whole dup'd x sequence (128 KB)
    if (layer == 0) {
        for (int idx = tid; idx < 16384; idx += 256) {
            int t = idx >> 10, b = (idx >> 8) & 3, k = idx & 255;
            sX[idx] = dup2(g_pos2[(b * 16 + t) * 256 + k]);
        }
    }
    __syncthreads();
    CLUSTER_SYNC();

    float creg = 0.0f;   // cell state for tid<64: (b=tid>>4, u=tid&15)

    for (int t = 0; t < 16; t++) {
        // ---- layer1: wait for layer0's hs0[t], stage dup'd x ----
        if (layer == 1) {
            if (tid == 0) { while (ld_acq_u32(&g_done0[t]) < 1024u) {} }
            __syncthreads();
            for (int idx = tid; idx < 1024; idx += 256)
                sX[idx] = dup2(ldcv_f32(&g_hs0f[t * 1024 + idx]));
            __syncthreads();
        }
        const U64* xb = layer ? sX : (sX + t * 1024);
        const U64* hb = sHd + (t & 1) * 1024;

        // ---- matmul: per thread 64 unified k x (2 cols) x 4 batches ----
        {
            const U64* src = (kc < 4) ? xb : hb;
            const U64* s0 = src + krbase;
            U64 a0 = 0ull, a1 = 0ull, a2 = 0ull, a3 = 0ull;
            #pragma unroll
            for (int i = 0; i < 64; i += 2) {
                ulonglong2 v0 = *(const ulonglong2*)(s0 + i);
                ulonglong2 v1 = *(const ulonglong2*)(s0 + 256 + i);
                ulonglong2 v2 = *(const ulonglong2*)(s0 + 512 + i);
                ulonglong2 v3 = *(const ulonglong2*)(s0 + 768 + i);
                a0 = fma2(v0.x, wAB[i], a0); a0 = fma2(v0.y, wAB[i + 1], a0);
                a1 = fma2(v1.x, wAB[i], a1); a1 = fma2(v1.y, wAB[i + 1], a1);
                a2 = fma2(v2.x, wAB[i], a2); a2 = fma2(v2.y, wAB[i + 1], a2);
                a3 = fma2(v3.x, wAB[i], a3); a3 = fma2(v3.y, wAB[i + 1], a3);
            }
            sPart[tid * 4 + 0] = a0;
            sPart[tid * 4 + 1] = a1;
            sPart[tid * 4 + 2] = a2;
            sPart[tid * 4 + 3] = a3;
        }
        __syncthreads();

        // ---- gates + update + push (tid<64: b=tid>>4, u=tid&15) ----
        if (tid < 64) {
            int b = tid >> 4, u = tid & 15;
            const float* pp = (const float*)sPart;
            float gate[4];
            #pragma unroll
            for (int g = 0; g < 4; g++) {
                int ci = g * 16 + u;
                int cgi = ci >> 1, half = ci & 1;
                float s = sBias[ci];
                #pragma unroll
                for (int kk = 0; kk < 8; kk++)
                    s += pp[(((kk * 32 + cgi) * 4) + b) * 2 + half];
                gate[g] = s;
            }
            float iv = sigf(gate[0]), fv = sigf(gate[1]);
            float gv = tanh_fast(gate[2]), ov = sigf(gate[3]);
            creg = fv * creg + iv * gv;
            float hv = ov * tanh_fast(creg);

            int j = (int)rank * 16 + u;
            U64 hd = dup2(hv);
            unsigned loc = smem_u32(&sHd[((t + 1) & 1) * 1024 + b * 256 + j]);
            #pragma unroll
            for (int r = 0; r < 16; r++) st_cluster_u64(loc, r, hd);

            if (layer == 0) {
                st_rel_f32(&g_hs0f[t * 1024 + b * 256 + j], hv);
                red_rel_add(&g_done0[t]);
            } else {
                out[240 + (b * 16 + t) * 256 + j] = hv;
                if (t == 15) g_h1f[b * 256 + j] = hv;
            }
        }
        CLUSTER_SYNC();
    }
}

// ---------------- heads: 4 CTAs, one per batch ----------------
__global__ void __launch_bounds__(256) mp_heads_kernel(
    const float* __restrict__ mp_w1, const float* __restrict__ mp_b1,
    const float* __restrict__ mp_w2, const float* __restrict__ mp_b2,
    const float* __restrict__ mp_w3, const float* __restrict__ mp_b3,
    const float* __restrict__ cf_w1, const float* __restrict__ cf_b1,
    const float* __restrict__ cf_w2, const float* __restrict__ cf_b2,
    float* __restrict__ out)
{
    __shared__ float slh[256];
    __shared__ float sx1[256];
    __shared__ float sx2[128];
    __shared__ float sch[128];
    __shared__ float sdel[20];
    int b   = blockIdx.x;
    int tid = threadIdx.x;

    slh[tid] = g_h1f[b * 256 + tid];
    __syncthreads();

    {
        float a = mp_b1[tid];
        #pragma unroll 8
        for (int k = 0; k < 256; k++) a += slh[k] * mp_w1[k * 256 + tid];
        sx1[tid] = fmaxf(a, 0.0f);
    }
    __syncthreads();

    if (tid < 128) {
        float a  = mp_b2[tid];
        float a2 = cf_b1[tid];
        #pragma unroll 8
        for (int k = 0; k < 256; k++) {
            a  += sx1[k] * mp_w2[k * 128 + tid];
            a2 += slh[k] * cf_w1[k * 128 + tid];
        }
        sx2[tid] = fmaxf(a, 0.0f);
        sch[tid] = fmaxf(a2, 0.0f);
    }
    __syncthreads();

    if (tid < 20) {
        float a = mp_b3[tid];
        #pragma unroll 8
        for (int k = 0; k < 128; k++) a += sx2[k] * mp_w3[k * 20 + tid];
        sdel[tid] = a;
        out[b * 20 + tid] = a;              // predicted_deltas
    }
    if (tid >= 32 && tid < 37) {
        int hh = tid - 32;
        float a = cf_b2[hh];
        #pragma unroll 8
        for (int k = 0; k < 128; k++) a += sch[k] * cf_w2[k * 5 + hh];
        out[16624 + b * 5 + hh] = sigf(a);  // confidence
    }
    __syncthreads();

    if (tid < 4) {
        int d = tid;
        float run = g_bbox[(b * 16 + 15) * 4 + d];
        #pragma unroll
        for (int hh = 0; hh < 5; hh++) {
            run += sdel[hh * 4 + d];
            out[80 + (b * 5 + hh) * 4 + d] = run;                   // predicted_bboxes
            if (d < 2) out[160 + (b * 5 + hh) * 2 + d] = run;       // locations
            else       out[200 + (b * 5 + hh) * 2 + (d - 2)] = run; // scales
        }
    }
}

extern "C" void kernel_launch(void* const* d_in, const int* in_sizes, int n_in,
                              void* d_out, int out_size) {
    (void)in_sizes; (void)n_in; (void)out_size;
    const float* pred  = (const float*)d_in[1];
    const float* pe_w1 = (const float*)d_in[2];
    const float* pe_b1 = (const float*)d_in[3];
    const float* pe_w2 = (const float*)d_in[4];
    const float* pe_b2 = (const float*)d_in[5];
    const float* wih0  = (const float*)d_in[6];
    const float* whh0  = (const float*)d_in[7];
    const float* bih0  = (const float*)d_in[8];
    const float* bhh0  = (const float*)d_in[9];
    const float* wih1  = (const float*)d_in[10];
    const float* whh1  = (const float*)d_in[11];
    const float* bih1  = (const float*)d_in[12];
    const float* bhh1  = (const float*)d_in[13];
    const float* mp_w1 = (const float*)d_in[14];
    const float* mp_b1 = (const float*)d_in[15];
    const float* mp_w2 = (const float*)d_in[16];
    const float* mp_b2 = (const float*)d_in[17];
    const float* mp_w3 = (const float*)d_in[18];
    const float* mp_b3 = (const float*)d_in[19];
    const float* cf_w1 = (const float*)d_in[20];
    const float* cf_b1 = (const float*)d_in[21];
    const float* cf_w2 = (const float*)d_in[22];
    const float* cf_b2 = (const float*)d_in[23];
    float* out = (float*)d_out;

    cudaFuncSetAttribute(mp_fused_kernel,
                         cudaFuncAttributeMaxDynamicSharedMemorySize, FUSED_SMEM);
    cudaFuncSetAttribute(mp_fused_kernel,
                         cudaFuncAttributeNonPortableClusterSizeAllowed, 1);

    mp_init_kernel<<<1, 256>>>();
    mp_scan_kernel<<<2048, 256>>>(pred);
    mp_pos_kernel<<<64, 256>>>(pe_w1, pe_b1, pe_w2, pe_b2, out);

    {
        cudaLaunchConfig_t cfg = {};
        cfg.gridDim = dim3(32, 1, 1);
        cfg.blockDim = dim3(256, 1, 1);
        cfg.dynamicSmemBytes = FUSED_SMEM;
        cfg.stream = 0;
        cudaLaunchAttribute attrs[1];
        attrs[0].id = cudaLaunchAttributeClusterDimension;
        attrs[0].val.clusterDim = {16, 1, 1};
        cfg.attrs = attrs;
        cfg.numAttrs = 1;
        cudaLaunchKernelEx(&cfg, mp_fused_kernel,
                           wih0, whh0, bih0, bhh0,
                           wih1, whh1, bih1, bhh1, out);
    }

    mp_heads_kernel<<<4, 256>>>(mp_w1, mp_b1, mp_w2, mp_b2, mp_w3, mp_b3,
                                cf_w1, cf_b1, cf_w2, cf_b2, out);
}

// round 8
// speedup vs baseline: 2.7519x; 1.0951x over previous
#include <cuda_runtime.h>
#include <cuda_bf16.h>
#include <math.h>
#include <stdint.h>

typedef unsigned long long U64;

// ---------------- device scratch (allocations are forbidden) ----------------
__device__ int   g_xmin[64], g_xmax[64], g_ymin[64], g_ymax[64];
__device__ float g_bbox[64 * 4];
__device__ float g_pos2[64 * 256];      // pos MLP output per (b*16+t)
__device__ float g_h1f[1024];           // layer1 final hidden [b*256+j] scalar

// ---------------- packed f32x2 helpers ----------------
__device__ __forceinline__ U64 pk2(float a, float b) {
    U64 r; asm("mov.b64 %0, {%1, %2};" : "=l"(r) : "f"(a), "f"(b)); return r;
}
__device__ __forceinline__ U64 dup2(float a) {
    U64 r; asm("mov.b64 %0, {%1, %1};" : "=l"(r) : "f"(a)); return r;
}
__device__ __forceinline__ U64 fma2(U64 x, U64 w, U64 a) {
    U64 d; asm("fma.rn.f32x2 %0, %1, %2, %3;" : "=l"(d) : "l"(x), "l"(w), "l"(a)); return d;
}
__device__ __forceinline__ float sigf(float x) { return 1.0f / (1.0f + __expf(-x)); }
__device__ __forceinline__ float tanh_fast(float x) {
    float e = __expf(2.0f * x);
    return 1.0f - 2.0f / (e + 1.0f);
}

// ---- cluster / DSMEM primitives ----
__device__ __forceinline__ unsigned smem_u32(const void* p) {
    unsigned r;
    asm("{ .reg .u64 t; cvta.to.shared.u64 t, %1; cvt.u32.u64 %0, t; }" : "=r"(r) : "l"(p));
    return r;
}
__device__ __forceinline__ void st_cluster_u64(unsigned laddr, unsigned rank, U64 v) {
    asm volatile("{ .reg .b32 ra; mapa.shared::cluster.u32 ra, %0, %1; st.shared::cluster.u64 [ra], %2; }"
                 :: "r"(laddr), "r"(rank), "l"(v) : "memory");
}
__device__ __forceinline__ unsigned ctarank() {
    unsigned r; asm("mov.u32 %0, %%cluster_ctarank;" : "=r"(r)); return r;
}
#define CLUSTER_SYNC() do { \
    asm volatile("barrier.cluster.arrive.aligned;" ::: "memory"); \
    asm volatile("barrier.cluster.wait.aligned;"   ::: "memory"); } while (0)

// ---------------- init: reset state every graph replay ----------------
__global__ void mp_init_kernel() {
    int t = threadIdx.x;
    if (t < 64) {
        g_xmin[t] = 0x7fffffff; g_xmax[t] = -1;
        g_ymin[t] = 0x7fffffff; g_ymax[t] = -1;
    }
}

// ---------------- 256 MB mask scan (DRAM-bound, MLP=8) ----------------
__global__ void __launch_bounds__(256) mp_scan_kernel(const float* __restrict__ pred) {
    int img   = blockIdx.x >> 5;   // 64 images (b*16+t)
    int slice = blockIdx.x & 31;   // 32 slices of 32 rows
    const float4* p4 = (const float4*)(pred + (size_t)img * (1024u * 1024u)
                                            + (size_t)slice * (32u * 1024u));
    int tid = threadIdx.x;

    int lxmin = 0x7fffffff, lxmax = -1, lymin = 0x7fffffff, lymax = -1;
    for (int rr = 0; rr < 4; rr++) {
        float4 v[8];
        #pragma unroll
        for (int u = 0; u < 8; u++)
            v[u] = __ldcs(p4 + (rr * 8 + u) * 256 + tid);
        #pragma unroll
        for (int u = 0; u < 8; u++) {
            bool m0 = v[u].x > 0.5f, m1 = v[u].y > 0.5f, m2 = v[u].z > 0.5f, m3 = v[u].w > 0.5f;
            if (m0 | m1 | m2 | m3) {
                int x0 = tid * 4;
                int f = m0 ? 0 : (m1 ? 1 : (m2 ? 2 : 3));
                int l = m3 ? 3 : (m2 ? 2 : (m1 ? 1 : 0));
                lxmin = min(lxmin, x0 + f);
                lxmax = max(lxmax, x0 + l);
                int y = slice * 32 + rr * 8 + u;
                lymin = min(lymin, y);
                lymax = max(lymax, y);
            }
        }
    }
    #pragma unroll
    for (int off = 16; off; off >>= 1) {
        lxmin = min(lxmin, __shfl_xor_sync(0xffffffffu, lxmin, off));
        lxmax = max(lxmax, __shfl_xor_sync(0xffffffffu, lxmax, off));
        lymin = min(lymin, __shfl_xor_sync(0xffffffffu, lymin, off));
        lymax = max(lymax, __shfl_xor_sync(0xffffffffu, lymax, off));
    }
    __shared__ int sx0, sx1, sy0, sy1;
    if (tid == 0) { sx0 = 0x7fffffff; sx1 = -1; sy0 = 0x7fffffff; sy1 = -1; }
    __syncthreads();
    if ((tid & 31) == 0) {
        atomicMin(&sx0, lxmin); atomicMax(&sx1, lxmax);
        atomicMin(&sy0, lymin); atomicMax(&sy1, lymax);
    }
    __syncthreads();
    if (tid == 0) {
        atomicMin(&g_xmin[img], sx0); atomicMax(&g_xmax[img], sx1);
        atomicMin(&g_ymin[img], sy0); atomicMax(&g_ymax[img], sy1);
    }
}

// ---------------- bbox finalize + pos MLP (64 CTAs, one per (b,t)) ----------------
__global__ void __launch_bounds__(256) mp_pos_kernel(
    const float* __restrict__ pe_w1, const float* __restrict__ pe_b1,
    const float* __restrict__ pe_w2, const float* __restrict__ pe_b2,
    float* __restrict__ out)
{
    __shared__ float sbb[4];
    __shared__ float sp1[256];
    int img = blockIdx.x;
    int tid = threadIdx.x;
    if (tid == 0) {
        int xm = g_xmin[img], xM = g_xmax[img], ym = g_ymin[img], yM = g_ymax[img];
        float b0, b1, b2, b3;
        if (xM < 0) { b0 = 0.5f; b1 = 0.5f; b2 = 0.1f; b3 = 0.1f; }
        else {
            b0 = (float)(xm + xM) / 2.0f / 1024.0f;
            b1 = (float)(ym + yM) / 2.0f / 1024.0f;
            b2 = (float)(xM - xm) / 1024.0f;
            b3 = (float)(yM - ym) / 1024.0f;
        }
        sbb[0] = b0; sbb[1] = b1; sbb[2] = b2; sbb[3] = b3;
        g_bbox[img * 4 + 0] = b0; g_bbox[img * 4 + 1] = b1;
        g_bbox[img * 4 + 2] = b2; g_bbox[img * 4 + 3] = b3;
        out[16644 + img * 4 + 0] = b0; out[16644 + img * 4 + 1] = b1;
        out[16644 + img * 4 + 2] = b2; out[16644 + img * 4 + 3] = b3;
    }
    __syncthreads();
    int j = tid;
    float a = pe_b1[j];
    #pragma unroll
    for (int k = 0; k < 4; k++) a += sbb[k] * pe_w1[k * 256 + j];
    sp1[j] = fmaxf(a, 0.0f);
    __syncthreads();
    float a2 = pe_b2[j];
    #pragma unroll 8
    for (int k = 0; k < 256; k++) a2 += sp1[k] * pe_w2[k * 256 + j];
    g_pos2[img * 256 + j] = fmaxf(a2, 0.0f);
}

// ---------------- fused cluster LSTM: batch-split, two sequential phases ----
// grid 32 = 2 clusters x 16 CTAs. Cluster c owns batches {2c, 2c+1} and runs
// layer0 (16 steps) then layer1 (16 steps) — NO cross-cluster communication.
// CTA rank r owns 16 hidden units (64 gate cols); weights in 64 f32x2
// registers per thread (reloaded at the phase switch). h all-gather per step
// via DSMEM push into all ranks' double-buffered mailboxes + cluster.sync.
// Layer0 h's are archived to SMEM (sXs0) and become layer1's x sequence.
#define FUSED_SMEM (65536 + 65536 + 8192 + 4096 + 256)   // 143616 B

__global__ void __launch_bounds__(256, 1) mp_fused_kernel(
    const float* __restrict__ wih0, const float* __restrict__ whh0,
    const float* __restrict__ bih0, const float* __restrict__ bhh0,
    const float* __restrict__ wih1, const float* __restrict__ whh1,
    const float* __restrict__ bih1, const float* __restrict__ bhh1,
    float* __restrict__ out)
{
    extern __shared__ char smem_raw[];
    U64*   sX0   = (U64*)smem_raw;        // [16 t][2 bl][256 k] dup  (64 KB)
    U64*   sXs0  = sX0 + 8192;            // layer0 h archive, same shape (64 KB)
    U64*   sHd   = sXs0 + 8192;           // [2 parity][2 bl][256] dup mailboxes
    U64*   sPart = sHd + 1024;            // [256 tid][2 bl]
    float* sBias = (float*)(sPart + 512); // [64]

    int tid     = threadIdx.x;
    int cluster = blockIdx.x >> 4;        // batch group
    unsigned rank = ctarank();
    int kc = tid >> 5, cg = tid & 31;
    int krbase = (kc & 3) * 64;

    // column pair this thread owns: ci0 = 2*cg (within 64 local gate cols)
    int ci0  = 2 * cg;
    int col0 = ((ci0 >> 4) << 8) + (int)rank * 16 + (ci0 & 15);

    // ---- prologue: stage dup'd x sequence for this cluster's 2 batches ----
    for (int idx = tid; idx < 8192; idx += 256) {
        int t = idx >> 9, bl = (idx >> 8) & 1, k = idx & 255;
        int b = 2 * cluster + bl;
        sX0[idx] = dup2(g_pos2[(b * 16 + t) * 256 + k]);
    }
    // zero mailbox parity 0 (h_{-1} = 0)
    for (int idx = tid; idx < 512; idx += 256) sHd[idx] = 0ull;
    __syncthreads();
    CLUSTER_SYNC();

    #pragma unroll 1
    for (int layer = 0; layer < 2; layer++) {
        // ---- per-phase: weights -> registers, bias -> smem ----
        const float* WxL = layer ? wih1 : wih0;
        const float* WhL = layer ? whh1 : whh0;
        const float* Wm  = (kc < 4) ? WxL : WhL;
        U64 wAB[64];
        #pragma unroll
        for (int i = 0; i < 64; i++) {
            float2 w2 = *(const float2*)(Wm + (size_t)(krbase + i) * 1024 + col0);
            wAB[i] = pk2(w2.x, w2.y);
        }
        if (tid < 64) {
            const float* bxL = layer ? bih1 : bih0;
            const float* bhL = layer ? bhh1 : bhh0;
            int col = ((tid >> 4) << 8) + (int)rank * 16 + (tid & 15);
            sBias[tid] = bxL[col] + bhL[col];
        }
        __syncthreads();

        const U64* xseq = layer ? sXs0 : sX0;
        float creg = 0.0f;   // cell state for tid<32: (bl=tid>>4, u=tid&15)

        for (int t = 0; t < 16; t++) {
            // archive h_{t-1} (layer0 only): mailbox parity t&1 -> sXs0[t-1]
            if (layer == 0 && t > 0) {
                sXs0[(t - 1) * 512 + tid]       = sHd[(t & 1) * 512 + tid];
                sXs0[(t - 1) * 512 + tid + 256] = sHd[(t & 1) * 512 + tid + 256];
            }
            const U64* xb = xseq + t * 512;
            const U64* hb = sHd + (t & 1) * 512;

            // ---- matmul: per thread 64 unified k x (2 cols) x 2 batches ----
            {
                const U64* s0 = ((kc < 4) ? xb : hb) + krbase;
                U64 a0 = 0ull, a1 = 0ull;
                #pragma unroll
                for (int i = 0; i < 64; i += 2) {
                    ulonglong2 v0 = *(const ulonglong2*)(s0 + i);
                    ulonglong2 v1 = *(const ulonglong2*)(s0 + 256 + i);
                    a0 = fma2(v0.x, wAB[i], a0); a0 = fma2(v0.y, wAB[i + 1], a0);
                    a1 = fma2(v1.x, wAB[i], a1); a1 = fma2(v1.y, wAB[i + 1], a1);
                }
                sPart[tid * 2 + 0] = a0;
                sPart[tid * 2 + 1] = a1;
            }
            __syncthreads();

            // ---- gates + update + DSMEM push (tid<32: bl=tid>>4, u=tid&15) ----
            if (tid < 32) {
                int bl = tid >> 4, u = tid & 15;
                const float* pp = (const float*)sPart;
                float gate[4];
                #pragma unroll
                for (int g = 0; g < 4; g++) {
                    int ci = g * 16 + u;
                    int cgi = ci >> 1, half = ci & 1;
                    float s = sBias[ci];
                    #pragma unroll
                    for (int kk = 0; kk < 8; kk++)
                        s += pp[(((kk * 32 + cgi) * 2) + bl) * 2 + half];
                    gate[g] = s;
                }
                float iv = sigf(gate[0]), fv = sigf(gate[1]);
                float gv = tanh_fast(gate[2]), ov = sigf(gate[3]);
                creg = fv * creg + iv * gv;
                float hv = ov * tanh_fast(creg);

                int j = (int)rank * 16 + u;
                U64 hd = dup2(hv);
                unsigned loc = smem_u32(&sHd[((t + 1) & 1) * 512 + bl * 256 + j]);
                #pragma unroll
                for (int r = 0; r < 16; r++) st_cluster_u64(loc, r, hd);

                if (layer == 1) {
                    int b = 2 * cluster + bl;
                    out[240 + (b * 16 + t) * 256 + j] = hv;
                    if (t == 15) g_h1f[b * 256 + j] = hv;
                }
            }
            CLUSTER_SYNC();
        }

        if (layer == 0) {
            // archive h_15 (sits in mailbox parity 0 after step 15)
            sXs0[15 * 512 + tid]       = sHd[tid];
            sXs0[15 * 512 + tid + 256] = sHd[tid + 256];
            __syncthreads();
            // reset mailbox parity 0 for layer1's h_{-1} = 0
            sHd[tid]       = 0ull;
            sHd[tid + 256] = 0ull;
            __syncthreads();
            CLUSTER_SYNC();
        }
    }
}

// ---------------- heads: 4 CTAs, one per batch ----------------
__global__ void __launch_bounds__(256) mp_heads_kernel(
    const float* __restrict__ mp_w1, const float* __restrict__ mp_b1,
    const float* __restrict__ mp_w2, const float* __restrict__ mp_b2,
    const float* __restrict__ mp_w3, const float* __restrict__ mp_b3,
    const float* __restrict__ cf_w1, const float* __restrict__ cf_b1,
    const float* __restrict__ cf_w2, const float* __restrict__ cf_b2,
    float* __restrict__ out)
{
    __shared__ float slh[256];
    __shared__ float sx1[256];
    __shared__ float sx2[128];
    __shared__ float sch[128];
    __shared__ float sdel[20];
    int b   = blockIdx.x;
    int tid = threadIdx.x;

    slh[tid] = g_h1f[b * 256 + tid];
    __syncthreads();

    {
        float a = mp_b1[tid];
        #pragma unroll 8
        for (int k = 0; k < 256; k++) a += slh[k] * mp_w1[k * 256 + tid];
        sx1[tid] = fmaxf(a, 0.0f);
    }
    __syncthreads();

    if (tid < 128) {
        float a  = mp_b2[tid];
        float a2 = cf_b1[tid];
        #pragma unroll 8
        for (int k = 0; k < 256; k++) {
            a  += sx1[k] * mp_w2[k * 128 + tid];
            a2 += slh[k] * cf_w1[k * 128 + tid];
        }
        sx2[tid] = fmaxf(a, 0.0f);
        sch[tid] = fmaxf(a2, 0.0f);
    }
    __syncthreads();

    if (tid < 20) {
        float a = mp_b3[tid];
        #pragma unroll 8
        for (int k = 0; k < 128; k++) a += sx2[k] * mp_w3[k * 20 + tid];
        sdel[tid] = a;
        out[b * 20 + tid] = a;              // predicted_deltas
    }
    if (tid >= 32 && tid < 37) {
        int hh = tid - 32;
        float a = cf_b2[hh];
        #pragma unroll 8
        for (int k = 0; k < 128; k++) a += sch[k] * cf_w2[k * 5 + hh];
        out[16624 + b * 5 + hh] = sigf(a);  // confidence
    }
    __syncthreads();

    if (tid < 4) {
        int d = tid;
        float run = g_bbox[(b * 16 + 15) * 4 + d];
        #pragma unroll
        for (int hh = 0; hh < 5; hh++) {
            run += sdel[hh * 4 + d];
            out[80 + (b * 5 + hh) * 4 + d] = run;                   // predicted_bboxes
            if (d < 2) out[160 + (b * 5 + hh) * 2 + d] = run;       // locations
            else       out[200 + (b * 5 + hh) * 2 + (d - 2)] = run; // scales
        }
    }
}

extern "C" void kernel_launch(void* const* d_in, const int* in_sizes, int n_in,
                              void* d_out, int out_size) {
    (void)in_sizes; (void)n_in; (void)out_size;
    const float* pred  = (const float*)d_in[1];
    const float* pe_w1 = (const float*)d_in[2];
    const float* pe_b1 = (const float*)d_in[3];
    const float* pe_w2 = (const float*)d_in[4];
    const float* pe_b2 = (const float*)d_in[5];
    const float* wih0  = (const float*)d_in[6];
    const float* whh0  = (const float*)d_in[7];
    const float* bih0  = (const float*)d_in[8];
    const float* bhh0  = (const float*)d_in[9];
    const float* wih1  = (const float*)d_in[10];
    const float* whh1  = (const float*)d_in[11];
    const float* bih1  = (const float*)d_in[12];
    const float* bhh1  = (const float*)d_in[13];
    const float* mp_w1 = (const float*)d_in[14];
    const float* mp_b1 = (const float*)d_in[15];
    const float* mp_w2 = (const float*)d_in[16];
    const float* mp_b2 = (const float*)d_in[17];
    const float* mp_w3 = (const float*)d_in[18];
    const float* mp_b3 = (const float*)d_in[19];
    const float* cf_w1 = (const float*)d_in[20];
    const float* cf_b1 = (const float*)d_in[21];
    const float* cf_w2 = (const float*)d_in[22];
    const float* cf_b2 = (const float*)d_in[23];
    float* out = (float*)d_out;

    cudaFuncSetAttribute(mp_fused_kernel,
                         cudaFuncAttributeMaxDynamicSharedMemorySize, FUSED_SMEM);
    cudaFuncSetAttribute(mp_fused_kernel,
                         cudaFuncAttributeNonPortableClusterSizeAllowed, 1);

    mp_init_kernel<<<1, 256>>>();
    mp_scan_kernel<<<2048, 256>>>(pred);
    mp_pos_kernel<<<64, 256>>>(pe_w1, pe_b1, pe_w2, pe_b2, out);

    {
        cudaLaunchConfig_t cfg = {};
        cfg.gridDim = dim3(32, 1, 1);
        cfg.blockDim = dim3(256, 1, 1);
        cfg.dynamicSmemBytes = FUSED_SMEM;
        cfg.stream = 0;
        cudaLaunchAttribute attrs[1];
        attrs[0].id = cudaLaunchAttributeClusterDimension;
        attrs[0].val.clusterDim = {16, 1, 1};
        cfg.attrs = attrs;
        cfg.numAttrs = 1;
        cudaLaunchKernelEx(&cfg, mp_fused_kernel,
                           wih0, whh0, bih0, bhh0,
                           wih1, whh1, bih1, bhh1, out);
    }

    mp_heads_kernel<<<4, 256>>>(mp_w1, mp_b1, mp_w2, mp_b2, mp_w3, mp_b3,
                                cf_w1, cf_b1, cf_w2, cf_b2, out);
}

// round 9
// speedup vs baseline: 2.9656x; 1.0776x over previous
#include <cuda_runtime.h>
#include <cuda_bf16.h>
#include <math.h>
#include <stdint.h>

typedef unsigned long long U64;

// ---------------- device scratch (allocations are forbidden) ----------------
__device__ int   g_xmin[64], g_xmax[64], g_ymin[64], g_ymax[64];
__device__ float g_bbox[64 * 4];
__device__ float g_pos2[64 * 256];      // pos MLP output per (b*16+t)
__device__ float g_h1f[1024];           // layer1 final hidden [b*256+j] scalar

// ---------------- packed f32x2 helpers ----------------
__device__ __forceinline__ U64 pk2(float a, float b) {
    U64 r; asm("mov.b64 %0, {%1, %2};" : "=l"(r) : "f"(a), "f"(b)); return r;
}
__device__ __forceinline__ U64 dup2(float a) {
    U64 r; asm("mov.b64 %0, {%1, %1};" : "=l"(r) : "f"(a)); return r;
}
__device__ __forceinline__ U64 fma2(U64 x, U64 w, U64 a) {
    U64 d; asm("fma.rn.f32x2 %0, %1, %2, %3;" : "=l"(d) : "l"(x), "l"(w), "l"(a)); return d;
}
__device__ __forceinline__ float sigf(float x) { return 1.0f / (1.0f + __expf(-x)); }
__device__ __forceinline__ float tanh_fast(float x) {
    float e = __expf(2.0f * x);
    return 1.0f - 2.0f / (e + 1.0f);
}

// ---- cluster / DSMEM primitives ----
__device__ __forceinline__ unsigned smem_u32(const void* p) {
    unsigned r;
    asm("{ .reg .u64 t; cvta.to.shared.u64 t, %1; cvt.u32.u64 %0, t; }" : "=r"(r) : "l"(p));
    return r;
}
__device__ __forceinline__ void st_cluster_u64(unsigned laddr, unsigned rank, U64 v) {
    asm volatile("{ .reg .b32 ra; mapa.shared::cluster.u32 ra, %0, %1; st.shared::cluster.u64 [ra], %2; }"
                 :: "r"(laddr), "r"(rank), "l"(v) : "memory");
}
__device__ __forceinline__ unsigned ctarank() {
    unsigned r; asm("mov.u32 %0, %%cluster_ctarank;" : "=r"(r)); return r;
}
#define CLUSTER_SYNC() do { \
    asm volatile("barrier.cluster.arrive.aligned;" ::: "memory"); \
    asm volatile("barrier.cluster.wait.aligned;"   ::: "memory"); } while (0)

// ---------------- init: reset state every graph replay ----------------
__global__ void mp_init_kernel() {
    int t = threadIdx.x;
    if (t < 64) {
        g_xmin[t] = 0x7fffffff; g_xmax[t] = -1;
        g_ymin[t] = 0x7fffffff; g_ymax[t] = -1;
    }
}

// ---------------- 256 MB mask scan (DRAM-bound, MLP=8) ----------------
__global__ void __launch_bounds__(256) mp_scan_kernel(const float* __restrict__ pred) {
    int img   = blockIdx.x >> 5;   // 64 images (b*16+t)
    int slice = blockIdx.x & 31;   // 32 slices of 32 rows
    const float4* p4 = (const float4*)(pred + (size_t)img * (1024u * 1024u)
                                            + (size_t)slice * (32u * 1024u));
    int tid = threadIdx.x;

    int lxmin = 0x7fffffff, lxmax = -1, lymin = 0x7fffffff, lymax = -1;
    for (int rr = 0; rr < 4; rr++) {
        float4 v[8];
        #pragma unroll
        for (int u = 0; u < 8; u++)
            v[u] = __ldcs(p4 + (rr * 8 + u) * 256 + tid);
        #pragma unroll
        for (int u = 0; u < 8; u++) {
            bool m0 = v[u].x > 0.5f, m1 = v[u].y > 0.5f, m2 = v[u].z > 0.5f, m3 = v[u].w > 0.5f;
            if (m0 | m1 | m2 | m3) {
                int x0 = tid * 4;
                int f = m0 ? 0 : (m1 ? 1 : (m2 ? 2 : 3));
                int l = m3 ? 3 : (m2 ? 2 : (m1 ? 1 : 0));
                lxmin = min(lxmin, x0 + f);
                lxmax = max(lxmax, x0 + l);
                int y = slice * 32 + rr * 8 + u;
                lymin = min(lymin, y);
                lymax = max(lymax, y);
            }
        }
    }
    #pragma unroll
    for (int off = 16; off; off >>= 1) {
        lxmin = min(lxmin, __shfl_xor_sync(0xffffffffu, lxmin, off));
        lxmax = max(lxmax, __shfl_xor_sync(0xffffffffu, lxmax, off));
        lymin = min(lymin, __shfl_xor_sync(0xffffffffu, lymin, off));
        lymax = max(lymax, __shfl_xor_sync(0xffffffffu, lymax, off));
    }
    __shared__ int sx0, sx1, sy0, sy1;
    if (tid == 0) { sx0 = 0x7fffffff; sx1 = -1; sy0 = 0x7fffffff; sy1 = -1; }
    __syncthreads();
    if ((tid & 31) == 0) {
        atomicMin(&sx0, lxmin); atomicMax(&sx1, lxmax);
        atomicMin(&sy0, lymin); atomicMax(&sy1, lymax);
    }
    __syncthreads();
    if (tid == 0) {
        atomicMin(&g_xmin[img], sx0); atomicMax(&g_xmax[img], sx1);
        atomicMin(&g_ymin[img], sy0); atomicMax(&g_ymax[img], sy1);
    }
}

// ---------------- bbox finalize + pos MLP (64 CTAs, one per (b,t)) ----------------
__global__ void __launch_bounds__(256) mp_pos_kernel(
    const float* __restrict__ pe_w1, const float* __restrict__ pe_b1,
    const float* __restrict__ pe_w2, const float* __restrict__ pe_b2,
    float* __restrict__ out)
{
    __shared__ float sbb[4];
    __shared__ float sp1[256];
    int img = blockIdx.x;
    int tid = threadIdx.x;
    if (tid == 0) {
        int xm = g_xmin[img], xM = g_xmax[img], ym = g_ymin[img], yM = g_ymax[img];
        float b0, b1, b2, b3;
        if (xM < 0) { b0 = 0.5f; b1 = 0.5f; b2 = 0.1f; b3 = 0.1f; }
        else {
            b0 = (float)(xm + xM) / 2.0f / 1024.0f;
            b1 = (float)(ym + yM) / 2.0f / 1024.0f;
            b2 = (float)(xM - xm) / 1024.0f;
            b3 = (float)(yM - ym) / 1024.0f;
        }
        sbb[0] = b0; sbb[1] = b1; sbb[2] = b2; sbb[3] = b3;
        g_bbox[img * 4 + 0] = b0; g_bbox[img * 4 + 1] = b1;
        g_bbox[img * 4 + 2] = b2; g_bbox[img * 4 + 3] = b3;
        out[16644 + img * 4 + 0] = b0; out[16644 + img * 4 + 1] = b1;
        out[16644 + img * 4 + 2] = b2; out[16644 + img * 4 + 3] = b3;
    }
    __syncthreads();
    int j = tid;
    float a = pe_b1[j];
    #pragma unroll
    for (int k = 0; k < 4; k++) a += sbb[k] * pe_w1[k * 256 + j];
    sp1[j] = fmaxf(a, 0.0f);
    __syncthreads();
    float a2 = pe_b2[j];
    #pragma unroll 8
    for (int k = 0; k < 256; k++) a2 += sp1[k] * pe_w2[k * 256 + j];
    g_pos2[img * 256 + j] = fmaxf(a2, 0.0f);
}

// ---------------- fused cluster LSTM: one batch per cluster ----------------
// grid 64 = 4 clusters x 16 CTAs. Cluster c owns batch c; runs layer0 (16
// steps) then layer1 (16 steps) with zero cross-cluster traffic.
// CTA rank r owns 16 hidden units (64 gate cols); weights in 64 f32x2
// registers per thread (reloaded at phase switch). h all-gathered per step
// via DSMEM push into all 16 ranks' double-buffered mailboxes + cluster.sync.
// Layer0 h's are archived in SMEM and become layer1's x sequence.
#define FUSED_SMEM (32768 + 32768 + 4096 + 2048 + 256)   // 71936 B

__global__ void __launch_bounds__(256, 1) mp_fused_kernel(
    const float* __restrict__ wih0, const float* __restrict__ whh0,
    const float* __restrict__ bih0, const float* __restrict__ bhh0,
    const float* __restrict__ wih1, const float* __restrict__ whh1,
    const float* __restrict__ bih1, const float* __restrict__ bhh1,
    float* __restrict__ out)
{
    extern __shared__ char smem_raw[];
    U64*   sX0   = (U64*)smem_raw;        // [16 t][256 k] dup (32 KB)
    U64*   sXs0  = sX0 + 4096;            // layer0 h archive (32 KB)
    U64*   sHd   = sXs0 + 4096;           // [2 parity][256] dup mailboxes (4 KB)
    U64*   sPart = sHd + 512;             // [256 tid] (2 KB)
    float* sBias = (float*)(sPart + 256); // [64]

    int tid = threadIdx.x;
    int b   = blockIdx.x >> 4;            // batch = cluster id
    unsigned rank = ctarank();
    int kc = tid >> 5, cg = tid & 31;
    int krbase = (kc & 3) * 64;

    // column pair this thread owns: ci0 = 2*cg (within 64 local gate cols)
    int ci0  = 2 * cg;
    int col0 = ((ci0 >> 4) << 8) + (int)rank * 16 + (ci0 & 15);

    // ---- prologue: stage dup'd x sequence for this cluster's batch ----
    for (int idx = tid; idx < 4096; idx += 256) {
        int t = idx >> 8, k = idx & 255;
        sX0[idx] = dup2(g_pos2[(b * 16 + t) * 256 + k]);
    }
    // zero mailbox parity 0 (h_{-1} = 0)
    for (int idx = tid; idx < 512; idx += 256) sHd[idx] = 0ull;
    __syncthreads();
    CLUSTER_SYNC();

    #pragma unroll 1
    for (int layer = 0; layer < 2; layer++) {
        // ---- per-phase: weights -> registers, bias -> smem ----
        const float* WxL = layer ? wih1 : wih0;
        const float* WhL = layer ? whh1 : whh0;
        const float* Wm  = (kc < 4) ? WxL : WhL;
        U64 wAB[64];
        #pragma unroll
        for (int i = 0; i < 64; i++) {
            float2 w2 = *(const float2*)(Wm + (size_t)(krbase + i) * 1024 + col0);
            wAB[i] = pk2(w2.x, w2.y);
        }
        if (tid < 64) {
            const float* bxL = layer ? bih1 : bih0;
            const float* bhL = layer ? bhh1 : bhh0;
            int col = ((tid >> 4) << 8) + (int)rank * 16 + (tid & 15);
            sBias[tid] = bxL[col] + bhL[col];
        }
        __syncthreads();

        const U64* xseq = layer ? sXs0 : sX0;
        float creg = 0.0f;   // cell state for tid<16: u = tid

        for (int t = 0; t < 16; t++) {
            // archive h_{t-1} (layer0 only): mailbox parity t&1 -> sXs0[t-1]
            if (layer == 0 && t > 0)
                sXs0[(t - 1) * 256 + tid] = sHd[(t & 1) * 256 + tid];

            const U64* xb = xseq + t * 256;
            const U64* hb = sHd + (t & 1) * 256;

            // ---- matmul: per thread 64 unified k x (2 cols) x 1 batch ----
            {
                const U64* s0 = ((kc < 4) ? xb : hb) + krbase;
                U64 a0 = 0ull;
                #pragma unroll
                for (int i = 0; i < 64; i += 2) {
                    ulonglong2 v = *(const ulonglong2*)(s0 + i);
                    a0 = fma2(v.x, wAB[i], a0);
                    a0 = fma2(v.y, wAB[i + 1], a0);
                }
                sPart[tid] = a0;
            }
            __syncthreads();

            // ---- gates + update + DSMEM push (tid<16: u = tid) ----
            if (tid < 16) {
                int u = tid;
                const float* pp = (const float*)sPart;
                float gate[4];
                #pragma unroll
                for (int g = 0; g < 4; g++) {
                    int ci = g * 16 + u;
                    int cgi = ci >> 1, half = ci & 1;
                    float s = sBias[ci];
                    #pragma unroll
                    for (int kk = 0; kk < 8; kk++)
                        s += pp[(kk * 32 + cgi) * 2 + half];
                    gate[g] = s;
                }
                float iv = sigf(gate[0]), fv = sigf(gate[1]);
                float gv = tanh_fast(gate[2]), ov = sigf(gate[3]);
                creg = fv * creg + iv * gv;
                float hv = ov * tanh_fast(creg);

                int j = (int)rank * 16 + u;
                U64 hd = dup2(hv);
                unsigned loc = smem_u32(&sHd[((t + 1) & 1) * 256 + j]);
                #pragma unroll
                for (int r = 0; r < 16; r++) st_cluster_u64(loc, r, hd);

                if (layer == 1) {
                    out[240 + (b * 16 + t) * 256 + j] = hv;
                    if (t == 15) g_h1f[b * 256 + j] = hv;
                }
            }
            CLUSTER_SYNC();
        }

        if (layer == 0) {
            // archive h_15 (sits in mailbox parity 0 after step 15's sync)
            sXs0[15 * 256 + tid] = sHd[tid];
            __syncthreads();
            // reset mailbox parity 0 for layer1's h_{-1} = 0 (local only)
            if (tid < 256) sHd[tid] = 0ull;
            __syncthreads();
            CLUSTER_SYNC();
        }
    }
}

// ---------------- heads: 4 CTAs, one per batch ----------------
__global__ void __launch_bounds__(256) mp_heads_kernel(
    const float* __restrict__ mp_w1, const float* __restrict__ mp_b1,
    const float* __restrict__ mp_w2, const float* __restrict__ mp_b2,
    const float* __restrict__ mp_w3, const float* __restrict__ mp_b3,
    const float* __restrict__ cf_w1, const float* __restrict__ cf_b1,
    const float* __restrict__ cf_w2, const float* __restrict__ cf_b2,
    float* __restrict__ out)
{
    __shared__ float slh[256];
    __shared__ float sx1[256];
    __shared__ float sx2[128];
    __shared__ float sch[128];
    __shared__ float sdel[20];
    int b   = blockIdx.x;
    int tid = threadIdx.x;

    slh[tid] = g_h1f[b * 256 + tid];
    __syncthreads();

    {
        float a = mp_b1[tid];
        #pragma unroll 8
        for (int k = 0; k < 256; k++) a += slh[k] * mp_w1[k * 256 + tid];
        sx1[tid] = fmaxf(a, 0.0f);
    }
    __syncthreads();

    if (tid < 128) {
        float a  = mp_b2[tid];
        float a2 = cf_b1[tid];
        #pragma unroll 8
        for (int k = 0; k < 256; k++) {
            a  += sx1[k] * mp_w2[k * 128 + tid];
            a2 += slh[k] * cf_w1[k * 128 + tid];
        }
        sx2[tid] = fmaxf(a, 0.0f);
        sch[tid] = fmaxf(a2, 0.0f);
    }
    __syncthreads();

    if (tid < 20) {
        float a = mp_b3[tid];
        #pragma unroll 8
        for (int k = 0; k < 128; k++) a += sx2[k] * mp_w3[k * 20 + tid];
        sdel[tid] = a;
        out[b * 20 + tid] = a;              // predicted_deltas
    }
    if (tid >= 32 && tid < 37) {
        int hh = tid - 32;
        float a = cf_b2[hh];
        #pragma unroll 8
        for (int k = 0; k < 128; k++) a += sch[k] * cf_w2[k * 5 + hh];
        out[16624 + b * 5 + hh] = sigf(a);  // confidence
    }
    __syncthreads();

    if (tid < 4) {
        int d = tid;
        float run = g_bbox[(b * 16 + 15) * 4 + d];
        #pragma unroll
        for (int hh = 0; hh < 5; hh++) {
            run += sdel[hh * 4 + d];
            out[80 + (b * 5 + hh) * 4 + d] = run;                   // predicted_bboxes
            if (d < 2) out[160 + (b * 5 + hh) * 2 + d] = run;       // locations
            else       out[200 + (b * 5 + hh) * 2 + (d - 2)] = run; // scales
        }
    }
}

extern "C" void kernel_launch(void* const* d_in, const int* in_sizes, int n_in,
                              void* d_out, int out_size) {
    (void)in_sizes; (void)n_in; (void)out_size;
    const float* pred  = (const float*)d_in[1];
    const float* pe_w1 = (const float*)d_in[2];
    const float* pe_b1 = (const float*)d_in[3];
    const float* pe_w2 = (const float*)d_in[4];
    const float* pe_b2 = (const float*)d_in[5];
    const float* wih0  = (const float*)d_in[6];
    const float* whh0  = (const float*)d_in[7];
    const float* bih0  = (const float*)d_in[8];
    const float* bhh0  = (const float*)d_in[9];
    const float* wih1  = (const float*)d_in[10];
    const float* whh1  = (const float*)d_in[11];
    const float* bih1  = (const float*)d_in[12];
    const float* bhh1  = (const float*)d_in[13];
    const float* mp_w1 = (const float*)d_in[14];
    const float* mp_b1 = (const float*)d_in[15];
    const float* mp_w2 = (const float*)d_in[16];
    const float* mp_b2 = (const float*)d_in[17];
    const float* mp_w3 = (const float*)d_in[18];
    const float* mp_b3 = (const float*)d_in[19];
    const float* cf_w1 = (const float*)d_in[20];
    const float* cf_b1 = (const float*)d_in[21];
    const float* cf_w2 = (const float*)d_in[22];
    const float* cf_b2 = (const float*)d_in[23];
    float* out = (float*)d_out;

    cudaFuncSetAttribute(mp_fused_kernel,
                         cudaFuncAttributeMaxDynamicSharedMemorySize, FUSED_SMEM);
    cudaFuncSetAttribute(mp_fused_kernel,
                         cudaFuncAttributeNonPortableClusterSizeAllowed, 1);

    mp_init_kernel<<<1, 256>>>();
    mp_scan_kernel<<<2048, 256>>>(pred);
    mp_pos_kernel<<<64, 256>>>(pe_w1, pe_b1, pe_w2, pe_b2, out);

    {
        cudaLaunchConfig_t cfg = {};
        cfg.gridDim = dim3(64, 1, 1);
        cfg.blockDim = dim3(256, 1, 1);
        cfg.dynamicSmemBytes = FUSED_SMEM;
        cfg.stream = 0;
        cudaLaunchAttribute attrs[1];
        attrs[0].id = cudaLaunchAttributeClusterDimension;
        attrs[0].val.clusterDim = {16, 1, 1};
        cfg.attrs = attrs;
        cfg.numAttrs = 1;
        cudaLaunchKernelEx(&cfg, mp_fused_kernel,
                           wih0, whh0, bih0, bhh0,
                           wih1, whh1, bih1, bhh1, out);
    }

    mp_heads_kernel<<<4, 256>>>(mp_w1, mp_b1, mp_w2, mp_b2, mp_w3, mp_b3,
                                cf_w1, cf_b1, cf_w2, cf_b2, out);
}

// round 12
// speedup vs baseline: 3.2928x; 1.1103x over previous
#include <cuda_runtime.h>
#include <cuda_bf16.h>
#include <math.h>
#include <stdint.h>

typedef unsigned long long U64;

// ---------------- device scratch (allocations are forbidden) ----------------
__device__ int4 g_part[2048];           // per-(img,slice) mask extents

// ---------------- packed f32x2 helpers ----------------
__device__ __forceinline__ U64 pk2(float a, float b) {
    U64 r; asm("mov.b64 %0, {%1, %2};" : "=l"(r) : "f"(a), "f"(b)); return r;
}
__device__ __forceinline__ float2 upk(U64 v) {
    float2 f; asm("mov.b64 {%0, %1}, %2;" : "=f"(f.x), "=f"(f.y) : "l"(v)); return f;
}
__device__ __forceinline__ U64 dup2(float a) {
    U64 r; asm("mov.b64 %0, {%1, %1};" : "=l"(r) : "f"(a)); return r;
}
__device__ __forceinline__ U64 fma2(U64 x, U64 w, U64 a) {
    U64 d; asm("fma.rn.f32x2 %0, %1, %2, %3;" : "=l"(d) : "l"(x), "l"(w), "l"(a)); return d;
}
__device__ __forceinline__ float sigf(float x) { return 1.0f / (1.0f + __expf(-x)); }
__device__ __forceinline__ float tanh_fast(float x) {
    float e = __expf(2.0f * x);
    return 1.0f - 2.0f / (e + 1.0f);
}

// ---- cluster / DSMEM primitives (proven in round 9) ----
__device__ __forceinline__ unsigned smem_u32(const void* p) {
    unsigned r;
    asm("{ .reg .u64 t; cvta.to.shared.u64 t, %1; cvt.u32.u64 %0, t; }" : "=r"(r) : "l"(p));
    return r;
}
__device__ __forceinline__ void st_cluster_u64(unsigned laddr, unsigned rank, U64 v) {
    asm volatile("{ .reg .b32 ra; mapa.shared::cluster.u32 ra, %0, %1; st.shared::cluster.u64 [ra], %2; }"
                 :: "r"(laddr), "r"(rank), "l"(v) : "memory");
}
__device__ __forceinline__ void st_cluster_f32(unsigned laddr, unsigned rank, float v) {
    asm volatile("{ .reg .b32 ra; mapa.shared::cluster.u32 ra, %0, %1; st.shared::cluster.f32 [ra], %2; }"
                 :: "r"(laddr), "r"(rank), "f"(v) : "memory");
}
__device__ __forceinline__ unsigned ctarank() {
    unsigned r; asm("mov.u32 %0, %%cluster_ctarank;" : "=r"(r)); return r;
}
#define CLUSTER_SYNC() do { \
    asm volatile("barrier.cluster.arrive.aligned;" ::: "memory"); \
    asm volatile("barrier.cluster.wait.aligned;"   ::: "memory"); } while (0)

// ---------------- 256 MB mask scan (DRAM-bound, MLP=8, no atomics) ----------
__global__ void __launch_bounds__(256) mp_scan_kernel(const float* __restrict__ pred) {
    int img   = blockIdx.x >> 5;   // 64 images (b*16+t)
    int slice = blockIdx.x & 31;   // 32 slices of 32 rows
    const float4* p4 = (const float4*)(pred + (size_t)img * (1024u * 1024u)
                                            + (size_t)slice * (32u * 1024u));
    int tid = threadIdx.x;

    int lxmin = 0x7fffffff, lxmax = -1, lymin = 0x7fffffff, lymax = -1;
    for (int rr = 0; rr < 4; rr++) {
        float4 v[8];
        #pragma unroll
        for (int u = 0; u < 8; u++)
            v[u] = __ldcs(p4 + (rr * 8 + u) * 256 + tid);
        #pragma unroll
        for (int u = 0; u < 8; u++) {
            bool m0 = v[u].x > 0.5f, m1 = v[u].y > 0.5f, m2 = v[u].z > 0.5f, m3 = v[u].w > 0.5f;
            if (m0 | m1 | m2 | m3) {
                int x0 = tid * 4;
                int f = m0 ? 0 : (m1 ? 1 : (m2 ? 2 : 3));
                int l = m3 ? 3 : (m2 ? 2 : (m1 ? 1 : 0));
                lxmin = min(lxmin, x0 + f);
                lxmax = max(lxmax, x0 + l);
                int y = slice * 32 + rr * 8 + u;
                lymin = min(lymin, y);
                lymax = max(lymax, y);
            }
        }
    }
    #pragma unroll
    for (int off = 16; off; off >>= 1) {
        lxmin = min(lxmin, __shfl_xor_sync(0xffffffffu, lxmin, off));
        lxmax = max(lxmax, __shfl_xor_sync(0xffffffffu, lxmax, off));
        lymin = min(lymin, __shfl_xor_sync(0xffffffffu, lymin, off));
        lymax = max(lymax, __shfl_xor_sync(0xffffffffu, lymax, off));
    }
    __shared__ int sx0, sx1, sy0, sy1;
    if (tid == 0) { sx0 = 0x7fffffff; sx1 = -1; sy0 = 0x7fffffff; sy1 = -1; }
    __syncthreads();
    if ((tid & 31) == 0) {
        atomicMin(&sx0, lxmin); atomicMax(&sx1, lxmax);
        atomicMin(&sy0, lymin); atomicMax(&sy1, lymax);
    }
    __syncthreads();
    if (tid == 0) g_part[blockIdx.x] = make_int4(sx0, sx1, sy0, sy1);
}

// ---------------- fused: bbox+posMLP prologue, cluster LSTM, heads epilogue --
// grid 64 = 4 clusters x 16 CTAs. Cluster c owns batch c. Rank r:
//  - prologue: reduce image (c*16+r)'s 32 slice extents, bbox, pos MLP,
//    DSMEM-push dup'd x row r into all 16 ranks' sX0; push bbox into sBB.
//  - LSTM loop: identical to round 9 (weights in 64 f32x2 regs, DSMEM h
//    all-gather + CLUSTER_SYNC per step, layer0 then layer1).
//  - epilogue (rank 0): heads for batch c from local parity-0 mailbox.
#define FUSED_SMEM (32768 + 32768 + 4096 + 2048 + 256 + 256)

__global__ void __launch_bounds__(256, 1) mp_fused_kernel(
    const float* __restrict__ pe_w1, const float* __restrict__ pe_b1,
    const float* __restrict__ pe_w2, const float* __restrict__ pe_b2,
    const float* __restrict__ wih0, const float* __restrict__ whh0,
    const float* __restrict__ bih0, const float* __restrict__ bhh0,
    const float* __restrict__ wih1, const float* __restrict__ whh1,
    const float* __restrict__ bih1, const float* __restrict__ bhh1,
    const float* __restrict__ mp_w1, const float* __restrict__ mp_b1,
    const float* __restrict__ mp_w2, const float* __restrict__ mp_b2,
    const float* __restrict__ mp_w3, const float* __restrict__ mp_b3,
    const float* __restrict__ cf_w1, const float* __restrict__ cf_b1,
    const float* __restrict__ cf_w2, const float* __restrict__ cf_b2,
    float* __restrict__ out)
{
    extern __shared__ char smem_raw[];
    U64*   sX0   = (U64*)smem_raw;        // [16 t][256 k] dup (32 KB)
    U64*   sXs0  = sX0 + 4096;            // layer0 h archive / scratch (32 KB)
    U64*   sHd   = sXs0 + 4096;           // [2 parity][256] dup mailboxes (4 KB)
    U64*   sPart = sHd + 512;             // [256 tid] (2 KB)
    float* sBias = (float*)(sPart + 256); // [64]
    float* sBB   = sBias + 64;            // [16 ranks][4] bboxes

    int tid = threadIdx.x;
    int b   = blockIdx.x >> 4;            // batch = cluster id
    unsigned rank = ctarank();
    int kc = tid >> 5, cg = tid & 31;
    int krbase = (kc & 3) * 64;
    int img = b * 16 + (int)rank;

    // column pair this thread owns: ci0 = 2*cg (within 64 local gate cols)
    int ci0  = 2 * cg;
    int col0 = ((ci0 >> 4) << 8) + (int)rank * 16 + (ci0 & 15);

    // ======== prologue: bbox reduce + pos MLP + x all-gather ========
    if (tid < 32) {
        int4 v = g_part[img * 32 + tid];
        int xm = v.x, xM = v.y, ym = v.z, yM = v.w;
        #pragma unroll
        for (int off = 16; off; off >>= 1) {
            xm = min(xm, __shfl_xor_sync(0xffffffffu, xm, off));
            xM = max(xM, __shfl_xor_sync(0xffffffffu, xM, off));
            ym = min(ym, __shfl_xor_sync(0xffffffffu, ym, off));
            yM = max(yM, __shfl_xor_sync(0xffffffffu, yM, off));
        }
        if (tid == 0) {
            float b0, b1, b2, b3;
            if (xM < 0) { b0 = 0.5f; b1 = 0.5f; b2 = 0.1f; b3 = 0.1f; }
            else {
                b0 = (float)(xm + xM) / 2.0f / 1024.0f;
                b1 = (float)(ym + yM) / 2.0f / 1024.0f;
                b2 = (float)(xM - xm) / 1024.0f;
                b3 = (float)(yM - ym) / 1024.0f;
            }
            sBB[rank * 4 + 0] = b0; sBB[rank * 4 + 1] = b1;
            sBB[rank * 4 + 2] = b2; sBB[rank * 4 + 3] = b3;
            out[16644 + img * 4 + 0] = b0; out[16644 + img * 4 + 1] = b1;
            out[16644 + img * 4 + 2] = b2; out[16644 + img * 4 + 3] = b3;
        }
    }
    __syncthreads();
    // broadcast own bbox to all ranks' sBB[rank]
    if (tid < 4) {
        float v = sBB[rank * 4 + tid];
        unsigned loc = smem_u32(&sBB[rank * 4 + tid]);
        #pragma unroll
        for (int r = 0; r < 16; r++) st_cluster_f32(loc, r, v);
    }
    // pos MLP layer 1 (sp1 aliases sXs0 — unused until LSTM archive)
    float* sp1 = (float*)sXs0;
    {
        float a = pe_b1[tid];
        #pragma unroll
        for (int k = 0; k < 4; k++) a += sBB[rank * 4 + k] * pe_w1[k * 256 + tid];
        sp1[tid] = fmaxf(a, 0.0f);
    }
    __syncthreads();
    // pos MLP layer 2 + all-gather dup'd x row into every rank's sX0[rank]
    {
        float a2 = pe_b2[tid];
        #pragma unroll 8
        for (int k = 0; k < 256; k++) a2 += sp1[k] * pe_w2[k * 256 + tid];
        U64 xd = dup2(fmaxf(a2, 0.0f));
        unsigned loc = smem_u32(&sX0[(int)rank * 256 + tid]);
        #pragma unroll
        for (int r = 0; r < 16; r++) st_cluster_u64(loc, r, xd);
    }
    for (int idx = tid; idx < 512; idx += 256) sHd[idx] = 0ull;  // h_{-1}=0
    __syncthreads();
    CLUSTER_SYNC();

    // ======== LSTM: identical structure to round 9 (passing) ========
    #pragma unroll 1
    for (int layer = 0; layer < 2; layer++) {
        const float* WxL = layer ? wih1 : wih0;
        const float* WhL = layer ? whh1 : whh0;
        const float* Wm  = (kc < 4) ? WxL : WhL;
        U64 wAB[64];
        #pragma unroll
        for (int i = 0; i < 64; i++) {
            float2 w2 = *(const float2*)(Wm + (size_t)(krbase + i) * 1024 + col0);
            wAB[i] = pk2(w2.x, w2.y);
        }
        if (tid < 64) {
            const float* bxL = layer ? bih1 : bih0;
            const float* bhL = layer ? bhh1 : bhh0;
            int col = ((tid >> 4) << 8) + (int)rank * 16 + (tid & 15);
            sBias[tid] = bxL[col] + bhL[col];
        }
        __syncthreads();

        const U64* xseq = layer ? sXs0 : sX0;
        float creg = 0.0f;   // cell state for tid<16: u = tid

        for (int t = 0; t < 16; t++) {
            // archive h_{t-1} (layer0 only): mailbox parity t&1 -> sXs0[t-1]
            if (layer == 0 && t > 0)
                sXs0[(t - 1) * 256 + tid] = sHd[(t & 1) * 256 + tid];

            const U64* xb = xseq + t * 256;
            const U64* hb = sHd + (t & 1) * 256;

            // ---- matmul: per thread 64 unified k x (2 cols) ----
            {
                const U64* s0 = ((kc < 4) ? xb : hb) + krbase;
                U64 a0 = 0ull;
                #pragma unroll
                for (int i = 0; i < 64; i += 2) {
                    ulonglong2 v = *(const ulonglong2*)(s0 + i);
                    a0 = fma2(v.x, wAB[i], a0);
                    a0 = fma2(v.y, wAB[i + 1], a0);
                }
                sPart[tid] = a0;
            }
            __syncthreads();

            // ---- gates + update + DSMEM push (tid<16: u = tid) ----
            if (tid < 16) {
                int u = tid;
                const float* pp = (const float*)sPart;
                float gate[4];
                #pragma unroll
                for (int g = 0; g < 4; g++) {
                    int ci = g * 16 + u;
                    int cgi = ci >> 1, half = ci & 1;
                    float s = sBias[ci];
                    #pragma unroll
                    for (int kk = 0; kk < 8; kk++)
                        s += pp[(kk * 32 + cgi) * 2 + half];
                    gate[g] = s;
                }
                float iv = sigf(gate[0]), fv = sigf(gate[1]);
                float gv = tanh_fast(gate[2]), ov = sigf(gate[3]);
                creg = fv * creg + iv * gv;
                float hv = ov * tanh_fast(creg);

                int j = (int)rank * 16 + u;
                U64 hd = dup2(hv);
                unsigned loc = smem_u32(&sHd[((t + 1) & 1) * 256 + j]);
                #pragma unroll
                for (int r = 0; r < 16; r++) st_cluster_u64(loc, r, hd);

                if (layer == 1)
                    out[240 + (b * 16 + t) * 256 + j] = hv;
            }
            CLUSTER_SYNC();
        }

        if (layer == 0) {
            // archive h_15 (sits in mailbox parity 0 after step 15's sync)
            sXs0[15 * 256 + tid] = sHd[tid];
            __syncthreads();
            sHd[tid] = 0ull;                // layer1 h_{-1} = 0 (parity 0)
            __syncthreads();
            CLUSTER_SYNC();
        }
    }

    // ======== epilogue: heads on rank 0 (local mailbox holds h_15) ========
    if (rank == 0) {
        float* slh  = (float*)sXs0;     // [256]
        float* sx1  = slh + 256;        // [256]
        float* sx2  = sx1 + 256;        // [128]
        float* sch  = sx2 + 128;        // [128]
        float* sdel = sch + 128;        // [20]

        slh[tid] = upk(sHd[tid]).x;     // parity-0 mailbox = h_15
        __syncthreads();

        {
            float a = mp_b1[tid];
            #pragma unroll 8
            for (int k = 0; k < 256; k++) a += slh[k] * mp_w1[k * 256 + tid];
            sx1[tid] = fmaxf(a, 0.0f);
        }
        __syncthreads();

        if (tid < 128) {
            float a  = mp_b2[tid];
            float a2 = cf_b1[tid];
            #pragma unroll 8
            for (int k = 0; k < 256; k++) {
                a  += sx1[k] * mp_w2[k * 128 + tid];
                a2 += slh[k] * cf_w1[k * 128 + tid];
            }
            sx2[tid] = fmaxf(a, 0.0f);
            sch[tid] = fmaxf(a2, 0.0f);
        }
        __syncthreads();

        if (tid < 20) {
            float a = mp_b3[tid];
            #pragma unroll 8
            for (int k = 0; k < 128; k++) a += sx2[k] * mp_w3[k * 20 + tid];
            sdel[tid] = a;
            out[b * 20 + tid] = a;              // predicted_deltas
        }
        if (tid >= 32 && tid < 37) {
            int hh = tid - 32;
            float a = cf_b2[hh];
            #pragma unroll 8
            for (int k = 0; k < 128; k++) a += sch[k] * cf_w2[k * 5 + hh];
            out[16624 + b * 5 + hh] = sigf(a);  // confidence
        }
        __syncthreads();

        if (tid < 4) {
            int d = tid;
            float run = sBB[15 * 4 + d];        // bbox of t=15 (pushed in prologue)
            #pragma unroll
            for (int hh = 0; hh < 5; hh++) {
                run += sdel[hh * 4 + d];
                out[80 + (b * 5 + hh) * 4 + d] = run;                   // predicted_bboxes
                if (d < 2) out[160 + (b * 5 + hh) * 2 + d] = run;       // locations
                else       out[200 + (b * 5 + hh) * 2 + (d - 2)] = run; // scales
            }
        }
    }
}

extern "C" void kernel_launch(void* const* d_in, const int* in_sizes, int n_in,
                              void* d_out, int out_size) {
    (void)in_sizes; (void)n_in; (void)out_size;
    const float* pred  = (const float*)d_in[1];
    const float* pe_w1 = (const float*)d_in[2];
    const float* pe_b1 = (const float*)d_in[3];
    const float* pe_w2 = (const float*)d_in[4];
    const float* pe_b2 = (const float*)d_in[5];
    const float* wih0  = (const float*)d_in[6];
    const float* whh0  = (const float*)d_in[7];
    const float* bih0  = (const float*)d_in[8];
    const float* bhh0  = (const float*)d_in[9];
    const float* wih1  = (const float*)d_in[10];
    const float* whh1  = (const float*)d_in[11];
    const float* bih1  = (const float*)d_in[12];
    const float* bhh1  = (const float*)d_in[13];
    const float* mp_w1 = (const float*)d_in[14];
    const float* mp_b1 = (const float*)d_in[15];
    const float* mp_w2 = (const float*)d_in[16];
    const float* mp_b2 = (const float*)d_in[17];
    const float* mp_w3 = (const float*)d_in[18];
    const float* mp_b3 = (const float*)d_in[19];
    const float* cf_w1 = (const float*)d_in[20];
    const float* cf_b1 = (const float*)d_in[21];
    const float* cf_w2 = (const float*)d_in[22];
    const float* cf_b2 = (const float*)d_in[23];
    float* out = (float*)d_out;

    cudaFuncSetAttribute(mp_fused_kernel,
                         cudaFuncAttributeMaxDynamicSharedMemorySize, FUSED_SMEM);
    cudaFuncSetAttribute(mp_fused_kernel,
                         cudaFuncAttributeNonPortableClusterSizeAllowed, 1);

    mp_scan_kernel<<<2048, 256>>>(pred);

    {
        cudaLaunchConfig_t cfg = {};
        cfg.gridDim = dim3(64, 1, 1);
        cfg.blockDim = dim3(256, 1, 1);
        cfg.dynamicSmemBytes = FUSED_SMEM;
        cfg.stream = 0;
        cudaLaunchAttribute attrs[1];
        attrs[0].id = cudaLaunchAttributeClusterDimension;
        attrs[0].val.clusterDim = {16, 1, 1};
        cfg.attrs = attrs;
        cfg.numAttrs = 1;
        cudaLaunchKernelEx(&cfg, mp_fused_kernel,
                           pe_w1, pe_b1, pe_w2, pe_b2,
                           wih0, whh0, bih0, bhh0,
                           wih1, whh1, bih1, bhh1,
                           mp_w1, mp_b1, mp_w2, mp_b2, mp_w3, mp_b3,
                           cf_w1, cf_b1, cf_w2, cf_b2, out);
    }
}

// round 13
// speedup vs baseline: 3.7012x; 1.1240x over previous
#include <cuda_runtime.h>
#include <cuda_bf16.h>
#include <math.h>
#include <stdint.h>

typedef unsigned long long U64;

// ---------------- device scratch (allocations are forbidden) ----------------
__device__ int4 g_part[2048];           // per-(img,slice) mask extents

// ---------------- packed f32x2 helpers ----------------
__device__ __forceinline__ U64 pk2(float a, float b) {
    U64 r; asm("mov.b64 %0, {%1, %2};" : "=l"(r) : "f"(a), "f"(b)); return r;
}
__device__ __forceinline__ float2 upk(U64 v) {
    float2 f; asm("mov.b64 {%0, %1}, %2;" : "=f"(f.x), "=f"(f.y) : "l"(v)); return f;
}
__device__ __forceinline__ U64 dup2(float a) {
    U64 r; asm("mov.b64 %0, {%1, %1};" : "=l"(r) : "f"(a)); return r;
}
__device__ __forceinline__ U64 fma2(U64 x, U64 w, U64 a) {
    U64 d; asm("fma.rn.f32x2 %0, %1, %2, %3;" : "=l"(d) : "l"(x), "l"(w), "l"(a)); return d;
}
__device__ __forceinline__ float sigf(float x) { return 1.0f / (1.0f + __expf(-x)); }
__device__ __forceinline__ float tanh_fast(float x) {
    float e = __expf(2.0f * x);
    return 1.0f - 2.0f / (e + 1.0f);
}

// ---- cluster / DSMEM primitives (proven in rounds 9/12) ----
__device__ __forceinline__ unsigned smem_u32(const void* p) {
    unsigned r;
    asm("{ .reg .u64 t; cvta.to.shared.u64 t, %1; cvt.u32.u64 %0, t; }" : "=r"(r) : "l"(p));
    return r;
}
__device__ __forceinline__ void st_cluster_u64(unsigned laddr, unsigned rank, U64 v) {
    asm volatile("{ .reg .b32 ra; mapa.shared::cluster.u32 ra, %0, %1; st.shared::cluster.u64 [ra], %2; }"
                 :: "r"(laddr), "r"(rank), "l"(v) : "memory");
}
__device__ __forceinline__ void st_cluster_f32(unsigned laddr, unsigned rank, float v) {
    asm volatile("{ .reg .b32 ra; mapa.shared::cluster.u32 ra, %0, %1; st.shared::cluster.f32 [ra], %2; }"
                 :: "r"(laddr), "r"(rank), "f"(v) : "memory");
}
__device__ __forceinline__ unsigned ctarank() {
    unsigned r; asm("mov.u32 %0, %%cluster_ctarank;" : "=r"(r)); return r;
}
#define CLUSTER_SYNC() do { \
    asm volatile("barrier.cluster.arrive.aligned;" ::: "memory"); \
    asm volatile("barrier.cluster.wait.aligned;"   ::: "memory"); } while (0)

// ---------------- 256 MB mask scan (DRAM-bound, MLP=8, no atomics) ----------
__global__ void __launch_bounds__(256) mp_scan_kernel(const float* __restrict__ pred) {
    int img   = blockIdx.x >> 5;   // 64 images (b*16+t)
    int slice = blockIdx.x & 31;   // 32 slices of 32 rows
    const float4* p4 = (const float4*)(pred + (size_t)img * (1024u * 1024u)
                                            + (size_t)slice * (32u * 1024u));
    int tid = threadIdx.x;

    int lxmin = 0x7fffffff, lxmax = -1, lymin = 0x7fffffff, lymax = -1;
    for (int rr = 0; rr < 4; rr++) {
        float4 v[8];
        #pragma unroll
        for (int u = 0; u < 8; u++)
            v[u] = __ldcs(p4 + (rr * 8 + u) * 256 + tid);
        #pragma unroll
        for (int u = 0; u < 8; u++) {
            bool m0 = v[u].x > 0.5f, m1 = v[u].y > 0.5f, m2 = v[u].z > 0.5f, m3 = v[u].w > 0.5f;
            if (m0 | m1 | m2 | m3) {
                int x0 = tid * 4;
                int f = m0 ? 0 : (m1 ? 1 : (m2 ? 2 : 3));
                int l = m3 ? 3 : (m2 ? 2 : (m1 ? 1 : 0));
                lxmin = min(lxmin, x0 + f);
                lxmax = max(lxmax, x0 + l);
                int y = slice * 32 + rr * 8 + u;
                lymin = min(lymin, y);
                lymax = max(lymax, y);
            }
        }
    }
    #pragma unroll
    for (int off = 16; off; off >>= 1) {
        lxmin = min(lxmin, __shfl_xor_sync(0xffffffffu, lxmin, off));
        lxmax = max(lxmax, __shfl_xor_sync(0xffffffffu, lxmax, off));
        lymin = min(lymin, __shfl_xor_sync(0xffffffffu, lymin, off));
        lymax = max(lymax, __shfl_xor_sync(0xffffffffu, lymax, off));
    }
    __shared__ int sx0, sx1, sy0, sy1;
    if (tid == 0) { sx0 = 0x7fffffff; sx1 = -1; sy0 = 0x7fffffff; sy1 = -1; }
    __syncthreads();
    if ((tid & 31) == 0) {
        atomicMin(&sx0, lxmin); atomicMax(&sx1, lxmax);
        atomicMin(&sy0, lymin); atomicMax(&sy1, lymax);
    }
    __syncthreads();
    if (tid == 0) g_part[blockIdx.x] = make_int4(sx0, sx1, sy0, sy1);
}

// ---------------- fused: bbox+posMLP prologue, cluster LSTM, heads epilogue --
// grid 64 = 4 clusters x 16 CTAs. Cluster c owns batch c. Rank r owns 16
// hidden units. LSTM sync skeleton identical to rounds 9/12 (CLUSTER_SYNC per
// step). New: x-warps precompute step t+1's input partials during step t's
// update/sync window (parity-buffered sPX); MLPs are k-split with float4.
#define FUSED_SMEM (32768 + 32768 + 4096 + 2048 + 1024 + 256 + 256)

__global__ void __launch_bounds__(256, 1) mp_fused_kernel(
    const float* __restrict__ pe_w1, const float* __restrict__ pe_b1,
    const float* __restrict__ pe_w2, const float* __restrict__ pe_b2,
    const float* __restrict__ wih0, const float* __restrict__ whh0,
    const float* __restrict__ bih0, const float* __restrict__ bhh0,
    const float* __restrict__ wih1, const float* __restrict__ whh1,
    const float* __restrict__ bih1, const float* __restrict__ bhh1,
    const float* __restrict__ mp_w1, const float* __restrict__ mp_b1,
    const float* __restrict__ mp_w2, const float* __restrict__ mp_b2,
    const float* __restrict__ mp_w3, const float* __restrict__ mp_b3,
    const float* __restrict__ cf_w1, const float* __restrict__ cf_b1,
    const float* __restrict__ cf_w2, const float* __restrict__ cf_b2,
    float* __restrict__ out)
{
    extern __shared__ char smem_raw[];
    U64*   sX0   = (U64*)smem_raw;        // [16 t][256 k] dup (32 KB)
    U64*   sXs0  = sX0 + 4096;            // layer0 h archive / scratch (32 KB)
    U64*   sHd   = sXs0 + 4096;           // [2 parity][256] dup mailboxes (4 KB)
    U64*   sPX   = sHd + 512;             // [2 parity][128] x partials (2 KB)
    U64*   sPH   = sPX + 256;             // [128] h partials (1 KB)
    float* sBias = (float*)(sPH + 128);   // [64]
    float* sBB   = sBias + 64;            // [16 ranks][4] bboxes

    int tid = threadIdx.x;
    int b   = blockIdx.x >> 4;            // batch = cluster id
    unsigned rank = ctarank();
    int kc = tid >> 5, cg = tid & 31;
    int krbase = (kc & 3) * 64;
    bool isH = (kc >= 4);
    int img = b * 16 + (int)rank;

    // column pair this thread owns: ci0 = 2*cg (within 64 local gate cols)
    int ci0  = 2 * cg;
    int col0 = ((ci0 >> 4) << 8) + (int)rank * 16 + (ci0 & 15);

    // ======== prologue: bbox reduce + pos MLP + x all-gather ========
    if (tid < 32) {
        int4 v = g_part[img * 32 + tid];
        int xm = v.x, xM = v.y, ym = v.z, yM = v.w;
        #pragma unroll
        for (int off = 16; off; off >>= 1) {
            xm = min(xm, __shfl_xor_sync(0xffffffffu, xm, off));
            xM = max(xM, __shfl_xor_sync(0xffffffffu, xM, off));
            ym = min(ym, __shfl_xor_sync(0xffffffffu, ym, off));
            yM = max(yM, __shfl_xor_sync(0xffffffffu, yM, off));
        }
        if (tid == 0) {
            float b0, b1, b2, b3;
            if (xM < 0) { b0 = 0.5f; b1 = 0.5f; b2 = 0.1f; b3 = 0.1f; }
            else {
                b0 = (float)(xm + xM) / 2.0f / 1024.0f;
                b1 = (float)(ym + yM) / 2.0f / 1024.0f;
                b2 = (float)(xM - xm) / 1024.0f;
                b3 = (float)(yM - ym) / 1024.0f;
            }
            sBB[rank * 4 + 0] = b0; sBB[rank * 4 + 1] = b1;
            sBB[rank * 4 + 2] = b2; sBB[rank * 4 + 3] = b3;
            out[16644 + img * 4 + 0] = b0; out[16644 + img * 4 + 1] = b1;
            out[16644 + img * 4 + 2] = b2; out[16644 + img * 4 + 3] = b3;
        }
    }
    __syncthreads();
    // broadcast own bbox to all ranks' sBB[rank]
    if (tid < 4) {
        float v = sBB[rank * 4 + tid];
        unsigned loc = smem_u32(&sBB[rank * 4 + tid]);
        #pragma unroll
        for (int r = 0; r < 16; r++) st_cluster_f32(loc, r, v);
    }
    // pos MLP layer 1 (scratch aliases sXs0)
    float*  sp1 = (float*)sXs0;             // [256]
    float4* pP4 = (float4*)(sp1 + 256);     // [256] float4 partials
    float*  sp2 = (float*)(pP4 + 256);      // [256]
    {
        float a = pe_b1[tid];
        #pragma unroll
        for (int k = 0; k < 4; k++) a += sBB[rank * 4 + k] * pe_w1[k * 256 + tid];
        sp1[tid] = fmaxf(a, 0.0f);
    }
    __syncthreads();
    // pos MLP layer 2: k-split (4 chunks x 64 k), 4 cols/thread via float4
    {
        int c4 = (tid & 63) * 4, kg = tid >> 6;
        float4 acc = make_float4(0.f, 0.f, 0.f, 0.f);
        const float* base = pe_w2 + (size_t)(kg * 64) * 256 + c4;
        #pragma unroll 8
        for (int i = 0; i < 64; i++) {
            float4 w = *(const float4*)(base + i * 256);
            float s = sp1[kg * 64 + i];
            acc.x += s * w.x; acc.y += s * w.y; acc.z += s * w.z; acc.w += s * w.w;
        }
        pP4[tid] = acc;
    }
    __syncthreads();
    if (tid < 64) {
        float4 a = pP4[tid], c1 = pP4[64 + tid], c2 = pP4[128 + tid], c3 = pP4[192 + tid];
        int col = tid * 4;
        sp2[col + 0] = fmaxf(a.x + c1.x + c2.x + c3.x + pe_b2[col + 0], 0.0f);
        sp2[col + 1] = fmaxf(a.y + c1.y + c2.y + c3.y + pe_b2[col + 1], 0.0f);
        sp2[col + 2] = fmaxf(a.z + c1.z + c2.z + c3.z + pe_b2[col + 2], 0.0f);
        sp2[col + 3] = fmaxf(a.w + c1.w + c2.w + c3.w + pe_b2[col + 3], 0.0f);
    }
    __syncthreads();
    // all-gather dup'd x row into every rank's sX0[rank]
    {
        U64 xd = dup2(sp2[tid]);
        unsigned loc = smem_u32(&sX0[(int)rank * 256 + tid]);
        #pragma unroll
        for (int r = 0; r < 16; r++) st_cluster_u64(loc, r, xd);
    }
    for (int idx = tid; idx < 512; idx += 256) sHd[idx] = 0ull;  // h_{-1}=0
    __syncthreads();
    CLUSTER_SYNC();

    // ======== LSTM: round-9 skeleton + x-precompute off critical path ========
    #pragma unroll 1
    for (int layer = 0; layer < 2; layer++) {
        const float* WxL = layer ? wih1 : wih0;
        const float* WhL = layer ? whh1 : whh0;
        const float* Wm  = isH ? WhL : WxL;
        U64 wAB[64];
        #pragma unroll
        for (int i = 0; i < 64; i++) {
            float2 w2 = *(const float2*)(Wm + (size_t)(krbase + i) * 1024 + col0);
            wAB[i] = pk2(w2.x, w2.y);
        }
        if (tid < 64) {
            const float* bxL = layer ? bih1 : bih0;
            const float* bhL = layer ? bhh1 : bhh0;
            int col = ((tid >> 4) << 8) + (int)rank * 16 + (tid & 15);
            sBias[tid] = bxL[col] + bhL[col];
        }
        __syncthreads();

        const U64* xseq = layer ? sXs0 : sX0;
        float creg = 0.0f;   // cell state for tid<16: u = tid

        // precompute x partials for step 0 (parity 0)
        if (!isH) {
            const U64* s0 = xseq + krbase;
            U64 a0 = 0ull;
            #pragma unroll
            for (int i = 0; i < 64; i += 2) {
                ulonglong2 v = *(const ulonglong2*)(s0 + i);
                a0 = fma2(v.x, wAB[i], a0);
                a0 = fma2(v.y, wAB[i + 1], a0);
            }
            sPX[tid] = a0;
        }

        for (int t = 0; t < 16; t++) {
            const U64* hb = sHd + (t & 1) * 256;

            if (isH) {
                // archive h_{t-1} (layer0): 128 h-threads copy 2 entries each
                if (layer == 0 && t > 0) {
                    int idx = tid - 128;
                    sXs0[(t - 1) * 256 + idx]       = hb[idx];
                    sXs0[(t - 1) * 256 + 128 + idx] = hb[128 + idx];
                }
                const U64* s0 = hb + krbase;
                U64 a0 = 0ull;
                #pragma unroll
                for (int i = 0; i < 64; i += 2) {
                    ulonglong2 v = *(const ulonglong2*)(s0 + i);
                    a0 = fma2(v.x, wAB[i], a0);
                    a0 = fma2(v.y, wAB[i + 1], a0);
                }
                sPH[tid - 128] = a0;
            } else if (t < 15) {
                // precompute NEXT step's x partials (parity (t+1)&1)
                const U64* s0 = xseq + (t + 1) * 256 + krbase;
                U64 a0 = 0ull;
                #pragma unroll
                for (int i = 0; i < 64; i += 2) {
                    ulonglong2 v = *(const ulonglong2*)(s0 + i);
                    a0 = fma2(v.x, wAB[i], a0);
                    a0 = fma2(v.y, wAB[i + 1], a0);
                }
                sPX[((t + 1) & 1) * 128 + tid] = a0;
            }
            __syncthreads();

            // ---- gates + update + DSMEM push (tid<16: u = tid) ----
            if (tid < 16) {
                int u = tid;
                const float* px = (const float*)(sPX + (t & 1) * 128);
                const float* ph = (const float*)sPH;
                float gate[4];
                #pragma unroll
                for (int g = 0; g < 4; g++) {
                    int ci = g * 16 + u;
                    int cgi = ci >> 1, half = ci & 1;
                    float s = sBias[ci];
                    #pragma unroll
                    for (int kk = 0; kk < 4; kk++)
                        s += px[(kk * 32 + cgi) * 2 + half];
                    #pragma unroll
                    for (int kk = 0; kk < 4; kk++)
                        s += ph[(kk * 32 + cgi) * 2 + half];
                    gate[g] = s;
                }
                float iv = sigf(gate[0]), fv = sigf(gate[1]);
                float gv = tanh_fast(gate[2]), ov = sigf(gate[3]);
                creg = fv * creg + iv * gv;
                float hv = ov * tanh_fast(creg);

                int j = (int)rank * 16 + u;
                U64 hd = dup2(hv);
                unsigned loc = smem_u32(&sHd[((t + 1) & 1) * 256 + j]);
                #pragma unroll
                for (int r = 0; r < 16; r++) st_cluster_u64(loc, r, hd);

                if (layer == 1)
                    out[240 + (b * 16 + t) * 256 + j] = hv;
            }
            CLUSTER_SYNC();
        }

        if (layer == 0) {
            // archive h_15 (sits in mailbox parity 0 after step 15's sync)
            sXs0[15 * 256 + tid] = sHd[tid];
            __syncthreads();
            sHd[tid] = 0ull;                // layer1 h_{-1} = 0 (parity 0)
            __syncthreads();
            CLUSTER_SYNC();
        }
    }

    // ======== epilogue: heads on rank 0 (local mailbox holds h_15) ========
    if (rank == 0) {
        float*  slh  = (float*)sXs0;            // [256]
        float4* hP4  = (float4*)(slh + 256);    // [256]
        float*  sx1  = (float*)(hP4 + 256);     // [256]
        float*  sx2  = sx1 + 256;               // [128]
        float*  sch  = sx2 + 128;               // [128]
        float*  sdel = sch + 128;               // [20] (+pad)
        float4* hPA  = (float4*)(sdel + 32);    // [256]
        float4* hPB  = hPA + 256;               // [256]

        slh[tid] = upk(sHd[tid]).x;     // parity-0 mailbox = h_15
        __syncthreads();

        // mp_w1 [256][256]: k-split 4x64, 4 cols/thread
        {
            int c4 = (tid & 63) * 4, kg = tid >> 6;
            float4 acc = make_float4(0.f, 0.f, 0.f, 0.f);
            const float* base = mp_w1 + (size_t)(kg * 64) * 256 + c4;
            #pragma unroll 8
            for (int i = 0; i < 64; i++) {
                float4 w = *(const float4*)(base + i * 256);
                float s = slh[kg * 64 + i];
                acc.x += s * w.x; acc.y += s * w.y; acc.z += s * w.z; acc.w += s * w.w;
            }
            hP4[tid] = acc;
        }
        __syncthreads();
        if (tid < 64) {
            float4 a = hP4[tid], c1 = hP4[64 + tid], c2 = hP4[128 + tid], c3 = hP4[192 + tid];
            int col = tid * 4;
            sx1[col + 0] = fmaxf(a.x + c1.x + c2.x + c3.x + mp_b1[col + 0], 0.0f);
            sx1[col + 1] = fmaxf(a.y + c1.y + c2.y + c3.y + mp_b1[col + 1], 0.0f);
            sx1[col + 2] = fmaxf(a.z + c1.z + c2.z + c3.z + mp_b1[col + 2], 0.0f);
            sx1[col + 3] = fmaxf(a.w + c1.w + c2.w + c3.w + mp_b1[col + 3], 0.0f);
        }
        __syncthreads();

        // mp_w2 & cf_w1 [256][128]: k-split 8x32, 4 cols/thread
        {
            int c4 = (tid & 31) * 4, kg = tid >> 5;
            float4 aA = make_float4(0.f, 0.f, 0.f, 0.f);
            float4 aB = make_float4(0.f, 0.f, 0.f, 0.f);
            const float* bA = mp_w2 + (size_t)(kg * 32) * 128 + c4;
            const float* bB = cf_w1 + (size_t)(kg * 32) * 128 + c4;
            #pragma unroll 8
            for (int i = 0; i < 32; i++) {
                float4 wA = *(const float4*)(bA + i * 128);
                float4 wB = *(const float4*)(bB + i * 128);
                float sA = sx1[kg * 32 + i];
                float sB = slh[kg * 32 + i];
                aA.x += sA * wA.x; aA.y += sA * wA.y; aA.z += sA * wA.z; aA.w += sA * wA.w;
                aB.x += sB * wB.x; aB.y += sB * wB.y; aB.z += sB * wB.z; aB.w += sB * wB.w;
            }
            hPA[tid] = aA;
            hPB[tid] = aB;
        }
        __syncthreads();
        if (tid < 32) {
            float4 sA = make_float4(0.f, 0.f, 0.f, 0.f);
            float4 sB = make_float4(0.f, 0.f, 0.f, 0.f);
            #pragma unroll
            for (int kg = 0; kg < 8; kg++) {
                float4 a = hPA[kg * 32 + tid];
                sA.x += a.x; sA.y += a.y; sA.z += a.z; sA.w += a.w;
                float4 bv = hPB[kg * 32 + tid];
                sB.x += bv.x; sB.y += bv.y; sB.z += bv.z; sB.w += bv.w;
            }
            int col = tid * 4;
            sx2[col + 0] = fmaxf(sA.x + mp_b2[col + 0], 0.0f);
            sx2[col + 1] = fmaxf(sA.y + mp_b2[col + 1], 0.0f);
            sx2[col + 2] = fmaxf(sA.z + mp_b2[col + 2], 0.0f);
            sx2[col + 3] = fmaxf(sA.w + mp_b2[col + 3], 0.0f);
            sch[col + 0] = fmaxf(sB.x + cf_b1[col + 0], 0.0f);
            sch[col + 1] = fmaxf(sB.y + cf_b1[col + 1], 0.0f);
            sch[col + 2] = fmaxf(sB.z + cf_b1[col + 2], 0.0f);
            sch[col + 3] = fmaxf(sB.w + cf_b1[col + 3], 0.0f);
        }
        __syncthreads();

        if (tid < 20) {
            float a = mp_b3[tid];
            #pragma unroll 8
            for (int k = 0; k < 128; k++) a += sx2[k] * mp_w3[k * 20 + tid];
            sdel[tid] = a;
            out[b * 20 + tid] = a;              // predicted_deltas
        }
        if (tid >= 32 && tid < 37) {
            int hh = tid - 32;
            float a = cf_b2[hh];
            #pragma unroll 8
            for (int k = 0; k < 128; k++) a += sch[k] * cf_w2[k * 5 + hh];
            out[16624 + b * 5 + hh] = sigf(a);  // confidence
        }
        __syncthreads();

        if (tid < 4) {
            int d = tid;
            float run = sBB[15 * 4 + d];        // bbox of t=15
            #pragma unroll
            for (int hh = 0; hh < 5; hh++) {
                run += sdel[hh * 4 + d];
                out[80 + (b * 5 + hh) * 4 + d] = run;                   // predicted_bboxes
                if (d < 2) out[160 + (b * 5 + hh) * 2 + d] = run;       // locations
                else       out[200 + (b * 5 + hh) * 2 + (d - 2)] = run; // scales
            }
        }
    }
}

extern "C" void kernel_launch(void* const* d_in, const int* in_sizes, int n_in,
                              void* d_out, int out_size) {
    (void)in_sizes; (void)n_in; (void)out_size;
    const float* pred  = (const float*)d_in[1];
    const float* pe_w1 = (const float*)d_in[2];
    const float* pe_b1 = (const float*)d_in[3];
    const float* pe_w2 = (const float*)d_in[4];
    const float* pe_b2 = (const float*)d_in[5];
    const float* wih0  = (const float*)d_in[6];
    const float* whh0  = (const float*)d_in[7];
    const float* bih0  = (const float*)d_in[8];
    const float* bhh0  = (const float*)d_in[9];
    const float* wih1  = (const float*)d_in[10];
    const float* whh1  = (const float*)d_in[11];
    const float* bih1  = (const float*)d_in[12];
    const float* bhh1  = (const float*)d_in[13];
    const float* mp_w1 = (const float*)d_in[14];
    const float* mp_b1 = (const float*)d_in[15];
    const float* mp_w2 = (const float*)d_in[16];
    const float* mp_b2 = (const float*)d_in[17];
    const float* mp_w3 = (const float*)d_in[18];
    const float* mp_b3 = (const float*)d_in[19];
    const float* cf_w1 = (const float*)d_in[20];
    const float* cf_b1 = (const float*)d_in[21];
    const float* cf_w2 = (const float*)d_in[22];
    const float* cf_b2 = (const float*)d_in[23];
    float* out = (float*)d_out;

    cudaFuncSetAttribute(mp_fused_kernel,
                         cudaFuncAttributeMaxDynamicSharedMemorySize, FUSED_SMEM);
    cudaFuncSetAttribute(mp_fused_kernel,
                         cudaFuncAttributeNonPortableClusterSizeAllowed, 1);

    mp_scan_kernel<<<2048, 256>>>(pred);

    {
        cudaLaunchConfig_t cfg = {};
        cfg.gridDim = dim3(64, 1, 1);
        cfg.blockDim = dim3(256, 1, 1);
        cfg.dynamicSmemBytes = FUSED_SMEM;
        cfg.stream = 0;
        cudaLaunchAttribute attrs[1];
        attrs[0].id = cudaLaunchAttributeClusterDimension;
        attrs[0].val.clusterDim = {16, 1, 1};
        cfg.attrs = attrs;
        cfg.numAttrs = 1;
        cudaLaunchKernelEx(&cfg, mp_fused_kernel,
                           pe_w1, pe_b1, pe_w2, pe_b2,
                           wih0, whh0, bih0, bhh0,
                           wih1, whh1, bih1, bhh1,
                           mp_w1, mp_b1, mp_w2, mp_b2, mp_w3, mp_b3,
                           cf_w1, cf_b1, cf_w2, cf_b2, out);
    }
}

// round 14
// speedup vs baseline: 3.7120x; 1.0029x over previous
#include <cuda_runtime.h>
#include <cuda_bf16.h>
#include <math.h>
#include <stdint.h>

typedef unsigned long long U64;

// ---------------- device scratch (allocations are forbidden) ----------------
__device__ int4 g_part[2048];           // per-(img,slice) mask extents

// ---------------- packed f32x2 helpers ----------------
__device__ __forceinline__ U64 pk2(float a, float b) {
    U64 r; asm("mov.b64 %0, {%1, %2};" : "=l"(r) : "f"(a), "f"(b)); return r;
}
__device__ __forceinline__ float2 upk(U64 v) {
    float2 f; asm("mov.b64 {%0, %1}, %2;" : "=f"(f.x), "=f"(f.y) : "l"(v)); return f;
}
__device__ __forceinline__ U64 dup2(float a) {
    U64 r; asm("mov.b64 %0, {%1, %1};" : "=l"(r) : "f"(a)); return r;
}
__device__ __forceinline__ U64 fma2(U64 x, U64 w, U64 a) {
    U64 d; asm("fma.rn.f32x2 %0, %1, %2, %3;" : "=l"(d) : "l"(x), "l"(w), "l"(a)); return d;
}
__device__ __forceinline__ U64 add2(U64 a, U64 b) {
    U64 d; asm("add.rn.f32x2 %0, %1, %2;" : "=l"(d) : "l"(a), "l"(b)); return d;
}
__device__ __forceinline__ float sigf(float x) { return 1.0f / (1.0f + __expf(-x)); }
__device__ __forceinline__ float tanh_fast(float x) {
    float e = __expf(2.0f * x);
    return 1.0f - 2.0f / (e + 1.0f);
}

// ---- cluster / DSMEM primitives (proven in rounds 9/12/13) ----
__device__ __forceinline__ unsigned smem_u32(const void* p) {
    unsigned r;
    asm("{ .reg .u64 t; cvta.to.shared.u64 t, %1; cvt.u32.u64 %0, t; }" : "=r"(r) : "l"(p));
    return r;
}
__device__ __forceinline__ void st_cluster_u64(unsigned laddr, unsigned rank, U64 v) {
    asm volatile("{ .reg .b32 ra; mapa.shared::cluster.u32 ra, %0, %1; st.shared::cluster.u64 [ra], %2; }"
                 :: "r"(laddr), "r"(rank), "l"(v) : "memory");
}
__device__ __forceinline__ void st_cluster_f32(unsigned laddr, unsigned rank, float v) {
    asm volatile("{ .reg .b32 ra; mapa.shared::cluster.u32 ra, %0, %1; st.shared::cluster.f32 [ra], %2; }"
                 :: "r"(laddr), "r"(rank), "f"(v) : "memory");
}
__device__ __forceinline__ unsigned ctarank() {
    unsigned r; asm("mov.u32 %0, %%cluster_ctarank;" : "=r"(r)); return r;
}
#define CLUSTER_SYNC() do { \
    asm volatile("barrier.cluster.arrive.aligned;" ::: "memory"); \
    asm volatile("barrier.cluster.wait.aligned;"   ::: "memory"); } while (0)

// ---------------- 256 MB mask scan (DRAM-bound, MLP=8, no atomics) ----------
__global__ void __launch_bounds__(256) mp_scan_kernel(const float* __restrict__ pred) {
    int img   = blockIdx.x >> 5;   // 64 images (b*16+t)
    int slice = blockIdx.x & 31;   // 32 slices of 32 rows
    const float4* p4 = (const float4*)(pred + (size_t)img * (1024u * 1024u)
                                            + (size_t)slice * (32u * 1024u));
    int tid = threadIdx.x;

    int lxmin = 0x7fffffff, lxmax = -1, lymin = 0x7fffffff, lymax = -1;
    for (int rr = 0; rr < 4; rr++) {
        float4 v[8];
        #pragma unroll
        for (int u = 0; u < 8; u++)
            v[u] = __ldcs(p4 + (rr * 8 + u) * 256 + tid);
        #pragma unroll
        for (int u = 0; u < 8; u++) {
            bool m0 = v[u].x > 0.5f, m1 = v[u].y > 0.5f, m2 = v[u].z > 0.5f, m3 = v[u].w > 0.5f;
            if (m0 | m1 | m2 | m3) {
                int x0 = tid * 4;
                int f = m0 ? 0 : (m1 ? 1 : (m2 ? 2 : 3));
                int l = m3 ? 3 : (m2 ? 2 : (m1 ? 1 : 0));
                lxmin = min(lxmin, x0 + f);
                lxmax = max(lxmax, x0 + l);
                int y = slice * 32 + rr * 8 + u;
                lymin = min(lymin, y);
                lymax = max(lymax, y);
            }
        }
    }
    #pragma unroll
    for (int off = 16; off; off >>= 1) {
        lxmin = min(lxmin, __shfl_xor_sync(0xffffffffu, lxmin, off));
        lxmax = max(lxmax, __shfl_xor_sync(0xffffffffu, lxmax, off));
        lymin = min(lymin, __shfl_xor_sync(0xffffffffu, lymin, off));
        lymax = max(lymax, __shfl_xor_sync(0xffffffffu, lymax, off));
    }
    __shared__ int sx0, sx1, sy0, sy1;
    if (tid == 0) { sx0 = 0x7fffffff; sx1 = -1; sy0 = 0x7fffffff; sy1 = -1; }
    __syncthreads();
    if ((tid & 31) == 0) {
        atomicMin(&sx0, lxmin); atomicMax(&sx1, lxmax);
        atomicMin(&sy0, lymin); atomicMax(&sy1, lymax);
    }
    __syncthreads();
    if (tid == 0) g_part[blockIdx.x] = make_int4(sx0, sx1, sy0, sy1);
}

// ---------------- fused: bbox+posMLP prologue, cluster LSTM, heads epilogue --
// grid 64 = 4 clusters x 16 CTAs. Cluster c owns batch c. Rank r owns 16
// hidden units. Skeleton identical to round 13; this round: 4-accumulator
// matmuls (chain depth /4) and two-stage update (64-thread gate sums).
#define FUSED_SMEM (32768 + 32768 + 4096 + 2048 + 1024 + 256 + 256 + 256)

__global__ void __launch_bounds__(256, 1) mp_fused_kernel(
    const float* __restrict__ pe_w1, const float* __restrict__ pe_b1,
    const float* __restrict__ pe_w2, const float* __restrict__ pe_b2,
    const float* __restrict__ wih0, const float* __restrict__ whh0,
    const float* __restrict__ bih0, const float* __restrict__ bhh0,
    const float* __restrict__ wih1, const float* __restrict__ whh1,
    const float* __restrict__ bih1, const float* __restrict__ bhh1,
    const float* __restrict__ mp_w1, const float* __restrict__ mp_b1,
    const float* __restrict__ mp_w2, const float* __restrict__ mp_b2,
    const float* __restrict__ mp_w3, const float* __restrict__ mp_b3,
    const float* __restrict__ cf_w1, const float* __restrict__ cf_b1,
    const float* __restrict__ cf_w2, const float* __restrict__ cf_b2,
    float* __restrict__ out)
{
    extern __shared__ char smem_raw[];
    U64*   sX0   = (U64*)smem_raw;        // [16 t][256 k] dup (32 KB)
    U64*   sXs0  = sX0 + 4096;            // layer0 h archive / scratch (32 KB)
    U64*   sHd   = sXs0 + 4096;           // [2 parity][256] dup mailboxes (4 KB)
    U64*   sPX   = sHd + 512;             // [2 parity][128] x partials (2 KB)
    U64*   sPH   = sPX + 256;             // [128] h partials (1 KB)
    float* sBias = (float*)(sPH + 128);   // [64]
    float* sBB   = sBias + 64;            // [16 ranks][4] bboxes
    float* sGate = sBB + 64;              // [64] gate preactivations

    int tid = threadIdx.x;
    int b   = blockIdx.x >> 4;            // batch = cluster id
    unsigned rank = ctarank();
    int kc = tid >> 5, cg = tid & 31;
    int krbase = (kc & 3) * 64;
    bool isH = (kc >= 4);
    int img = b * 16 + (int)rank;

    // column pair this thread owns: ci0 = 2*cg (within 64 local gate cols)
    int ci0  = 2 * cg;
    int col0 = ((ci0 >> 4) << 8) + (int)rank * 16 + (ci0 & 15);

    // 4-accumulator matmul over 64 packed k
    #define MM64(S0, OUT) do { \
        U64 a0 = 0ull, a1 = 0ull, a2 = 0ull, a3 = 0ull; \
        _Pragma("unroll") \
        for (int i = 0; i < 64; i += 8) { \
            ulonglong2 va = *(const ulonglong2*)((S0) + i); \
            ulonglong2 vb = *(const ulonglong2*)((S0) + i + 2); \
            ulonglong2 vc = *(const ulonglong2*)((S0) + i + 4); \
            ulonglong2 vd = *(const ulonglong2*)((S0) + i + 6); \
            a0 = fma2(va.x, wAB[i],     a0); a0 = fma2(va.y, wAB[i + 1], a0); \
            a1 = fma2(vb.x, wAB[i + 2], a1); a1 = fma2(vb.y, wAB[i + 3], a1); \
            a2 = fma2(vc.x, wAB[i + 4], a2); a2 = fma2(vc.y, wAB[i + 5], a2); \
            a3 = fma2(vd.x, wAB[i + 6], a3); a3 = fma2(vd.y, wAB[i + 7], a3); \
        } \
        (OUT) = add2(add2(a0, a1), add2(a2, a3)); \
    } while (0)

    // ======== prologue: bbox reduce + pos MLP + x all-gather ========
    if (tid < 32) {
        int4 v = g_part[img * 32 + tid];
        int xm = v.x, xM = v.y, ym = v.z, yM = v.w;
        #pragma unroll
        for (int off = 16; off; off >>= 1) {
            xm = min(xm, __shfl_xor_sync(0xffffffffu, xm, off));
            xM = max(xM, __shfl_xor_sync(0xffffffffu, xM, off));
            ym = min(ym, __shfl_xor_sync(0xffffffffu, ym, off));
            yM = max(yM, __shfl_xor_sync(0xffffffffu, yM, off));
        }
        if (tid == 0) {
            float b0, b1, b2, b3;
            if (xM < 0) { b0 = 0.5f; b1 = 0.5f; b2 = 0.1f; b3 = 0.1f; }
            else {
                b0 = (float)(xm + xM) / 2.0f / 1024.0f;
                b1 = (float)(ym + yM) / 2.0f / 1024.0f;
                b2 = (float)(xM - xm) / 1024.0f;
                b3 = (float)(yM - ym) / 1024.0f;
            }
            sBB[rank * 4 + 0] = b0; sBB[rank * 4 + 1] = b1;
            sBB[rank * 4 + 2] = b2; sBB[rank * 4 + 3] = b3;
            out[16644 + img * 4 + 0] = b0; out[16644 + img * 4 + 1] = b1;
            out[16644 + img * 4 + 2] = b2; out[16644 + img * 4 + 3] = b3;
        }
    }
    __syncthreads();
    if (tid < 4) {
        float v = sBB[rank * 4 + tid];
        unsigned loc = smem_u32(&sBB[rank * 4 + tid]);
        #pragma unroll
        for (int r = 0; r < 16; r++) st_cluster_f32(loc, r, v);
    }
    // pos MLP layer 1 (scratch aliases sXs0)
    float*  sp1 = (float*)sXs0;             // [256]
    float4* pP4 = (float4*)(sp1 + 256);     // [256] float4 partials
    float*  sp2 = (float*)(pP4 + 256);      // [256]
    {
        float a = pe_b1[tid];
        #pragma unroll
        for (int k = 0; k < 4; k++) a += sBB[rank * 4 + k] * pe_w1[k * 256 + tid];
        sp1[tid] = fmaxf(a, 0.0f);
    }
    __syncthreads();
    {
        int c4 = (tid & 63) * 4, kg = tid >> 6;
        float4 accA = make_float4(0.f, 0.f, 0.f, 0.f);
        float4 accB = make_float4(0.f, 0.f, 0.f, 0.f);
        const float* base = pe_w2 + (size_t)(kg * 64) * 256 + c4;
        #pragma unroll 8
        for (int i = 0; i < 64; i += 2) {
            float4 w0 = *(const float4*)(base + i * 256);
            float4 w1 = *(const float4*)(base + (i + 1) * 256);
            float s0 = sp1[kg * 64 + i], s1 = sp1[kg * 64 + i + 1];
            accA.x += s0 * w0.x; accA.y += s0 * w0.y; accA.z += s0 * w0.z; accA.w += s0 * w0.w;
            accB.x += s1 * w1.x; accB.y += s1 * w1.y; accB.z += s1 * w1.z; accB.w += s1 * w1.w;
        }
        pP4[tid] = make_float4(accA.x + accB.x, accA.y + accB.y,
                               accA.z + accB.z, accA.w + accB.w);
    }
    __syncthreads();
    if (tid < 64) {
        float4 a = pP4[tid], c1 = pP4[64 + tid], c2 = pP4[128 + tid], c3 = pP4[192 + tid];
        int col = tid * 4;
        sp2[col + 0] = fmaxf(a.x + c1.x + c2.x + c3.x + pe_b2[col + 0], 0.0f);
        sp2[col + 1] = fmaxf(a.y + c1.y + c2.y + c3.y + pe_b2[col + 1], 0.0f);
        sp2[col + 2] = fmaxf(a.z + c1.z + c2.z + c3.z + pe_b2[col + 2], 0.0f);
        sp2[col + 3] = fmaxf(a.w + c1.w + c2.w + c3.w + pe_b2[col + 3], 0.0f);
    }
    __syncthreads();
    {
        U64 xd = dup2(sp2[tid]);
        unsigned loc = smem_u32(&sX0[(int)rank * 256 + tid]);
        #pragma unroll
        for (int r = 0; r < 16; r++) st_cluster_u64(loc, r, xd);
    }
    for (int idx = tid; idx < 512; idx += 256) sHd[idx] = 0ull;  // h_{-1}=0
    __syncthreads();
    CLUSTER_SYNC();

    // ======== LSTM: round-13 skeleton + ILP matmuls + 2-stage update ========
    #pragma unroll 1
    for (int layer = 0; layer < 2; layer++) {
        const float* WxL = layer ? wih1 : wih0;
        const float* WhL = layer ? whh1 : whh0;
        const float* Wm  = isH ? WhL : WxL;
        U64 wAB[64];
        #pragma unroll
        for (int i = 0; i < 64; i++) {
            float2 w2 = *(const float2*)(Wm + (size_t)(krbase + i) * 1024 + col0);
            wAB[i] = pk2(w2.x, w2.y);
        }
        if (tid < 64) {
            const float* bxL = layer ? bih1 : bih0;
            const float* bhL = layer ? bhh1 : bhh0;
            int col = ((tid >> 4) << 8) + (int)rank * 16 + (tid & 15);
            sBias[tid] = bxL[col] + bhL[col];
        }
        __syncthreads();

        const U64* xseq = layer ? sXs0 : sX0;
        float creg = 0.0f;   // cell state for tid<16: u = tid

        // precompute x partials for step 0 (parity 0)
        if (!isH) {
            const U64* s0 = xseq + krbase;
            MM64(s0, sPX[tid]);
        }

        for (int t = 0; t < 16; t++) {
            const U64* hb = sHd + (t & 1) * 256;

            if (isH) {
                if (layer == 0 && t > 0) {
                    int idx = tid - 128;
                    sXs0[(t - 1) * 256 + idx]       = hb[idx];
                    sXs0[(t - 1) * 256 + 128 + idx] = hb[128 + idx];
                }
                const U64* s0 = hb + krbase;
                MM64(s0, sPH[tid - 128]);
            } else if (t < 15) {
                const U64* s0 = xseq + (t + 1) * 256 + krbase;
                MM64(s0, sPX[((t + 1) & 1) * 128 + tid]);
            }
            __syncthreads();

            // ---- stage 1: 64 threads compute gate preactivations ----
            if (tid < 64) {
                int ci = tid;                 // g*16 + u
                int cgi = ci >> 1, half = ci & 1;
                const float* px = (const float*)(sPX + (t & 1) * 128);
                const float* ph = (const float*)sPH;
                float sa = sBias[ci];
                float sb = 0.0f;
                #pragma unroll
                for (int kk = 0; kk < 4; kk++) {
                    sa += px[(kk * 32 + cgi) * 2 + half];
                    sb += ph[(kk * 32 + cgi) * 2 + half];
                }
                sGate[ci] = sa + sb;
            }
            __syncthreads();

            // ---- stage 2: nonlinearity + cell update + DSMEM push ----
            if (tid < 16) {
                int u = tid;
                float iv = sigf(sGate[u]);
                float fv = sigf(sGate[16 + u]);
                float gv = tanh_fast(sGate[32 + u]);
                float ov = sigf(sGate[48 + u]);
                creg = fv * creg + iv * gv;
                float hv = ov * tanh_fast(creg);

                int j = (int)rank * 16 + u;
                U64 hd = dup2(hv);
                unsigned loc = smem_u32(&sHd[((t + 1) & 1) * 256 + j]);
                #pragma unroll
                for (int r = 0; r < 16; r++) st_cluster_u64(loc, r, hd);

                if (layer == 1)
                    out[240 + (b * 16 + t) * 256 + j] = hv;
            }
            CLUSTER_SYNC();
        }

        if (layer == 0) {
            sXs0[15 * 256 + tid] = sHd[tid];   // archive h_15 (parity 0)
            __syncthreads();
            sHd[tid] = 0ull;                   // layer1 h_{-1} = 0 (parity 0)
            __syncthreads();
            CLUSTER_SYNC();
        }
    }

    // ======== epilogue: heads on rank 0 (local mailbox holds h_15) ========
    if (rank == 0) {
        float*  slh  = (float*)sXs0;            // [256]
        float4* hP4  = (float4*)(slh + 256);    // [256]
        float*  sx1  = (float*)(hP4 + 256);     // [256]
        float*  sx2  = sx1 + 256;               // [128]
        float*  sch  = sx2 + 128;               // [128]
        float*  sdel = sch + 128;               // [20] (+pad)
        float4* hPA  = (float4*)(sdel + 32);    // [256]
        float4* hPB  = hPA + 256;               // [256]

        slh[tid] = upk(sHd[tid]).x;     // parity-0 mailbox = h_15
        __syncthreads();

        // mp_w1 [256][256]: k-split 4x64, 4 cols/thread, 2 accumulators
        {
            int c4 = (tid & 63) * 4, kg = tid >> 6;
            float4 accA = make_float4(0.f, 0.f, 0.f, 0.f);
            float4 accB = make_float4(0.f, 0.f, 0.f, 0.f);
            const float* base = mp_w1 + (size_t)(kg * 64) * 256 + c4;
            #pragma unroll 8
            for (int i = 0; i < 64; i += 2) {
                float4 w0 = *(const float4*)(base + i * 256);
                float4 w1 = *(const float4*)(base + (i + 1) * 256);
                float s0 = slh[kg * 64 + i], s1 = slh[kg * 64 + i + 1];
                accA.x += s0 * w0.x; accA.y += s0 * w0.y; accA.z += s0 * w0.z; accA.w += s0 * w0.w;
                accB.x += s1 * w1.x; accB.y += s1 * w1.y; accB.z += s1 * w1.z; accB.w += s1 * w1.w;
            }
            hP4[tid] = make_float4(accA.x + accB.x, accA.y + accB.y,
                                   accA.z + accB.z, accA.w + accB.w);
        }
        __syncthreads();
        if (tid < 64) {
            float4 a = hP4[tid], c1 = hP4[64 + tid], c2 = hP4[128 + tid], c3 = hP4[192 + tid];
            int col = tid * 4;
            sx1[col + 0] = fmaxf(a.x + c1.x + c2.x + c3.x + mp_b1[col + 0], 0.0f);
            sx1[col + 1] = fmaxf(a.y + c1.y + c2.y + c3.y + mp_b1[col + 1], 0.0f);
            sx1[col + 2] = fmaxf(a.z + c1.z + c2.z + c3.z + mp_b1[col + 2], 0.0f);
            sx1[col + 3] = fmaxf(a.w + c1.w + c2.w + c3.w + mp_b1[col + 3], 0.0f);
        }
        __syncthreads();

        // mp_w2 & cf_w1 [256][128]: k-split 8x32, 4 cols/thread
        {
            int c4 = (tid & 31) * 4, kg = tid >> 5;
            float4 aA = make_float4(0.f, 0.f, 0.f, 0.f);
            float4 aB = make_float4(0.f, 0.f, 0.f, 0.f);
            const float* bA = mp_w2 + (size_t)(kg * 32) * 128 + c4;
            const float* bB = cf_w1 + (size_t)(kg * 32) * 128 + c4;
            #pragma unroll 8
            for (int i = 0; i < 32; i++) {
                float4 wA = *(const float4*)(bA + i * 128);
                float4 wB = *(const float4*)(bB + i * 128);
                float sA = sx1[kg * 32 + i];
                float sB = slh[kg * 32 + i];
                aA.x += sA * wA.x; aA.y += sA * wA.y; aA.z += sA * wA.z; aA.w += sA * wA.w;
                aB.x += sB * wB.x; aB.y += sB * wB.y; aB.z += sB * wB.z; aB.w += sB * wB.w;
            }
            hPA[tid] = aA;
            hPB[tid] = aB;
        }
        __syncthreads();
        if (tid < 32) {
            float4 sA = make_float4(0.f, 0.f, 0.f, 0.f);
            float4 sB = make_float4(0.f, 0.f, 0.f, 0.f);
            #pragma unroll
            for (int kg = 0; kg < 8; kg++) {
                float4 a = hPA[kg * 32 + tid];
                sA.x += a.x; sA.y += a.y; sA.z += a.z; sA.w += a.w;
                float4 bv = hPB[kg * 32 + tid];
                sB.x += bv.x; sB.y += bv.y; sB.z += bv.z; sB.w += bv.w;
            }
            int col = tid * 4;
            sx2[col + 0] = fmaxf(sA.x + mp_b2[col + 0], 0.0f);
            sx2[col + 1] = fmaxf(sA.y + mp_b2[col + 1], 0.0f);
            sx2[col + 2] = fmaxf(sA.z + mp_b2[col + 2], 0.0f);
            sx2[col + 3] = fmaxf(sA.w + mp_b2[col + 3], 0.0f);
            sch[col + 0] = fmaxf(sB.x + cf_b1[col + 0], 0.0f);
            sch[col + 1] = fmaxf(sB.y + cf_b1[col + 1], 0.0f);
            sch[col + 2] = fmaxf(sB.z + cf_b1[col + 2], 0.0f);
            sch[col + 3] = fmaxf(sB.w + cf_b1[col + 3], 0.0f);
        }
        __syncthreads();

        if (tid < 20) {
            float a = mp_b3[tid];
            #pragma unroll 8
            for (int k = 0; k < 128; k++) a += sx2[k] * mp_w3[k * 20 + tid];
            sdel[tid] = a;
            out[b * 20 + tid] = a;              // predicted_deltas
        }
        if (tid >= 32 && tid < 37) {
            int hh = tid - 32;
            float a = cf_b2[hh];
            #pragma unroll 8
            for (int k = 0; k < 128; k++) a += sch[k] * cf_w2[k * 5 + hh];
            out[16624 + b * 5 + hh] = sigf(a);  // confidence
        }
        __syncthreads();

        if (tid < 4) {
            int d = tid;
            float run = sBB[15 * 4 + d];        // bbox of t=15
            #pragma unroll
            for (int hh = 0; hh < 5; hh++) {
                run += sdel[hh * 4 + d];
                out[80 + (b * 5 + hh) * 4 + d] = run;                   // predicted_bboxes
                if (d < 2) out[160 + (b * 5 + hh) * 2 + d] = run;       // locations
                else       out[200 + (b * 5 + hh) * 2 + (d - 2)] = run; // scales
            }
        }
    }
    #undef MM64
}

extern "C" void kernel_launch(void* const* d_in, const int* in_sizes, int n_in,
                              void* d_out, int out_size) {
    (void)in_sizes; (void)n_in; (void)out_size;
    const float* pred  = (const float*)d_in[1];
    const float* pe_w1 = (const float*)d_in[2];
    const float* pe_b1 = (const float*)d_in[3];
    const float* pe_w2 = (const float*)d_in[4];
    const float* pe_b2 = (const float*)d_in[5];
    const float* wih0  = (const float*)d_in[6];
    const float* whh0  = (const float*)d_in[7];
    const float* bih0  = (const float*)d_in[8];
    const float* bhh0  = (const float*)d_in[9];
    const float* wih1  = (const float*)d_in[10];
    const float* whh1  = (const float*)d_in[11];
    const float* bih1  = (const float*)d_in[12];
    const float* bhh1  = (const float*)d_in[13];
    const float* mp_w1 = (const float*)d_in[14];
    const float* mp_b1 = (const float*)d_in[15];
    const float* mp_w2 = (const float*)d_in[16];
    const float* mp_b2 = (const float*)d_in[17];
    const float* mp_w3 = (const float*)d_in[18];
    const float* mp_b3 = (const float*)d_in[19];
    const float* cf_w1 = (const float*)d_in[20];
    const float* cf_b1 = (const float*)d_in[21];
    const float* cf_w2 = (const float*)d_in[22];
    const float* cf_b2 = (const float*)d_in[23];
    float* out = (float*)d_out;

    cudaFuncSetAttribute(mp_fused_kernel,
                         cudaFuncAttributeMaxDynamicSharedMemorySize, FUSED_SMEM);
    cudaFuncSetAttribute(mp_fused_kernel,
                         cudaFuncAttributeNonPortableClusterSizeAllowed, 1);

    mp_scan_kernel<<<2048, 256>>>(pred);

    {
        cudaLaunchConfig_t cfg = {};
        cfg.gridDim = dim3(64, 1, 1);
        cfg.blockDim = dim3(256, 1, 1);
        cfg.dynamicSmemBytes = FUSED_SMEM;
        cfg.stream = 0;
        cudaLaunchAttribute attrs[1];
        attrs[0].id = cudaLaunchAttributeClusterDimension;
        attrs[0].val.clusterDim = {16, 1, 1};
        cfg.attrs = attrs;
        cfg.numAttrs = 1;
        cudaLaunchKernelEx(&cfg, mp_fused_kernel,
                           pe_w1, pe_b1, pe_w2, pe_b2,
                           wih0, whh0, bih0, bhh0,
                           wih1, whh1, bih1, bhh1,
                           mp_w1, mp_b1, mp_w2, mp_b2, mp_w3, mp_b3,
                           cf_w1, cf_b1, cf_w2, cf_b2, out);
    }
}

// round 15
// speedup vs baseline: 3.8095x; 1.0263x over previous
#include <cuda_runtime.h>
#include <cuda_bf16.h>
#include <math.h>
#include <stdint.h>

typedef unsigned long long U64;

// ---------------- device scratch (allocations are forbidden) ----------------
__device__ int4 g_part[2048];           // per-(img,slice) mask extents

// ---------------- packed f32x2 helpers ----------------
__device__ __forceinline__ U64 pk2(float a, float b) {
    U64 r; asm("mov.b64 %0, {%1, %2};" : "=l"(r) : "f"(a), "f"(b)); return r;
}
__device__ __forceinline__ float2 upk(U64 v) {
    float2 f; asm("mov.b64 {%0, %1}, %2;" : "=f"(f.x), "=f"(f.y) : "l"(v)); return f;
}
__device__ __forceinline__ U64 dup2(float a) {
    U64 r; asm("mov.b64 %0, {%1, %1};" : "=l"(r) : "f"(a)); return r;
}
__device__ __forceinline__ U64 fma2(U64 x, U64 w, U64 a) {
    U64 d; asm("fma.rn.f32x2 %0, %1, %2, %3;" : "=l"(d) : "l"(x), "l"(w), "l"(a)); return d;
}
__device__ __forceinline__ U64 add2(U64 a, U64 b) {
    U64 d; asm("add.rn.f32x2 %0, %1, %2;" : "=l"(d) : "l"(a), "l"(b)); return d;
}
__device__ __forceinline__ float sigf(float x) { return 1.0f / (1.0f + __expf(-x)); }
__device__ __forceinline__ float tanh_fast(float x) {
    float e = __expf(2.0f * x);
    return 1.0f - 2.0f / (e + 1.0f);
}

// ---- cluster / DSMEM primitives (proven rounds 9/12/13/14) ----
__device__ __forceinline__ unsigned smem_u32(const void* p) {
    unsigned r;
    asm("{ .reg .u64 t; cvta.to.shared.u64 t, %1; cvt.u32.u64 %0, t; }" : "=r"(r) : "l"(p));
    return r;
}
__device__ __forceinline__ void st_cluster_u64(unsigned laddr, unsigned rank, U64 v) {
    asm volatile("{ .reg .b32 ra; mapa.shared::cluster.u32 ra, %0, %1; st.shared::cluster.u64 [ra], %2; }"
                 :: "r"(laddr), "r"(rank), "l"(v) : "memory");
}
__device__ __forceinline__ void st_cluster_f32(unsigned laddr, unsigned rank, float v) {
    asm volatile("{ .reg .b32 ra; mapa.shared::cluster.u32 ra, %0, %1; st.shared::cluster.f32 [ra], %2; }"
                 :: "r"(laddr), "r"(rank), "f"(v) : "memory");
}
__device__ __forceinline__ unsigned ctarank() {
    unsigned r; asm("mov.u32 %0, %%cluster_ctarank;" : "=r"(r)); return r;
}
#define CLUSTER_SYNC() do { \
    asm volatile("barrier.cluster.arrive.aligned;" ::: "memory"); \
    asm volatile("barrier.cluster.wait.aligned;"   ::: "memory"); } while (0)

// ---------------- 256 MB mask scan (DRAM-bound, MLP=8, no atomics) ----------
__global__ void __launch_bounds__(256) mp_scan_kernel(const float* __restrict__ pred) {
    int img   = blockIdx.x >> 5;
    int slice = blockIdx.x & 31;
    const float4* p4 = (const float4*)(pred + (size_t)img * (1024u * 1024u)
                                            + (size_t)slice * (32u * 1024u));
    int tid = threadIdx.x;

    int lxmin = 0x7fffffff, lxmax = -1, lymin = 0x7fffffff, lymax = -1;
    for (int rr = 0; rr < 4; rr++) {
        float4 v[8];
        #pragma unroll
        for (int u = 0; u < 8; u++)
            v[u] = __ldcs(p4 + (rr * 8 + u) * 256 + tid);
        #pragma unroll
        for (int u = 0; u < 8; u++) {
            bool m0 = v[u].x > 0.5f, m1 = v[u].y > 0.5f, m2 = v[u].z > 0.5f, m3 = v[u].w > 0.5f;
            if (m0 | m1 | m2 | m3) {
                int x0 = tid * 4;
                int f = m0 ? 0 : (m1 ? 1 : (m2 ? 2 : 3));
                int l = m3 ? 3 : (m2 ? 2 : (m1 ? 1 : 0));
                lxmin = min(lxmin, x0 + f);
                lxmax = max(lxmax, x0 + l);
                int y = slice * 32 + rr * 8 + u;
                lymin = min(lymin, y);
                lymax = max(lymax, y);
            }
        }
    }
    #pragma unroll
    for (int off = 16; off; off >>= 1) {
        lxmin = min(lxmin, __shfl_xor_sync(0xffffffffu, lxmin, off));
        lxmax = max(lxmax, __shfl_xor_sync(0xffffffffu, lxmax, off));
        lymin = min(lymin, __shfl_xor_sync(0xffffffffu, lymin, off));
        lymax = max(lymax, __shfl_xor_sync(0xffffffffu, lymax, off));
    }
    __shared__ int sx0, sx1, sy0, sy1;
    if (tid == 0) { sx0 = 0x7fffffff; sx1 = -1; sy0 = 0x7fffffff; sy1 = -1; }
    __syncthreads();
    if ((tid & 31) == 0) {
        atomicMin(&sx0, lxmin); atomicMax(&sx1, lxmax);
        atomicMin(&sy0, lymin); atomicMax(&sy1, lymax);
    }
    __syncthreads();
    if (tid == 0) g_part[blockIdx.x] = make_int4(sx0, sx1, sy0, sy1);
}

// ---------------- fused: prologue + 17-slot pipelined 2-layer LSTM + heads --
// grid 64 = 4 clusters x 16 CTAs. Cluster c owns batch c; rank r owns hidden
// units [r*16, r*16+16) of BOTH layers. Slot s (0..16): layer0 step s (warps
// 0-3, whh0 regs; x0 partials all precomputed) and layer1 step s-1 (warps
// 4-7: whh1 regs + wih1 streamed from packed SMEM; x1 input = h0 mailbox).
// Per slot: matmuls, bar, gate-sums (128 thr), bar, 32 updaters push via
// DSMEM, CLUSTER_SYNC. 17 syncs total instead of 33.
#define FUSED_SMEM 127232

__global__ void __launch_bounds__(256, 1) mp_fused_kernel(
    const float* __restrict__ pe_w1, const float* __restrict__ pe_b1,
    const float* __restrict__ pe_w2, const float* __restrict__ pe_b2,
    const float* __restrict__ wih0, const float* __restrict__ whh0,
    const float* __restrict__ bih0, const float* __restrict__ bhh0,
    const float* __restrict__ wih1, const float* __restrict__ whh1,
    const float* __restrict__ bih1, const float* __restrict__ bhh1,
    const float* __restrict__ mp_w1, const float* __restrict__ mp_b1,
    const float* __restrict__ mp_w2, const float* __restrict__ mp_b2,
    const float* __restrict__ mp_w3, const float* __restrict__ mp_b3,
    const float* __restrict__ cf_w1, const float* __restrict__ cf_b1,
    const float* __restrict__ cf_w2, const float* __restrict__ cf_b2,
    float* __restrict__ out)
{
    extern __shared__ char smem_raw[];
    U64*   sW1   = (U64*)smem_raw;        // [256 k][32 cg] packed wih1 pairs (64 KB)
    U64*   sX0   = sW1 + 8192;            // [16 t][256 k] dup x (32 KB, prologue)
    U64*   sPX0  = sX0 + 4096;            // [16 t][128] x0 partials (16 KB)
    U64*   sH0d  = sPX0 + 2048;           // [2 parity][256] h0 mailboxes (4 KB)
    U64*   sH1d  = sH0d + 512;            // [2 parity][256] h1 mailboxes (4 KB)
    U64*   sPH0  = sH1d + 512;            // [128] layer0 h partials
    U64*   sPH1  = sPH0 + 128;            // [128] layer1 h partials
    U64*   sPX1  = sPH1 + 128;            // [128] layer1 x partials
    float* sBias = (float*)(sPX1 + 128);  // [128] both layers
    float* sBB   = sBias + 128;           // [16 ranks][4] bboxes
    float* sGate = sBB + 64;              // [128] gate preactivations

    int tid = threadIdx.x;
    int b   = blockIdx.x >> 4;            // batch = cluster id
    unsigned rank = ctarank();
    int kc4 = (tid >> 5) & 3, cg = tid & 31;
    int krbase = kc4 * 64;
    bool isB = (tid >= 128);              // layer1 warps
    int img = b * 16 + (int)rank;

    int ci0  = 2 * cg;
    int col0 = ((ci0 >> 4) << 8) + (int)rank * 16 + (ci0 & 15);

    #define MM64(S0, OUT) do { \
        U64 a0 = 0ull, a1 = 0ull, a2 = 0ull, a3 = 0ull; \
        _Pragma("unroll") \
        for (int i = 0; i < 64; i += 8) { \
            ulonglong2 va = *(const ulonglong2*)((S0) + i); \
            ulonglong2 vb = *(const ulonglong2*)((S0) + i + 2); \
            ulonglong2 vc = *(const ulonglong2*)((S0) + i + 4); \
            ulonglong2 vd = *(const ulonglong2*)((S0) + i + 6); \
            a0 = fma2(va.x, wAB[i],     a0); a0 = fma2(va.y, wAB[i + 1], a0); \
            a1 = fma2(vb.x, wAB[i + 2], a1); a1 = fma2(vb.y, wAB[i + 3], a1); \
            a2 = fma2(vc.x, wAB[i + 4], a2); a2 = fma2(vc.y, wAB[i + 5], a2); \
            a3 = fma2(vd.x, wAB[i + 6], a3); a3 = fma2(vd.y, wAB[i + 7], a3); \
        } \
        (OUT) = add2(add2(a0, a1), add2(a2, a3)); \
    } while (0)

    // ======== prologue: bbox + pos MLP + x all-gather ========
    if (tid < 32) {
        int4 v = g_part[img * 32 + tid];
        int xm = v.x, xM = v.y, ym = v.z, yM = v.w;
        #pragma unroll
        for (int off = 16; off; off >>= 1) {
            xm = min(xm, __shfl_xor_sync(0xffffffffu, xm, off));
            xM = max(xM, __shfl_xor_sync(0xffffffffu, xM, off));
            ym = min(ym, __shfl_xor_sync(0xffffffffu, ym, off));
            yM = max(yM, __shfl_xor_sync(0xffffffffu, yM, off));
        }
        if (tid == 0) {
            float b0, b1, b2, b3;
            if (xM < 0) { b0 = 0.5f; b1 = 0.5f; b2 = 0.1f; b3 = 0.1f; }
            else {
                b0 = (float)(xm + xM) / 2.0f / 1024.0f;
                b1 = (float)(ym + yM) / 2.0f / 1024.0f;
                b2 = (float)(xM - xm) / 1024.0f;
                b3 = (float)(yM - ym) / 1024.0f;
            }
            sBB[rank * 4 + 0] = b0; sBB[rank * 4 + 1] = b1;
            sBB[rank * 4 + 2] = b2; sBB[rank * 4 + 3] = b3;
            out[16644 + img * 4 + 0] = b0; out[16644 + img * 4 + 1] = b1;
            out[16644 + img * 4 + 2] = b2; out[16644 + img * 4 + 3] = b3;
        }
    }
    __syncthreads();
    if (tid < 4) {
        float v = sBB[rank * 4 + tid];
        unsigned loc = smem_u32(&sBB[rank * 4 + tid]);
        #pragma unroll
        for (int r = 0; r < 16; r++) st_cluster_f32(loc, r, v);
    }
    // pos MLP (scratch aliases sPX0 — dead until x0 precompute)
    float*  sp1 = (float*)sPX0;             // [256]
    float4* pP4 = (float4*)(sp1 + 256);     // [256]
    float*  sp2 = (float*)(pP4 + 256);      // [256]
    {
        float a = pe_b1[tid];
        #pragma unroll
        for (int k = 0; k < 4; k++) a += sBB[rank * 4 + k] * pe_w1[k * 256 + tid];
        sp1[tid] = fmaxf(a, 0.0f);
    }
    __syncthreads();
    {
        int c4 = (tid & 63) * 4, kg = tid >> 6;
        float4 accA = make_float4(0.f, 0.f, 0.f, 0.f);
        float4 accB = make_float4(0.f, 0.f, 0.f, 0.f);
        const float* base = pe_w2 + (size_t)(kg * 64) * 256 + c4;
        #pragma unroll 8
        for (int i = 0; i < 64; i += 2) {
            float4 w0 = *(const float4*)(base + i * 256);
            float4 w1 = *(const float4*)(base + (i + 1) * 256);
            float s0 = sp1[kg * 64 + i], s1 = sp1[kg * 64 + i + 1];
            accA.x += s0 * w0.x; accA.y += s0 * w0.y; accA.z += s0 * w0.z; accA.w += s0 * w0.w;
            accB.x += s1 * w1.x; accB.y += s1 * w1.y; accB.z += s1 * w1.z; accB.w += s1 * w1.w;
        }
        pP4[tid] = make_float4(accA.x + accB.x, accA.y + accB.y,
                               accA.z + accB.z, accA.w + accB.w);
    }
    __syncthreads();
    if (tid < 64) {
        float4 a = pP4[tid], c1 = pP4[64 + tid], c2 = pP4[128 + tid], c3 = pP4[192 + tid];
        int col = tid * 4;
        sp2[col + 0] = fmaxf(a.x + c1.x + c2.x + c3.x + pe_b2[col + 0], 0.0f);
        sp2[col + 1] = fmaxf(a.y + c1.y + c2.y + c3.y + pe_b2[col + 1], 0.0f);
        sp2[col + 2] = fmaxf(a.z + c1.z + c2.z + c3.z + pe_b2[col + 2], 0.0f);
        sp2[col + 3] = fmaxf(a.w + c1.w + c2.w + c3.w + pe_b2[col + 3], 0.0f);
    }
    __syncthreads();
    {
        U64 xd = dup2(sp2[tid]);
        unsigned loc = smem_u32(&sX0[(int)rank * 256 + tid]);
        #pragma unroll
        for (int r = 0; r < 16; r++) st_cluster_u64(loc, r, xd);
    }
    // mailbox init: sH0d parity 0 (h0_{-1}=0), sH1d parity 1 (h1_{-1}=0)
    if (tid < 256) {
        sH0d[tid]       = 0ull;
        sH1d[256 + tid] = 0ull;
    }
    // biases (both layers)
    if (tid < 128) {
        int ci = tid & 63;
        int col = ((ci >> 4) << 8) + (int)rank * 16 + (ci & 15);
        sBias[tid] = (tid < 64) ? (bih0[col] + bhh0[col])
                                : (bih1[col] + bhh1[col]);
    }
    __syncthreads();
    CLUSTER_SYNC();   // sX0 + sBB gathered everywhere

    // ======== weight setup ========
    U64 wAB[64];
    if (!isB) {
        // A-group: wih0 regs -> precompute all 16 x0 partial slots, then whh0
        #pragma unroll
        for (int i = 0; i < 64; i++) {
            float2 w2 = *(const float2*)(wih0 + (size_t)(krbase + i) * 1024 + col0);
            wAB[i] = pk2(w2.x, w2.y);
        }
        for (int t = 0; t < 16; t++) {
            const U64* s0 = sX0 + t * 256 + krbase;
            MM64(s0, sPX0[t * 128 + tid]);
        }
        #pragma unroll
        for (int i = 0; i < 64; i++) {
            float2 w2 = *(const float2*)(whh0 + (size_t)(krbase + i) * 1024 + col0);
            wAB[i] = pk2(w2.x, w2.y);
        }
    } else {
        // B-group: pack wih1 -> sW1 (col-pair layout), then whh1 regs
        int z = tid - 128;
        int cgz = z & 31, kb = (z >> 5) * 64;
        int czi = 2 * cgz;
        int czcol = ((czi >> 4) << 8) + (int)rank * 16 + (czi & 15);
        for (int i = 0; i < 64; i++) {
            float2 w2 = *(const float2*)(wih1 + (size_t)(kb + i) * 1024 + czcol);
            sW1[(kb + i) * 32 + cgz] = pk2(w2.x, w2.y);
        }
        #pragma unroll
        for (int i = 0; i < 64; i++) {
            float2 w2 = *(const float2*)(whh1 + (size_t)(krbase + i) * 1024 + col0);
            wAB[i] = pk2(w2.x, w2.y);
        }
    }
    __syncthreads();

    // ======== 17-slot pipelined loop ========
    float creg = 0.0f;   // tid<16: layer0 cell; tid 16-31: layer1 cell

    for (int s = 0; s < 17; s++) {
        int p = s & 1;
        const U64* hb0 = sH0d + p * 256;   // h0_{s-1}
        const U64* hb1 = sH1d + p * 256;   // h1_{s-2}

        if (!isB) {
            if (s < 16) {
                const U64* s0 = hb0 + krbase;
                MM64(s0, sPH0[tid]);
            }
        } else if (s > 0) {
            int z = tid - 128;
            // h1-matmul (register weights)
            {
                const U64* s0 = hb1 + krbase;
                MM64(s0, sPH1[z]);
            }
            // x1-matmul: input h0_{s-1}, weights streamed from sW1
            {
                const U64* s0 = hb0 + krbase;
                const U64* wp = sW1 + krbase * 32 + cg;
                U64 b0 = 0ull, b1 = 0ull, b2 = 0ull, b3 = 0ull;
                #pragma unroll
                for (int i = 0; i < 64; i += 4) {
                    ulonglong2 va = *(const ulonglong2*)(s0 + i);
                    ulonglong2 vb = *(const ulonglong2*)(s0 + i + 2);
                    b0 = fma2(va.x, wp[(i)     * 32], b0);
                    b1 = fma2(va.y, wp[(i + 1) * 32], b1);
                    b2 = fma2(vb.x, wp[(i + 2) * 32], b2);
                    b3 = fma2(vb.y, wp[(i + 3) * 32], b3);
                }
                sPX1[z] = add2(add2(b0, b1), add2(b2, b3));
            }
        }
        __syncthreads();

        // ---- gate-sums: tid<64 layer0, tid 64-127 layer1 ----
        if (tid < 64) {
            if (s < 16) {
                int ci = tid, cgi = ci >> 1, half = ci & 1;
                const float* px = (const float*)(sPX0 + s * 128);
                const float* ph = (const float*)sPH0;
                float sa = sBias[ci], sb = 0.0f;
                #pragma unroll
                for (int kk = 0; kk < 4; kk++) {
                    sa += px[(kk * 32 + cgi) * 2 + half];
                    sb += ph[(kk * 32 + cgi) * 2 + half];
                }
                sGate[ci] = sa + sb;
            }
        } else if (tid < 128) {
            if (s > 0) {
                int ci = tid - 64, cgi = ci >> 1, half = ci & 1;
                const float* px = (const float*)sPX1;
                const float* ph = (const float*)sPH1;
                float sa = sBias[64 + ci], sb = 0.0f;
                #pragma unroll
                for (int kk = 0; kk < 4; kk++) {
                    sa += px[(kk * 32 + cgi) * 2 + half];
                    sb += ph[(kk * 32 + cgi) * 2 + half];
                }
                sGate[64 + ci] = sa + sb;
            }
        }
        __syncthreads();

        // ---- updates + DSMEM pushes ----
        if (tid < 16) {
            if (s < 16) {
                int u = tid;
                float iv = sigf(sGate[u]);
                float fv = sigf(sGate[16 + u]);
                float gv = tanh_fast(sGate[32 + u]);
                float ov = sigf(sGate[48 + u]);
                creg = fv * creg + iv * gv;
                float hv = ov * tanh_fast(creg);
                int j = (int)rank * 16 + u;
                U64 hd = dup2(hv);
                unsigned loc = smem_u32(&sH0d[((s + 1) & 1) * 256 + j]);
                #pragma unroll
                for (int r = 0; r < 16; r++) st_cluster_u64(loc, r, hd);
            }
        } else if (tid < 32) {
            if (s > 0) {
                int u = tid - 16, t1 = s - 1;
                float iv = sigf(sGate[64 + u]);
                float fv = sigf(sGate[80 + u]);
                float gv = tanh_fast(sGate[96 + u]);
                float ov = sigf(sGate[112 + u]);
                creg = fv * creg + iv * gv;
                float hv = ov * tanh_fast(creg);
                int j = (int)rank * 16 + u;
                U64 hd = dup2(hv);
                unsigned loc = smem_u32(&sH1d[((s + 1) & 1) * 256 + j]);
                #pragma unroll
                for (int r = 0; r < 16; r++) st_cluster_u64(loc, r, hd);
                out[240 + (b * 16 + t1) * 256 + j] = hv;
            }
        }
        CLUSTER_SYNC();
    }

    // ======== epilogue: heads on rank 0 (h1_15 in sH1d parity 1) ========
    if (rank == 0) {
        float*  slh  = (float*)sW1;             // scratch aliases sW1 (dead)
        float4* hP4  = (float4*)(slh + 256);
        float*  sx1  = (float*)(hP4 + 256);
        float*  sx2  = sx1 + 256;
        float*  sch  = sx2 + 128;
        float*  sdel = sch + 128;
        float4* hPA  = (float4*)(sdel + 32);
        float4* hPB  = hPA + 256;

        slh[tid] = upk(sH1d[256 + tid]).x;
        __syncthreads();

        {
            int c4 = (tid & 63) * 4, kg = tid >> 6;
            float4 accA = make_float4(0.f, 0.f, 0.f, 0.f);
            float4 accB = make_float4(0.f, 0.f, 0.f, 0.f);
            const float* base = mp_w1 + (size_t)(kg * 64) * 256 + c4;
            #pragma unroll 8
            for (int i = 0; i < 64; i += 2) {
                float4 w0 = *(const float4*)(base + i * 256);
                float4 w1 = *(const float4*)(base + (i + 1) * 256);
                float s0 = slh[kg * 64 + i], s1 = slh[kg * 64 + i + 1];
                accA.x += s0 * w0.x; accA.y += s0 * w0.y; accA.z += s0 * w0.z; accA.w += s0 * w0.w;
                accB.x += s1 * w1.x; accB.y += s1 * w1.y; accB.z += s1 * w1.z; accB.w += s1 * w1.w;
            }
            hP4[tid] = make_float4(accA.x + accB.x, accA.y + accB.y,
                                   accA.z + accB.z, accA.w + accB.w);
        }
        __syncthreads();
        if (tid < 64) {
            float4 a = hP4[tid], c1 = hP4[64 + tid], c2 = hP4[128 + tid], c3 = hP4[192 + tid];
            int col = tid * 4;
            sx1[col + 0] = fmaxf(a.x + c1.x + c2.x + c3.x + mp_b1[col + 0], 0.0f);
            sx1[col + 1] = fmaxf(a.y + c1.y + c2.y + c3.y + mp_b1[col + 1], 0.0f);
            sx1[col + 2] = fmaxf(a.z + c1.z + c2.z + c3.z + mp_b1[col + 2], 0.0f);
            sx1[col + 3] = fmaxf(a.w + c1.w + c2.w + c3.w + mp_b1[col + 3], 0.0f);
        }
        __syncthreads();

        {
            int c4 = (tid & 31) * 4, kg = tid >> 5;
            float4 aA = make_float4(0.f, 0.f, 0.f, 0.f);
            float4 aB = make_float4(0.f, 0.f, 0.f, 0.f);
            const float* bA = mp_w2 + (size_t)(kg * 32) * 128 + c4;
            const float* bB = cf_w1 + (size_t)(kg * 32) * 128 + c4;
            #pragma unroll 8
            for (int i = 0; i < 32; i++) {
                float4 wA = *(const float4*)(bA + i * 128);
                float4 wB = *(const float4*)(bB + i * 128);
                float sA = sx1[kg * 32 + i];
                float sB = slh[kg * 32 + i];
                aA.x += sA * wA.x; aA.y += sA * wA.y; aA.z += sA * wA.z; aA.w += sA * wA.w;
                aB.x += sB * wB.x; aB.y += sB * wB.y; aB.z += sB * wB.z; aB.w += sB * wB.w;
            }
            hPA[tid] = aA;
            hPB[tid] = aB;
        }
        __syncthreads();
        if (tid < 32) {
            float4 sA = make_float4(0.f, 0.f, 0.f, 0.f);
            float4 sB = make_float4(0.f, 0.f, 0.f, 0.f);
            #pragma unroll
            for (int kg = 0; kg < 8; kg++) {
                float4 a = hPA[kg * 32 + tid];
                sA.x += a.x; sA.y += a.y; sA.z += a.z; sA.w += a.w;
                float4 bv = hPB[kg * 32 + tid];
                sB.x += bv.x; sB.y += bv.y; sB.z += bv.z; sB.w += bv.w;
            }
            int col = tid * 4;
            sx2[col + 0] = fmaxf(sA.x + mp_b2[col + 0], 0.0f);
            sx2[col + 1] = fmaxf(sA.y + mp_b2[col + 1], 0.0f);
            sx2[col + 2] = fmaxf(sA.z + mp_b2[col + 2], 0.0f);
            sx2[col + 3] = fmaxf(sA.w + mp_b2[col + 3], 0.0f);
            sch[col + 0] = fmaxf(sB.x + cf_b1[col + 0], 0.0f);
            sch[col + 1] = fmaxf(sB.y + cf_b1[col + 1], 0.0f);
            sch[col + 2] = fmaxf(sB.z + cf_b1[col + 2], 0.0f);
            sch[col + 3] = fmaxf(sB.w + cf_b1[col + 3], 0.0f);
        }
        __syncthreads();

        if (tid < 20) {
            float a = mp_b3[tid];
            #pragma unroll 8
            for (int k = 0; k < 128; k++) a += sx2[k] * mp_w3[k * 20 + tid];
            sdel[tid] = a;
            out[b * 20 + tid] = a;              // predicted_deltas
        }
        if (tid >= 32 && tid < 37) {
            int hh = tid - 32;
            float a = cf_b2[hh];
            #pragma unroll 8
            for (int k = 0; k < 128; k++) a += sch[k] * cf_w2[k * 5 + hh];
            out[16624 + b * 5 + hh] = sigf(a);  // confidence
        }
        __syncthreads();

        if (tid < 4) {
            int d = tid;
            float run = sBB[15 * 4 + d];        // bbox of t=15
            #pragma unroll
            for (int hh = 0; hh < 5; hh++) {
                run += sdel[hh * 4 + d];
                out[80 + (b * 5 + hh) * 4 + d] = run;                   // predicted_bboxes
                if (d < 2) out[160 + (b * 5 + hh) * 2 + d] = run;       // locations
                else       out[200 + (b * 5 + hh) * 2 + (d - 2)] = run; // scales
            }
        }
    }
    #undef MM64
}

extern "C" void kernel_launch(void* const* d_in, const int* in_sizes, int n_in,
                              void* d_out, int out_size) {
    (void)in_sizes; (void)n_in; (void)out_size;
    const float* pred  = (const float*)d_in[1];
    const float* pe_w1 = (const float*)d_in[2];
    const float* pe_b1 = (const float*)d_in[3];
    const float* pe_w2 = (const float*)d_in[4];
    const float* pe_b2 = (const float*)d_in[5];
    const float* wih0  = (const float*)d_in[6];
    const float* whh0  = (const float*)d_in[7];
    const float* bih0  = (const float*)d_in[8];
    const float* bhh0  = (const float*)d_in[9];
    const float* wih1  = (const float*)d_in[10];
    const float* whh1  = (const float*)d_in[11];
    const float* bih1  = (const float*)d_in[12];
    const float* bhh1  = (const float*)d_in[13];
    const float* mp_w1 = (const float*)d_in[14];
    const float* mp_b1 = (const float*)d_in[15];
    const float* mp_w2 = (const float*)d_in[16];
    const float* mp_b2 = (const float*)d_in[17];
    const float* mp_w3 = (const float*)d_in[18];
    const float* mp_b3 = (const float*)d_in[19];
    const float* cf_w1 = (const float*)d_in[20];
    const float* cf_b1 = (const float*)d_in[21];
    const float* cf_w2 = (const float*)d_in[22];
    const float* cf_b2 = (const float*)d_in[23];
    float* out = (float*)d_out;

    cudaFuncSetAttribute(mp_fused_kernel,
                         cudaFuncAttributeMaxDynamicSharedMemorySize, FUSED_SMEM);
    cudaFuncSetAttribute(mp_fused_kernel,
                         cudaFuncAttributeNonPortableClusterSizeAllowed, 1);

    mp_scan_kernel<<<2048, 256>>>(pred);

    {
        cudaLaunchConfig_t cfg = {};
        cfg.gridDim = dim3(64, 1, 1);
        cfg.blockDim = dim3(256, 1, 1);
        cfg.dynamicSmemBytes = FUSED_SMEM;
        cfg.stream = 0;
        cudaLaunchAttribute attrs[1];
        attrs[0].id = cudaLaunchAttributeClusterDimension;
        attrs[0].val.clusterDim = {16, 1, 1};
        cfg.attrs = attrs;
        cfg.numAttrs = 1;
        cudaLaunchKernelEx(&cfg, mp_fused_kernel,
                           pe_w1, pe_b1, pe_w2, pe_b2,
                           wih0, whh0, bih0, bhh0,
                           wih1, whh1, bih1, bhh1,
                           mp_w1, mp_b1, mp_w2, mp_b2, mp_w3, mp_b3,
                           cf_w1, cf_b1, cf_w2, cf_b2, out);
    }
}

// round 16
// speedup vs baseline: 3.9568x; 1.0387x over previous
#include <cuda_runtime.h>
#include <cuda_bf16.h>
#include <math.h>
#include <stdint.h>

typedef unsigned long long U64;

// ---------------- device scratch (allocations are forbidden) ----------------
__device__ int4 g_part[2048];           // per-(img,slice) mask extents

// ---------------- packed f32x2 helpers ----------------
__device__ __forceinline__ U64 pk2(float a, float b) {
    U64 r; asm("mov.b64 %0, {%1, %2};" : "=l"(r) : "f"(a), "f"(b)); return r;
}
__device__ __forceinline__ float2 upk(U64 v) {
    float2 f; asm("mov.b64 {%0, %1}, %2;" : "=f"(f.x), "=f"(f.y) : "l"(v)); return f;
}
__device__ __forceinline__ U64 dup2(float a) {
    U64 r; asm("mov.b64 %0, {%1, %1};" : "=l"(r) : "f"(a)); return r;
}
__device__ __forceinline__ U64 fma2(U64 x, U64 w, U64 a) {
    U64 d; asm("fma.rn.f32x2 %0, %1, %2, %3;" : "=l"(d) : "l"(x), "l"(w), "l"(a)); return d;
}
__device__ __forceinline__ U64 add2(U64 a, U64 b) {
    U64 d; asm("add.rn.f32x2 %0, %1, %2;" : "=l"(d) : "l"(a), "l"(b)); return d;
}
__device__ __forceinline__ float sigf(float x) { return 1.0f / (1.0f + __expf(-x)); }
__device__ __forceinline__ float tanh_fast(float x) {
    float e = __expf(2.0f * x);
    return 1.0f - 2.0f / (e + 1.0f);
}

// ---- cluster / DSMEM primitives (proven rounds 9/12/13/14/15) ----
__device__ __forceinline__ unsigned smem_u32(const void* p) {
    unsigned r;
    asm("{ .reg .u64 t; cvta.to.shared.u64 t, %1; cvt.u32.u64 %0, t; }" : "=r"(r) : "l"(p));
    return r;
}
__device__ __forceinline__ void st_cluster_u64(unsigned laddr, unsigned rank, U64 v) {
    asm volatile("{ .reg .b32 ra; mapa.shared::cluster.u32 ra, %0, %1; st.shared::cluster.u64 [ra], %2; }"
                 :: "r"(laddr), "r"(rank), "l"(v) : "memory");
}
__device__ __forceinline__ void st_cluster_f32(unsigned laddr, unsigned rank, float v) {
    asm volatile("{ .reg .b32 ra; mapa.shared::cluster.u32 ra, %0, %1; st.shared::cluster.f32 [ra], %2; }"
                 :: "r"(laddr), "r"(rank), "f"(v) : "memory");
}
__device__ __forceinline__ unsigned ctarank() {
    unsigned r; asm("mov.u32 %0, %%cluster_ctarank;" : "=r"(r)); return r;
}
#define CLUSTER_SYNC() do { \
    asm volatile("barrier.cluster.arrive.aligned;" ::: "memory"); \
    asm volatile("barrier.cluster.wait.aligned;"   ::: "memory"); } while (0)

// ---------------- 256 MB mask scan (DRAM-bound, MLP=8, no atomics) ----------
__global__ void __launch_bounds__(256) mp_scan_kernel(const float* __restrict__ pred) {
    // allow the dependent fused kernel to launch & run its scan-independent
    // prologue concurrently (PDL)
    cudaTriggerProgrammaticLaunchCompletion();

    int img   = blockIdx.x >> 5;
    int slice = blockIdx.x & 31;
    const float4* p4 = (const float4*)(pred + (size_t)img * (1024u * 1024u)
                                            + (size_t)slice * (32u * 1024u));
    int tid = threadIdx.x;

    int lxmin = 0x7fffffff, lxmax = -1, lymin = 0x7fffffff, lymax = -1;
    for (int rr = 0; rr < 4; rr++) {
        float4 v[8];
        #pragma unroll
        for (int u = 0; u < 8; u++)
            v[u] = __ldcs(p4 + (rr * 8 + u) * 256 + tid);
        #pragma unroll
        for (int u = 0; u < 8; u++) {
            bool m0 = v[u].x > 0.5f, m1 = v[u].y > 0.5f, m2 = v[u].z > 0.5f, m3 = v[u].w > 0.5f;
            if (m0 | m1 | m2 | m3) {
                int x0 = tid * 4;
                int f = m0 ? 0 : (m1 ? 1 : (m2 ? 2 : 3));
                int l = m3 ? 3 : (m2 ? 2 : (m1 ? 1 : 0));
                lxmin = min(lxmin, x0 + f);
                lxmax = max(lxmax, x0 + l);
                int y = slice * 32 + rr * 8 + u;
                lymin = min(lymin, y);
                lymax = max(lymax, y);
            }
        }
    }
    #pragma unroll
    for (int off = 16; off; off >>= 1) {
        lxmin = min(lxmin, __shfl_xor_sync(0xffffffffu, lxmin, off));
        lxmax = max(lxmax, __shfl_xor_sync(0xffffffffu, lxmax, off));
        lymin = min(lymin, __shfl_xor_sync(0xffffffffu, lymin, off));
        lymax = max(lymax, __shfl_xor_sync(0xffffffffu, lymax, off));
    }
    __shared__ int sx0, sx1, sy0, sy1;
    if (tid == 0) { sx0 = 0x7fffffff; sx1 = -1; sy0 = 0x7fffffff; sy1 = -1; }
    __syncthreads();
    if ((tid & 31) == 0) {
        atomicMin(&sx0, lxmin); atomicMax(&sx1, lxmax);
        atomicMin(&sy0, lymin); atomicMax(&sy1, lymax);
    }
    __syncthreads();
    if (tid == 0) g_part[blockIdx.x] = make_int4(sx0, sx1, sy0, sy1);
}

// ---------------- fused: PDL prologue + 17-slot pipelined LSTM + heads -----
// grid 64 = 4 clusters x 16 CTAs (same as round 15). Scan-independent weight
// staging runs BEFORE cudaGridDependencySynchronize(); everything after it is
// byte-identical to round 15.
#define FUSED_SMEM 127232

__global__ void __launch_bounds__(256, 1) mp_fused_kernel(
    const float* __restrict__ pe_w1, const float* __restrict__ pe_b1,
    const float* __restrict__ pe_w2, const float* __restrict__ pe_b2,
    const float* __restrict__ wih0, const float* __restrict__ whh0,
    const float* __restrict__ bih0, const float* __restrict__ bhh0,
    const float* __restrict__ wih1, const float* __restrict__ whh1,
    const float* __restrict__ bih1, const float* __restrict__ bhh1,
    const float* __restrict__ mp_w1, const float* __restrict__ mp_b1,
    const float* __restrict__ mp_w2, const float* __restrict__ mp_b2,
    const float* __restrict__ mp_w3, const float* __restrict__ mp_b3,
    const float* __restrict__ cf_w1, const float* __restrict__ cf_b1,
    const float* __restrict__ cf_w2, const float* __restrict__ cf_b2,
    float* __restrict__ out)
{
    extern __shared__ char smem_raw[];
    U64*   sW1   = (U64*)smem_raw;        // [256 k][32 cg] packed wih1 pairs (64 KB)
    U64*   sX0   = sW1 + 8192;            // [16 t][256 k] dup x (32 KB)
    U64*   sPX0  = sX0 + 4096;            // [16 t][128] x0 partials (16 KB)
    U64*   sH0d  = sPX0 + 2048;           // [2 parity][256] h0 mailboxes (4 KB)
    U64*   sH1d  = sH0d + 512;            // [2 parity][256] h1 mailboxes (4 KB)
    U64*   sPH0  = sH1d + 512;            // [128] layer0 h partials
    U64*   sPH1  = sPH0 + 128;            // [128] layer1 h partials
    U64*   sPX1  = sPH1 + 128;            // [128] layer1 x partials
    float* sBias = (float*)(sPX1 + 128);  // [128] both layers
    float* sBB   = sBias + 128;           // [16 ranks][4] bboxes
    float* sGate = sBB + 64;              // [128] gate preactivations

    int tid = threadIdx.x;
    int b   = blockIdx.x >> 4;            // batch = cluster id
    unsigned rank = ctarank();
    int kc4 = (tid >> 5) & 3, cg = tid & 31;
    int krbase = kc4 * 64;
    bool isB = (tid >= 128);              // layer1 warps
    int img = b * 16 + (int)rank;

    int ci0  = 2 * cg;
    int col0 = ((ci0 >> 4) << 8) + (int)rank * 16 + (ci0 & 15);

    #define MM64(S0, OUT) do { \
        U64 a0 = 0ull, a1 = 0ull, a2 = 0ull, a3 = 0ull; \
        _Pragma("unroll") \
        for (int i = 0; i < 64; i += 8) { \
            ulonglong2 va = *(const ulonglong2*)((S0) + i); \
            ulonglong2 vb = *(const ulonglong2*)((S0) + i + 2); \
            ulonglong2 vc = *(const ulonglong2*)((S0) + i + 4); \
            ulonglong2 vd = *(const ulonglong2*)((S0) + i + 6); \
            a0 = fma2(va.x, wAB[i],     a0); a0 = fma2(va.y, wAB[i + 1], a0); \
            a1 = fma2(vb.x, wAB[i + 2], a1); a1 = fma2(vb.y, wAB[i + 3], a1); \
            a2 = fma2(vc.x, wAB[i + 4], a2); a2 = fma2(vc.y, wAB[i + 5], a2); \
            a3 = fma2(vd.x, wAB[i + 6], a3); a3 = fma2(vd.y, wAB[i + 7], a3); \
        } \
        (OUT) = add2(add2(a0, a1), add2(a2, a3)); \
    } while (0)

    // ======== PDL phase: everything scan-INDEPENDENT ========
    // weight staging: A-warps get wih0 in regs now (whh0 comes after the x0
    // precompute); B-warps pack wih1 -> sW1 and hold whh1 in regs.
    U64 wAB[64];
    if (!isB) {
        #pragma unroll
        for (int i = 0; i < 64; i++) {
            float2 w2 = *(const float2*)(wih0 + (size_t)(krbase + i) * 1024 + col0);
            wAB[i] = pk2(w2.x, w2.y);
        }
    } else {
        int z = tid - 128;
        int cgz = z & 31, kb = (z >> 5) * 64;
        int czi = 2 * cgz;
        int czcol = ((czi >> 4) << 8) + (int)rank * 16 + (czi & 15);
        for (int i = 0; i < 64; i++) {
            float2 w2 = *(const float2*)(wih1 + (size_t)(kb + i) * 1024 + czcol);
            sW1[(kb + i) * 32 + cgz] = pk2(w2.x, w2.y);
        }
        #pragma unroll
        for (int i = 0; i < 64; i++) {
            float2 w2 = *(const float2*)(whh1 + (size_t)(krbase + i) * 1024 + col0);
            wAB[i] = pk2(w2.x, w2.y);
        }
    }
    // biases (both layers)
    if (tid < 128) {
        int ci = tid & 63;
        int col = ((ci >> 4) << 8) + (int)rank * 16 + (ci & 15);
        sBias[tid] = (tid < 64) ? (bih0[col] + bhh0[col])
                                : (bih1[col] + bhh1[col]);
    }
    // mailbox init: sH0d parity 0 (h0_{-1}=0), sH1d parity 1 (h1_{-1}=0)
    if (tid < 256) {
        sH0d[tid]       = 0ull;
        sH1d[256 + tid] = 0ull;
    }

    // ======== wait for the scan's g_part to be complete & visible ========
    cudaGridDependencySynchronize();

    // ======== prologue: bbox + pos MLP + x all-gather ========
    if (tid < 32) {
        int4 v = g_part[img * 32 + tid];
        int xm = v.x, xM = v.y, ym = v.z, yM = v.w;
        #pragma unroll
        for (int off = 16; off; off >>= 1) {
            xm = min(xm, __shfl_xor_sync(0xffffffffu, xm, off));
            xM = max(xM, __shfl_xor_sync(0xffffffffu, xM, off));
            ym = min(ym, __shfl_xor_sync(0xffffffffu, ym, off));
            yM = max(yM, __shfl_xor_sync(0xffffffffu, yM, off));
        }
        if (tid == 0) {
            float b0, b1, b2, b3;
            if (xM < 0) { b0 = 0.5f; b1 = 0.5f; b2 = 0.1f; b3 = 0.1f; }
            else {
                b0 = (float)(xm + xM) / 2.0f / 1024.0f;
                b1 = (float)(ym + yM) / 2.0f / 1024.0f;
                b2 = (float)(xM - xm) / 1024.0f;
                b3 = (float)(yM - ym) / 1024.0f;
            }
            sBB[rank * 4 + 0] = b0; sBB[rank * 4 + 1] = b1;
            sBB[rank * 4 + 2] = b2; sBB[rank * 4 + 3] = b3;
            out[16644 + img * 4 + 0] = b0; out[16644 + img * 4 + 1] = b1;
            out[16644 + img * 4 + 2] = b2; out[16644 + img * 4 + 3] = b3;
        }
    }
    __syncthreads();
    if (tid < 4) {
        float v = sBB[rank * 4 + tid];
        unsigned loc = smem_u32(&sBB[rank * 4 + tid]);
        #pragma unroll
        for (int r = 0; r < 16; r++) st_cluster_f32(loc, r, v);
    }
    // pos MLP (scratch aliases sPX0 — dead until x0 precompute)
    float*  sp1 = (float*)sPX0;             // [256]
    float4* pP4 = (float4*)(sp1 + 256);     // [256]
    float*  sp2 = (float*)(pP4 + 256);      // [256]
    {
        float a = pe_b1[tid];
        #pragma unroll
        for (int k = 0; k < 4; k++) a += sBB[rank * 4 + k] * pe_w1[k * 256 + tid];
        sp1[tid] = fmaxf(a, 0.0f);
    }
    __syncthreads();
    {
        int c4 = (tid & 63) * 4, kg = tid >> 6;
        float4 accA = make_float4(0.f, 0.f, 0.f, 0.f);
        float4 accB = make_float4(0.f, 0.f, 0.f, 0.f);
        const float* base = pe_w2 + (size_t)(kg * 64) * 256 + c4;
        #pragma unroll 8
        for (int i = 0; i < 64; i += 2) {
            float4 w0 = *(const float4*)(base + i * 256);
            float4 w1 = *(const float4*)(base + (i + 1) * 256);
            float s0 = sp1[kg * 64 + i], s1 = sp1[kg * 64 + i + 1];
            accA.x += s0 * w0.x; accA.y += s0 * w0.y; accA.z += s0 * w0.z; accA.w += s0 * w0.w;
            accB.x += s1 * w1.x; accB.y += s1 * w1.y; accB.z += s1 * w1.z; accB.w += s1 * w1.w;
        }
        pP4[tid] = make_float4(accA.x + accB.x, accA.y + accB.y,
                               accA.z + accB.z, accA.w + accB.w);
    }
    __syncthreads();
    if (tid < 64) {
        float4 a = pP4[tid], c1 = pP4[64 + tid], c2 = pP4[128 + tid], c3 = pP4[192 + tid];
        int col = tid * 4;
        sp2[col + 0] = fmaxf(a.x + c1.x + c2.x + c3.x + pe_b2[col + 0], 0.0f);
        sp2[col + 1] = fmaxf(a.y + c1.y + c2.y + c3.y + pe_b2[col + 1], 0.0f);
        sp2[col + 2] = fmaxf(a.z + c1.z + c2.z + c3.z + pe_b2[col + 2], 0.0f);
        sp2[col + 3] = fmaxf(a.w + c1.w + c2.w + c3.w + pe_b2[col + 3], 0.0f);
    }
    __syncthreads();
    {
        U64 xd = dup2(sp2[tid]);
        unsigned loc = smem_u32(&sX0[(int)rank * 256 + tid]);
        #pragma unroll
        for (int r = 0; r < 16; r++) st_cluster_u64(loc, r, xd);
    }
    __syncthreads();
    CLUSTER_SYNC();   // sX0 + sBB gathered everywhere

    // ======== A-warps: x0 precompute (wih0 in regs), then whh0 -> regs ======
    if (!isB) {
        for (int t = 0; t < 16; t++) {
            const U64* s0 = sX0 + t * 256 + krbase;
            MM64(s0, sPX0[t * 128 + tid]);
        }
        #pragma unroll
        for (int i = 0; i < 64; i++) {
            float2 w2 = *(const float2*)(whh0 + (size_t)(krbase + i) * 1024 + col0);
            wAB[i] = pk2(w2.x, w2.y);
        }
    }
    __syncthreads();

    // ======== 17-slot pipelined loop (identical to round 15) ========
    float creg = 0.0f;   // tid<16: layer0 cell; tid 16-31: layer1 cell

    for (int s = 0; s < 17; s++) {
        int p = s & 1;
        const U64* hb0 = sH0d + p * 256;   // h0_{s-1}
        const U64* hb1 = sH1d + p * 256;   // h1_{s-2}

        if (!isB) {
            if (s < 16) {
                const U64* s0 = hb0 + krbase;
                MM64(s0, sPH0[tid]);
            }
        } else if (s > 0) {
            int z = tid - 128;
            {
                const U64* s0 = hb1 + krbase;
                MM64(s0, sPH1[z]);
            }
            {
                const U64* s0 = hb0 + krbase;
                const U64* wp = sW1 + krbase * 32 + cg;
                U64 b0 = 0ull, b1 = 0ull, b2 = 0ull, b3 = 0ull;
                #pragma unroll
                for (int i = 0; i < 64; i += 4) {
                    ulonglong2 va = *(const ulonglong2*)(s0 + i);
                    ulonglong2 vb = *(const ulonglong2*)(s0 + i + 2);
                    b0 = fma2(va.x, wp[(i)     * 32], b0);
                    b1 = fma2(va.y, wp[(i + 1) * 32], b1);
                    b2 = fma2(vb.x, wp[(i + 2) * 32], b2);
                    b3 = fma2(vb.y, wp[(i + 3) * 32], b3);
                }
                sPX1[z] = add2(add2(b0, b1), add2(b2, b3));
            }
        }
        __syncthreads();

        if (tid < 64) {
            if (s < 16) {
                int ci = tid, cgi = ci >> 1, half = ci & 1;
                const float* px = (const float*)(sPX0 + s * 128);
                const float* ph = (const float*)sPH0;
                float sa = sBias[ci], sb = 0.0f;
                #pragma unroll
                for (int kk = 0; kk < 4; kk++) {
                    sa += px[(kk * 32 + cgi) * 2 + half];
                    sb += ph[(kk * 32 + cgi) * 2 + half];
                }
                sGate[ci] = sa + sb;
            }
        } else if (tid < 128) {
            if (s > 0) {
                int ci = tid - 64, cgi = ci >> 1, half = ci & 1;
                const float* px = (const float*)sPX1;
                const float* ph = (const float*)sPH1;
                float sa = sBias[64 + ci], sb = 0.0f;
                #pragma unroll
                for (int kk = 0; kk < 4; kk++) {
                    sa += px[(kk * 32 + cgi) * 2 + half];
                    sb += ph[(kk * 32 + cgi) * 2 + half];
                }
                sGate[64 + ci] = sa + sb;
            }
        }
        __syncthreads();

        if (tid < 16) {
            if (s < 16) {
                int u = tid;
                float iv = sigf(sGate[u]);
                float fv = sigf(sGate[16 + u]);
                float gv = tanh_fast(sGate[32 + u]);
                float ov = sigf(sGate[48 + u]);
                creg = fv * creg + iv * gv;
                float hv = ov * tanh_fast(creg);
                int j = (int)rank * 16 + u;
                U64 hd = dup2(hv);
                unsigned loc = smem_u32(&sH0d[((s + 1) & 1) * 256 + j]);
                #pragma unroll
                for (int r = 0; r < 16; r++) st_cluster_u64(loc, r, hd);
            }
        } else if (tid < 32) {
            if (s > 0) {
                int u = tid - 16, t1 = s - 1;
                float iv = sigf(sGate[64 + u]);
                float fv = sigf(sGate[80 + u]);
                float gv = tanh_fast(sGate[96 + u]);
                float ov = sigf(sGate[112 + u]);
                creg = fv * creg + iv * gv;
                float hv = ov * tanh_fast(creg);
                int j = (int)rank * 16 + u;
                U64 hd = dup2(hv);
                unsigned loc = smem_u32(&sH1d[((s + 1) & 1) * 256 + j]);
                #pragma unroll
                for (int r = 0; r < 16; r++) st_cluster_u64(loc, r, hd);
                out[240 + (b * 16 + t1) * 256 + j] = hv;
            }
        }
        CLUSTER_SYNC();
    }

    // ======== epilogue: heads on rank 0 (h1_15 in sH1d parity 1) ========
    if (rank == 0) {
        float*  slh  = (float*)sW1;             // scratch aliases sW1 (dead)
        float4* hP4  = (float4*)(slh + 256);
        float*  sx1  = (float*)(hP4 + 256);
        float*  sx2  = sx1 + 256;
        float*  sch  = sx2 + 128;
        float*  sdel = sch + 128;
        float4* hPA  = (float4*)(sdel + 32);
        float4* hPB  = hPA + 256;

        slh[tid] = upk(sH1d[256 + tid]).x;
        __syncthreads();

        {
            int c4 = (tid & 63) * 4, kg = tid >> 6;
            float4 accA = make_float4(0.f, 0.f, 0.f, 0.f);
            float4 accB = make_float4(0.f, 0.f, 0.f, 0.f);
            const float* base = mp_w1 + (size_t)(kg * 64) * 256 + c4;
            #pragma unroll 8
            for (int i = 0; i < 64; i += 2) {
                float4 w0 = *(const float4*)(base + i * 256);
                float4 w1 = *(const float4*)(base + (i + 1) * 256);
                float s0 = slh[kg * 64 + i], s1 = slh[kg * 64 + i + 1];
                accA.x += s0 * w0.x; accA.y += s0 * w0.y; accA.z += s0 * w0.z; accA.w += s0 * w0.w;
                accB.x += s1 * w1.x; accB.y += s1 * w1.y; accB.z += s1 * w1.z; accB.w += s1 * w1.w;
            }
            hP4[tid] = make_float4(accA.x + accB.x, accA.y + accB.y,
                                   accA.z + accB.z, accA.w + accB.w);
        }
        __syncthreads();
        if (tid < 64) {
            float4 a = hP4[tid], c1 = hP4[64 + tid], c2 = hP4[128 + tid], c3 = hP4[192 + tid];
            int col = tid * 4;
            sx1[col + 0] = fmaxf(a.x + c1.x + c2.x + c3.x + mp_b1[col + 0], 0.0f);
            sx1[col + 1] = fmaxf(a.y + c1.y + c2.y + c3.y + mp_b1[col + 1], 0.0f);
            sx1[col + 2] = fmaxf(a.z + c1.z + c2.z + c3.z + mp_b1[col + 2], 0.0f);
            sx1[col + 3] = fmaxf(a.w + c1.w + c2.w + c3.w + mp_b1[col + 3], 0.0f);
        }
        __syncthreads();

        {
            int c4 = (tid & 31) * 4, kg = tid >> 5;
            float4 aA = make_float4(0.f, 0.f, 0.f, 0.f);
            float4 aB = make_float4(0.f, 0.f, 0.f, 0.f);
            const float* bA = mp_w2 + (size_t)(kg * 32) * 128 + c4;
            const float* bB = cf_w1 + (size_t)(kg * 32) * 128 + c4;
            #pragma unroll 8
            for (int i = 0; i < 32; i++) {
                float4 wA = *(const float4*)(bA + i * 128);
                float4 wB = *(const float4*)(bB + i * 128);
                float sA = sx1[kg * 32 + i];
                float sB = slh[kg * 32 + i];
                aA.x += sA * wA.x; aA.y += sA * wA.y; aA.z += sA * wA.z; aA.w += sA * wA.w;
                aB.x += sB * wB.x; aB.y += sB * wB.y; aB.z += sB * wB.z; aB.w += sB * wB.w;
            }
            hPA[tid] = aA;
            hPB[tid] = aB;
        }
        __syncthreads();
        if (tid < 32) {
            float4 sA = make_float4(0.f, 0.f, 0.f, 0.f);
            float4 sB = make_float4(0.f, 0.f, 0.f, 0.f);
            #pragma unroll
            for (int kg = 0; kg < 8; kg++) {
                float4 a = hPA[kg * 32 + tid];
                sA.x += a.x; sA.y += a.y; sA.z += a.z; sA.w += a.w;
                float4 bv = hPB[kg * 32 + tid];
                sB.x += bv.x; sB.y += bv.y; sB.z += bv.z; sB.w += bv.w;
            }
            int col = tid * 4;
            sx2[col + 0] = fmaxf(sA.x + mp_b2[col + 0], 0.0f);
            sx2[col + 1] = fmaxf(sA.y + mp_b2[col + 1], 0.0f);
            sx2[col + 2] = fmaxf(sA.z + mp_b2[col + 2], 0.0f);
            sx2[col + 3] = fmaxf(sA.w + mp_b2[col + 3], 0.0f);
            sch[col + 0] = fmaxf(sB.x + cf_b1[col + 0], 0.0f);
            sch[col + 1] = fmaxf(sB.y + cf_b1[col + 1], 0.0f);
            sch[col + 2] = fmaxf(sB.z + cf_b1[col + 2], 0.0f);
            sch[col + 3] = fmaxf(sB.w + cf_b1[col + 3], 0.0f);
        }
        __syncthreads();

        if (tid < 20) {
            float a = mp_b3[tid];
            #pragma unroll 8
            for (int k = 0; k < 128; k++) a += sx2[k] * mp_w3[k * 20 + tid];
            sdel[tid] = a;
            out[b * 20 + tid] = a;              // predicted_deltas
        }
        if (tid >= 32 && tid < 37) {
            int hh = tid - 32;
            float a = cf_b2[hh];
            #pragma unroll 8
            for (int k = 0; k < 128; k++) a += sch[k] * cf_w2[k * 5 + hh];
            out[16624 + b * 5 + hh] = sigf(a);  // confidence
        }
        __syncthreads();

        if (tid < 4) {
            int d = tid;
            float run = sBB[15 * 4 + d];        // bbox of t=15
            #pragma unroll
            for (int hh = 0; hh < 5; hh++) {
                run += sdel[hh * 4 + d];
                out[80 + (b * 5 + hh) * 4 + d] = run;                   // predicted_bboxes
                if (d < 2) out[160 + (b * 5 + hh) * 2 + d] = run;       // locations
                else       out[200 + (b * 5 + hh) * 2 + (d - 2)] = run; // scales
            }
        }
    }
    #undef MM64
}

extern "C" void kernel_launch(void* const* d_in, const int* in_sizes, int n_in,
                              void* d_out, int out_size) {
    (void)in_sizes; (void)n_in; (void)out_size;
    const float* pred  = (const float*)d_in[1];
    const float* pe_w1 = (const float*)d_in[2];
    const float* pe_b1 = (const float*)d_in[3];
    const float* pe_w2 = (const float*)d_in[4];
    const float* pe_b2 = (const float*)d_in[5];
    const float* wih0  = (const float*)d_in[6];
    const float* whh0  = (const float*)d_in[7];
    const float* bih0  = (const float*)d_in[8];
    const float* bhh0  = (const float*)d_in[9];
    const float* wih1  = (const float*)d_in[10];
    const float* whh1  = (const float*)d_in[11];
    const float* bih1  = (const float*)d_in[12];
    const float* bhh1  = (const float*)d_in[13];
    const float* mp_w1 = (const float*)d_in[14];
    const float* mp_b1 = (const float*)d_in[15];
    const float* mp_w2 = (const float*)d_in[16];
    const float* mp_b2 = (const float*)d_in[17];
    const float* mp_w3 = (const float*)d_in[18];
    const float* mp_b3 = (const float*)d_in[19];
    const float* cf_w1 = (const float*)d_in[20];
    const float* cf_b1 = (const float*)d_in[21];
    const float* cf_w2 = (const float*)d_in[22];
    const float* cf_b2 = (const float*)d_in[23];
    float* out = (float*)d_out;

    cudaFuncSetAttribute(mp_fused_kernel,
                         cudaFuncAttributeMaxDynamicSharedMemorySize, FUSED_SMEM);
    cudaFuncSetAttribute(mp_fused_kernel,
                         cudaFuncAttributeNonPortableClusterSizeAllowed, 1);

    mp_scan_kernel<<<2048, 256>>>(pred);

    {
        cudaLaunchConfig_t cfg = {};
        cfg.gridDim = dim3(64, 1, 1);
        cfg.blockDim = dim3(256, 1, 1);
        cfg.dynamicSmemBytes = FUSED_SMEM;
        cfg.stream = 0;
        cudaLaunchAttribute attrs[2];
        attrs[0].id = cudaLaunchAttributeClusterDimension;
        attrs[0].val.clusterDim = {16, 1, 1};
        attrs[1].id = cudaLaunchAttributeProgrammaticStreamSerialization;
        attrs[1].val.programmaticStreamSerializationAllowed = 1;
        cfg.attrs = attrs;
        cfg.numAttrs = 2;
        cudaLaunchKernelEx(&cfg, mp_fused_kernel,
                           pe_w1, pe_b1, pe_w2, pe_b2,
                           wih0, whh0, bih0, bhh0,
                           wih1, whh1, bih1, bhh1,
                           mp_w1, mp_b1, mp_w2, mp_b2, mp_w3, mp_b3,
                           cf_w1, cf_b1, cf_w2, cf_b2, out);
    }
}